// round 3
// baseline (speedup 1.0000x reference)
#include <cuda_runtime.h>
#include <cuda_bf16.h>
#include <math.h>

// Problem constants
#define BB 16
#define SS 1024
#define DD 512
#define HH 8
#define HD 64
#define MM (BB * SS)          // 16384 rows
#define D3 (3 * DD)           // 1536

// ---------------------------------------------------------------------------
// Scratch (static device globals; no runtime allocation allowed)
// ---------------------------------------------------------------------------
__device__ float g_qkv[(size_t)MM * D3];    // [B*S, 1536] packed q|k|v (per branch, reused)
__device__ float g_att[(size_t)MM * DD];    // [B*S, 512] attention output (per branch, reused)
__device__ float g_comb[(size_t)MM * D3];   // [B*S, 1536] concat of branch projections

// ---------------------------------------------------------------------------
// GEMM: C[m, col0+n] = sum_k A[m,k] * W[n,k] + bias[n]
// A row-major [M,K] (lda=K), W row-major [N,K] (ldw=K), C row pitch ldc.
// Tiles: BM=BN=128, BK=16. 256 threads, 8x8 per thread (two 4-wide subtiles).
// ---------------------------------------------------------------------------
__global__ __launch_bounds__(256) void gemm_bias_kernel(
    const float* __restrict__ A, const float* __restrict__ W,
    const float* __restrict__ bias, float* __restrict__ C,
    int M, int N, int K, int ldc, int col0)
{
    __shared__ float As[128 * 20];   // [row][k] pitch 20
    __shared__ float Ws[128 * 20];   // [col][k] pitch 20

    const int tid = threadIdx.x;
    const int ty = tid >> 4;         // 0..15
    const int tx = tid & 15;         // 0..15
    const int m0 = blockIdx.y * 128;
    const int n0 = blockIdx.x * 128;

    float acc[8][8];
#pragma unroll
    for (int i = 0; i < 8; i++)
#pragma unroll
        for (int j = 0; j < 8; j++) acc[i][j] = 0.0f;

    for (int kt = 0; kt < K; kt += 16) {
        // Load A tile: 128 rows x 16 cols = 512 float4; 2 per thread
#pragma unroll
        for (int l = 0; l < 2; l++) {
            int f4 = tid + l * 256;
            int row = f4 >> 2, c4 = f4 & 3;
            float4 v = *(const float4*)(A + (size_t)(m0 + row) * K + kt + c4 * 4);
            *(float4*)(As + row * 20 + c4 * 4) = v;
        }
        // Load W tile
#pragma unroll
        for (int l = 0; l < 2; l++) {
            int f4 = tid + l * 256;
            int row = f4 >> 2, c4 = f4 & 3;
            float4 v = *(const float4*)(W + (size_t)(n0 + row) * K + kt + c4 * 4);
            *(float4*)(Ws + row * 20 + c4 * 4) = v;
        }
        __syncthreads();

#pragma unroll
        for (int k4 = 0; k4 < 4; k4++) {
            float4 a[8], b[8];
#pragma unroll
            for (int r = 0; r < 4; r++) {
                a[r]     = *(const float4*)(As + (ty * 4 + r) * 20 + k4 * 4);
                a[r + 4] = *(const float4*)(As + (64 + ty * 4 + r) * 20 + k4 * 4);
            }
#pragma unroll
            for (int c = 0; c < 4; c++) {
                b[c]     = *(const float4*)(Ws + (tx * 4 + c) * 20 + k4 * 4);
                b[c + 4] = *(const float4*)(Ws + (64 + tx * 4 + c) * 20 + k4 * 4);
            }
#pragma unroll
            for (int r = 0; r < 8; r++)
#pragma unroll
                for (int c = 0; c < 8; c++) {
                    acc[r][c] += a[r].x * b[c].x;
                    acc[r][c] += a[r].y * b[c].y;
                    acc[r][c] += a[r].z * b[c].z;
                    acc[r][c] += a[r].w * b[c].w;
                }
        }
        __syncthreads();
    }

    // Epilogue: add bias, write float4s
#pragma unroll
    for (int ri = 0; ri < 2; ri++)
#pragma unroll
        for (int i = 0; i < 4; i++) {
            int row = m0 + ri * 64 + ty * 4 + i;
            int r = ri * 4 + i;
#pragma unroll
            for (int ci = 0; ci < 2; ci++) {
                int colb = n0 + ci * 64 + tx * 4;
                float4 o;
                o.x = acc[r][ci * 4 + 0] + bias[colb + 0];
                o.y = acc[r][ci * 4 + 1] + bias[colb + 1];
                o.z = acc[r][ci * 4 + 2] + bias[colb + 2];
                o.w = acc[r][ci * 4 + 3] + bias[colb + 3];
                *(float4*)(C + (size_t)row * ldc + col0 + colb) = o;
            }
        }
}

// ---------------------------------------------------------------------------
// Flash attention, full (no mask). qkv layout [B*S, 1536] (q|k|v, heads packed).
// Grid: (S/64, B*H), block 256. Br=Bc=64, hd=64.
// ---------------------------------------------------------------------------
#define FLASH_SMEM (4 * 64 * 68 * 4)

__global__ __launch_bounds__(256) void flash_full_kernel(
    const float* __restrict__ qkv, float* __restrict__ att)
{
    extern __shared__ float sm[];
    float* Qs = sm;                 // [64][68]
    float* Ks = sm + 64 * 68;
    float* Vs = sm + 2 * 64 * 68;
    float* Ps = sm + 3 * 64 * 68;

    const int tid = threadIdx.x;
    const int ty = tid >> 4, tx = tid & 15;
    const int ty4 = ty * 4, tx4 = tx * 4;
    const int q0 = blockIdx.x * 64;
    const int bh = blockIdx.y;
    const int b = bh >> 3, h = bh & 7;

    const float* base = qkv + (size_t)b * SS * D3 + h * HD;

    // Load Q tile (scaled by 1/sqrt(64) = 0.125)
#pragma unroll
    for (int l = 0; l < 4; l++) {
        int f4 = tid + l * 256;               // 0..1023
        int row = f4 >> 4, c4 = f4 & 15;
        float4 v = *(const float4*)(base + (size_t)(q0 + row) * D3 + c4 * 4);
        v.x *= 0.125f; v.y *= 0.125f; v.z *= 0.125f; v.w *= 0.125f;
        *(float4*)(Qs + row * 68 + c4 * 4) = v;
    }

    float o[4][4];
    float mrow[4], lrow[4];
#pragma unroll
    for (int i = 0; i < 4; i++) {
        mrow[i] = -1e30f; lrow[i] = 0.0f;
#pragma unroll
        for (int j = 0; j < 4; j++) o[i][j] = 0.0f;
    }

    for (int kt = 0; kt < 16; kt++) {
        __syncthreads();   // prev iter's P*V done before overwriting K/V/P
        int k0 = kt * 64;
#pragma unroll
        for (int l = 0; l < 4; l++) {
            int f4 = tid + l * 256;
            int row = f4 >> 4, c4 = f4 & 15;
            const float* src = base + (size_t)(k0 + row) * D3 + c4 * 4;
            *(float4*)(Ks + row * 68 + c4 * 4) = *(const float4*)(src + 512);
            *(float4*)(Vs + row * 68 + c4 * 4) = *(const float4*)(src + 1024);
        }
        __syncthreads();

        // S = Q K^T (64x64), this thread's 4x4
        float s[4][4];
#pragma unroll
        for (int i = 0; i < 4; i++)
#pragma unroll
            for (int j = 0; j < 4; j++) s[i][j] = 0.0f;

#pragma unroll
        for (int d4 = 0; d4 < 16; d4++) {
            float4 qv[4], kv[4];
#pragma unroll
            for (int i = 0; i < 4; i++) qv[i] = *(const float4*)(Qs + (ty4 + i) * 68 + d4 * 4);
#pragma unroll
            for (int j = 0; j < 4; j++) kv[j] = *(const float4*)(Ks + (tx4 + j) * 68 + d4 * 4);
#pragma unroll
            for (int i = 0; i < 4; i++)
#pragma unroll
                for (int j = 0; j < 4; j++) {
                    s[i][j] += qv[i].x * kv[j].x;
                    s[i][j] += qv[i].y * kv[j].y;
                    s[i][j] += qv[i].z * kv[j].z;
                    s[i][j] += qv[i].w * kv[j].w;
                }
        }

        // Online softmax per query row (row group = 16 lanes sharing ty)
#pragma unroll
        for (int i = 0; i < 4; i++) {
            float mx = fmaxf(fmaxf(s[i][0], s[i][1]), fmaxf(s[i][2], s[i][3]));
#pragma unroll
            for (int off = 8; off > 0; off >>= 1)
                mx = fmaxf(mx, __shfl_xor_sync(0xffffffffu, mx, off));
            float mnew = fmaxf(mrow[i], mx);
            float p0 = __expf(s[i][0] - mnew);
            float p1 = __expf(s[i][1] - mnew);
            float p2 = __expf(s[i][2] - mnew);
            float p3 = __expf(s[i][3] - mnew);
            float ls = p0 + p1 + p2 + p3;
#pragma unroll
            for (int off = 8; off > 0; off >>= 1)
                ls += __shfl_xor_sync(0xffffffffu, ls, off);
            float alpha = __expf(mrow[i] - mnew);
            lrow[i] = lrow[i] * alpha + ls;
            mrow[i] = mnew;
#pragma unroll
            for (int j = 0; j < 4; j++) o[i][j] *= alpha;
            float4 pp; pp.x = p0; pp.y = p1; pp.z = p2; pp.w = p3;
            *(float4*)(Ps + (ty4 + i) * 68 + tx4) = pp;
        }
        __syncthreads();

        // O += P V  (this thread owns O[q 4][d 4])
#pragma unroll
        for (int k4 = 0; k4 < 16; k4++) {
            float4 p4[4], v4[4];
#pragma unroll
            for (int i = 0; i < 4; i++) p4[i] = *(const float4*)(Ps + (ty4 + i) * 68 + k4 * 4);
#pragma unroll
            for (int kk = 0; kk < 4; kk++) v4[kk] = *(const float4*)(Vs + (k4 * 4 + kk) * 68 + tx4);
#pragma unroll
            for (int i = 0; i < 4; i++) {
                o[i][0] += p4[i].x * v4[0].x + p4[i].y * v4[1].x + p4[i].z * v4[2].x + p4[i].w * v4[3].x;
                o[i][1] += p4[i].x * v4[0].y + p4[i].y * v4[1].y + p4[i].z * v4[2].y + p4[i].w * v4[3].y;
                o[i][2] += p4[i].x * v4[0].z + p4[i].y * v4[1].z + p4[i].z * v4[2].z + p4[i].w * v4[3].z;
                o[i][3] += p4[i].x * v4[0].w + p4[i].y * v4[1].w + p4[i].z * v4[2].w + p4[i].w * v4[3].w;
            }
        }
    }

    // Write output
#pragma unroll
    for (int i = 0; i < 4; i++) {
        float inv = 1.0f / lrow[i];
        float4 r;
        r.x = o[i][0] * inv; r.y = o[i][1] * inv;
        r.z = o[i][2] * inv; r.w = o[i][3] * inv;
        *(float4*)(att + (size_t)(b * SS + q0 + ty4 + i) * DD + h * HD + tx4) = r;
    }
}

// ---------------------------------------------------------------------------
// Windowed causal attention: query q attends keys k with 0 <= q-k < W (W<=10).
// Grid: (S/64, B*H), block 128 (2 threads per query, interleaved half-dims).
// ---------------------------------------------------------------------------
template <int W>
__global__ __launch_bounds__(128) void window_attn_kernel(
    const float* __restrict__ qkv, float* __restrict__ att)
{
    __shared__ float Ks[80 * 65];
    __shared__ float Vs[80 * 65];

    const int tid = threadIdx.x;
    const int q0 = blockIdx.x * 64;
    const int bh = blockIdx.y;
    const int b = bh >> 3, h = bh & 7;
    const float* base = qkv + (size_t)b * SS * D3 + h * HD;

    // Stage K/V rows s = q0-16+r, r=0..79 (clamped at s>=0)
    for (int f4 = tid; f4 < 80 * 16; f4 += 128) {
        int r = f4 >> 4, c4 = f4 & 15;
        int s = q0 - 16 + r;
        if (s >= 0) {
            const float* src = base + (size_t)s * D3 + c4 * 4;
            float4 kv = *(const float4*)(src + 512);
            float4 vv = *(const float4*)(src + 1024);
            Ks[r * 65 + c4 * 4 + 0] = kv.x; Ks[r * 65 + c4 * 4 + 1] = kv.y;
            Ks[r * 65 + c4 * 4 + 2] = kv.z; Ks[r * 65 + c4 * 4 + 3] = kv.w;
            Vs[r * 65 + c4 * 4 + 0] = vv.x; Vs[r * 65 + c4 * 4 + 1] = vv.y;
            Vs[r * 65 + c4 * 4 + 2] = vv.z; Vs[r * 65 + c4 * 4 + 3] = vv.w;
        }
    }
    __syncthreads();

    const int ql = tid >> 1;          // query within tile
    const int half = tid & 1;         // dim parity: owns dims 2*dd + half
    const int q = q0 + ql;

    float qreg[32];
#pragma unroll
    for (int dd = 0; dd < 32; dd++)
        qreg[dd] = base[(size_t)q * D3 + 2 * dd + half] * 0.125f;

    float sc[W];
    float m = -1e30f;
#pragma unroll
    for (int w = 0; w < W; w++) {
        int k = q - w;
        int kr = ql + 16 - w;
        float dot = 0.0f;
        if (k >= 0) {
#pragma unroll
            for (int dd = 0; dd < 32; dd++)
                dot += qreg[dd] * Ks[kr * 65 + 2 * dd + half];
        }
        dot += __shfl_xor_sync(0xffffffffu, dot, 1);
        sc[w] = (k >= 0) ? dot : -1e30f;
        m = fmaxf(m, sc[w]);
    }

    float l = 0.0f;
    float p[W];
#pragma unroll
    for (int w = 0; w < W; w++) {
        p[w] = (q - w >= 0) ? __expf(sc[w] - m) : 0.0f;
        l += p[w];
    }

    float o[32];
#pragma unroll
    for (int dd = 0; dd < 32; dd++) o[dd] = 0.0f;
#pragma unroll
    for (int w = 0; w < W; w++) {
        int k = q - w;
        if (k >= 0) {
            int kr = ql + 16 - w;
#pragma unroll
            for (int dd = 0; dd < 32; dd++)
                o[dd] += p[w] * Vs[kr * 65 + 2 * dd + half];
        }
    }

    float inv = 1.0f / l;
    float* dst = att + (size_t)(b * SS + q) * DD + h * HD;
#pragma unroll
    for (int dd = 0; dd < 32; dd++)
        dst[2 * dd + half] = o[dd] * inv;
}

// ---------------------------------------------------------------------------
// Launch
// ---------------------------------------------------------------------------
extern "C" void kernel_launch(void* const* d_in, const int* in_sizes, int n_in,
                              void* d_out, int out_size)
{
    const float* x    = (const float*)d_in[0];   // [16,1024,512]
    const float* Wqkv = (const float*)d_in[1];   // [3,1536,512]
    const float* bqkv = (const float*)d_in[2];   // [3,1536]
    const float* Wo   = (const float*)d_in[3];   // [3,512,512]
    const float* bo   = (const float*)d_in[4];   // [3,512]
    const float* Wf   = (const float*)d_in[5];   // [512,1536]
    const float* bf   = (const float*)d_in[6];   // [512]
    float* out = (float*)d_out;

    float *qkv, *att, *comb;
    cudaGetSymbolAddress((void**)&qkv, g_qkv);
    cudaGetSymbolAddress((void**)&att, g_att);
    cudaGetSymbolAddress((void**)&comb, g_comb);

    cudaFuncSetAttribute(flash_full_kernel,
                         cudaFuncAttributeMaxDynamicSharedMemorySize, FLASH_SMEM);

    dim3 gemm_qkv_grid(D3 / 128, MM / 128);   // (12, 128)
    dim3 gemm_d_grid(DD / 128, MM / 128);     // (4, 128)
    dim3 attn_grid(SS / 64, BB * HH);         // (16, 128)

    for (int i = 0; i < 3; i++) {
        gemm_bias_kernel<<<gemm_qkv_grid, 256>>>(
            x, Wqkv + (size_t)i * D3 * DD, bqkv + (size_t)i * D3,
            qkv, MM, D3, DD, D3, 0);

        if (i == 0)
            window_attn_kernel<5><<<attn_grid, 128>>>(qkv, att);
        else if (i == 1)
            window_attn_kernel<10><<<attn_grid, 128>>>(qkv, att);
        else
            flash_full_kernel<<<attn_grid, 256, FLASH_SMEM>>>(qkv, att);

        gemm_bias_kernel<<<gemm_d_grid, 256>>>(
            att, Wo + (size_t)i * DD * DD, bo + (size_t)i * DD,
            comb, MM, DD, DD, D3, i * DD);
    }

    gemm_bias_kernel<<<gemm_d_grid, 256>>>(
        comb, Wf, bf, out, MM, DD, D3, DD, 0);
}

// round 5
// speedup vs baseline: 1.9754x; 1.9754x over previous
#include <cuda_runtime.h>
#include <cuda_bf16.h>
#include <cstdint>
#include <math.h>

// Problem constants
#define BB 16
#define SS 1024
#define DD 512
#define HH 8
#define HD 64
#define MM (BB * SS)          // 16384 rows
#define D3 (3 * DD)           // 1536

// ---------------------------------------------------------------------------
// Scratch (static device globals; no runtime allocation allowed)
// ---------------------------------------------------------------------------
__device__ float g_qkv[(size_t)MM * D3];    // [B*S, 1536] packed q|k|v (per branch, reused)
__device__ float g_att[(size_t)MM * DD];    // [B*S, 512] attention output (per branch, reused)
__device__ float g_comb[(size_t)MM * D3];   // [B*S, 1536] concat of branch projections

// ---------------------------------------------------------------------------
// Warp-level tensor core helpers (base sm_80+ PTX only — NO 'a'-suffix features;
// the harness PTX-targets plain sm_103, which rejects tcgen05/TMEM).
// ---------------------------------------------------------------------------
__device__ __forceinline__ uint32_t smem_u32(const void* p) {
    uint32_t a;
    asm("{ .reg .u64 t; cvta.to.shared.u64 t, %1; cvt.u32.u64 %0, t; }" : "=r"(a) : "l"(p));
    return a;
}

__device__ __forceinline__ void ldsm4(uint32_t* r, uint32_t addr) {
    asm volatile("ldmatrix.sync.aligned.m8n8.x4.shared.b16 {%0,%1,%2,%3}, [%4];"
                 : "=r"(r[0]), "=r"(r[1]), "=r"(r[2]), "=r"(r[3]) : "r"(addr));
}

// D = A(16x16) * B(16x8) + D, bf16 inputs, f32 accum.
__device__ __forceinline__ void mma16816(float* c, const uint32_t* a, const uint32_t* b) {
    asm volatile("mma.sync.aligned.m16n8k16.row.col.f32.bf16.bf16.f32 "
                 "{%0,%1,%2,%3}, {%4,%5,%6,%7}, {%8,%9}, {%0,%1,%2,%3};"
                 : "+f"(c[0]), "+f"(c[1]), "+f"(c[2]), "+f"(c[3])
                 : "r"(a[0]), "r"(a[1]), "r"(a[2]), "r"(a[3]), "r"(b[0]), "r"(b[1]));
}

// ---------------------------------------------------------------------------
// HMMA GEMM: C[m, col0+n] = sum_k A[m,k]*W[n,k] + bias[n]
// bf16 hi/lo 3-term split for ~fp32 accuracy.
// Block tile 128x128, K chunks of 32. 8 warps = 4(m) x 2(n), warp tile 32x64.
// Smem rows padded to 40 bf16 (80B pitch): 8-row ldmatrix groups hit 8
// distinct 16B bank-quads mod 128B -> conflict-free without swizzle.
// ---------------------------------------------------------------------------
#define KC 32
#define PITCH 40                       // bf16 elements per smem row (80 bytes)
#define TILE_B (128 * PITCH * 2)       // 10240 bytes per tile

__global__ __launch_bounds__(256) void gemm_tc_kernel(
    const float* __restrict__ A, const float* __restrict__ W,
    const float* __restrict__ bias, float* __restrict__ C,
    int K, int ldc, int col0)
{
    __shared__ __align__(128) __nv_bfloat16 sAhi[128 * PITCH];
    __shared__ __align__(128) __nv_bfloat16 sAlo[128 * PITCH];
    __shared__ __align__(128) __nv_bfloat16 sWhi[128 * PITCH];
    __shared__ __align__(128) __nv_bfloat16 sWlo[128 * PITCH];

    const int tid = threadIdx.x;
    const int wid = tid >> 5, lane = tid & 31;
    const int m0 = blockIdx.y * 128;
    const int n0 = blockIdx.x * 128;
    const int warp_m = (wid & 3) * 32;   // 0,32,64,96
    const int warp_n = (wid >> 2) * 64;  // 0,64

    const uint32_t uAhi = smem_u32(sAhi), uAlo = smem_u32(sAlo);
    const uint32_t uWhi = smem_u32(sWhi), uWlo = smem_u32(sWlo);

    // ldmatrix base offsets (bytes), constant over chunks
    const int rowA = warp_m + (lane & 15);          // + mt*16
    const int colA = (lane >> 4) << 3;              // 0 or 8 bf16
    const int aoff = rowA * (PITCH * 2) + colA * 2;
    const int bm = lane >> 3;
    const int rowB = warp_n + (lane & 7) + ((bm >> 1) << 3);  // + np*16
    const int colB = (bm & 1) << 3;
    const int boff = rowB * (PITCH * 2) + colB * 2;

    float acc[2][8][4];
#pragma unroll
    for (int mt = 0; mt < 2; mt++)
#pragma unroll
        for (int nt = 0; nt < 8; nt++)
#pragma unroll
            for (int i = 0; i < 4; i++) acc[mt][nt][i] = 0.0f;

    const float* Abase = A + (size_t)m0 * K;
    const float* Wbase = W + (size_t)n0 * K;
    const int nchunks = K / KC;

    for (int kt = 0; kt < nchunks; kt++) {
        const int k0 = kt * KC;
        __syncthreads();   // previous chunk's MMAs done reading smem

        // Load fp32 chunk, split to bf16 hi/lo, store to padded smem.
        // 128 rows x 32 cols = 1024 float4 per operand; 4 per thread.
#pragma unroll
        for (int l = 0; l < 4; l++) {
            int f4 = tid + l * 256;
            int row = f4 >> 3, c4 = f4 & 7;
            int so = row * PITCH + c4 * 4;   // bf16 element offset (8B aligned)

            float4 va = *(const float4*)(Abase + (size_t)row * K + k0 + c4 * 4);
            float4 vw = *(const float4*)(Wbase + (size_t)row * K + k0 + c4 * 4);

            float fa[4] = {va.x, va.y, va.z, va.w};
            float fw[4] = {vw.x, vw.y, vw.z, vw.w};
            uint16_t ah[4], al[4], wh[4], wl[4];
#pragma unroll
            for (int i = 0; i < 4; i++) {
                __nv_bfloat16 h = __float2bfloat16_rn(fa[i]);
                ah[i] = __bfloat16_as_ushort(h);
                al[i] = __bfloat16_as_ushort(__float2bfloat16_rn(fa[i] - __bfloat162float(h)));
                __nv_bfloat16 g = __float2bfloat16_rn(fw[i]);
                wh[i] = __bfloat16_as_ushort(g);
                wl[i] = __bfloat16_as_ushort(__float2bfloat16_rn(fw[i] - __bfloat162float(g)));
            }
            uint2 p;
            p.x = (uint32_t)ah[0] | ((uint32_t)ah[1] << 16);
            p.y = (uint32_t)ah[2] | ((uint32_t)ah[3] << 16);
            *(uint2*)(sAhi + so) = p;
            p.x = (uint32_t)al[0] | ((uint32_t)al[1] << 16);
            p.y = (uint32_t)al[2] | ((uint32_t)al[3] << 16);
            *(uint2*)(sAlo + so) = p;
            p.x = (uint32_t)wh[0] | ((uint32_t)wh[1] << 16);
            p.y = (uint32_t)wh[2] | ((uint32_t)wh[3] << 16);
            *(uint2*)(sWhi + so) = p;
            p.x = (uint32_t)wl[0] | ((uint32_t)wl[1] << 16);
            p.y = (uint32_t)wl[2] | ((uint32_t)wl[3] << 16);
            *(uint2*)(sWlo + so) = p;
        }
        __syncthreads();

#pragma unroll
        for (int ks = 0; ks < 2; ks++) {
            const int kb = ks * 16 * 2;   // byte offset for this k16 step

            uint32_t aH[2][4], aL[2][4];
#pragma unroll
            for (int mt = 0; mt < 2; mt++) {
                ldsm4(aH[mt], uAhi + aoff + mt * 16 * (PITCH * 2) + kb);
                ldsm4(aL[mt], uAlo + aoff + mt * 16 * (PITCH * 2) + kb);
            }
            uint32_t bH[4][4], bL[4][4];
#pragma unroll
            for (int np = 0; np < 4; np++) {
                ldsm4(bH[np], uWhi + boff + np * 16 * (PITCH * 2) + kb);
                ldsm4(bL[np], uWlo + boff + np * 16 * (PITCH * 2) + kb);
            }

#pragma unroll
            for (int mt = 0; mt < 2; mt++)
#pragma unroll
                for (int np = 0; np < 4; np++) {
                    // ntile 2*np uses b regs {0,1}; ntile 2*np+1 uses {2,3}
                    mma16816(acc[mt][2 * np],     aH[mt], bH[np]);
                    mma16816(acc[mt][2 * np],     aH[mt], bL[np]);
                    mma16816(acc[mt][2 * np],     aL[mt], bH[np]);
                    mma16816(acc[mt][2 * np + 1], aH[mt], bH[np] + 2);
                    mma16816(acc[mt][2 * np + 1], aH[mt], bL[np] + 2);
                    mma16816(acc[mt][2 * np + 1], aL[mt], bH[np] + 2);
                }
        }
    }

    // Epilogue: c{0,1} -> (row g, col tg*2..+1), c{2,3} -> row g+8
    const int g = lane >> 2, tg = lane & 3;
#pragma unroll
    for (int nt = 0; nt < 8; nt++) {
        const int ncol = warp_n + nt * 8 + tg * 2;
        const float b0 = bias[n0 + ncol], b1 = bias[n0 + ncol + 1];
#pragma unroll
        for (int mt = 0; mt < 2; mt++) {
            const int r0 = m0 + warp_m + mt * 16 + g;
            float2 o;
            o.x = acc[mt][nt][0] + b0; o.y = acc[mt][nt][1] + b1;
            *(float2*)(C + (size_t)r0 * ldc + col0 + n0 + ncol) = o;
            o.x = acc[mt][nt][2] + b0; o.y = acc[mt][nt][3] + b1;
            *(float2*)(C + (size_t)(r0 + 8) * ldc + col0 + n0 + ncol) = o;
        }
    }
}

// ---------------------------------------------------------------------------
// Flash attention, full (no mask). qkv layout [B*S, 1536] (q|k|v, heads packed).
// Grid: (S/64, B*H), block 256. Br=Bc=64, hd=64.   (unchanged)
// ---------------------------------------------------------------------------
#define FLASH_SMEM (4 * 64 * 68 * 4)

__global__ __launch_bounds__(256) void flash_full_kernel(
    const float* __restrict__ qkv, float* __restrict__ att)
{
    extern __shared__ float sm[];
    float* Qs = sm;                 // [64][68]
    float* Ks = sm + 64 * 68;
    float* Vs = sm + 2 * 64 * 68;
    float* Ps = sm + 3 * 64 * 68;

    const int tid = threadIdx.x;
    const int ty = tid >> 4, tx = tid & 15;
    const int ty4 = ty * 4, tx4 = tx * 4;
    const int q0 = blockIdx.x * 64;
    const int bh = blockIdx.y;
    const int b = bh >> 3, h = bh & 7;

    const float* base = qkv + (size_t)b * SS * D3 + h * HD;

#pragma unroll
    for (int l = 0; l < 4; l++) {
        int f4 = tid + l * 256;
        int row = f4 >> 4, c4 = f4 & 15;
        float4 v = *(const float4*)(base + (size_t)(q0 + row) * D3 + c4 * 4);
        v.x *= 0.125f; v.y *= 0.125f; v.z *= 0.125f; v.w *= 0.125f;
        *(float4*)(Qs + row * 68 + c4 * 4) = v;
    }

    float o[4][4];
    float mrow[4], lrow[4];
#pragma unroll
    for (int i = 0; i < 4; i++) {
        mrow[i] = -1e30f; lrow[i] = 0.0f;
#pragma unroll
        for (int j = 0; j < 4; j++) o[i][j] = 0.0f;
    }

    for (int kt = 0; kt < 16; kt++) {
        __syncthreads();
        int k0 = kt * 64;
#pragma unroll
        for (int l = 0; l < 4; l++) {
            int f4 = tid + l * 256;
            int row = f4 >> 4, c4 = f4 & 15;
            const float* src = base + (size_t)(k0 + row) * D3 + c4 * 4;
            *(float4*)(Ks + row * 68 + c4 * 4) = *(const float4*)(src + 512);
            *(float4*)(Vs + row * 68 + c4 * 4) = *(const float4*)(src + 1024);
        }
        __syncthreads();

        float s[4][4];
#pragma unroll
        for (int i = 0; i < 4; i++)
#pragma unroll
            for (int j = 0; j < 4; j++) s[i][j] = 0.0f;

#pragma unroll
        for (int d4 = 0; d4 < 16; d4++) {
            float4 qv[4], kv[4];
#pragma unroll
            for (int i = 0; i < 4; i++) qv[i] = *(const float4*)(Qs + (ty4 + i) * 68 + d4 * 4);
#pragma unroll
            for (int j = 0; j < 4; j++) kv[j] = *(const float4*)(Ks + (tx4 + j) * 68 + d4 * 4);
#pragma unroll
            for (int i = 0; i < 4; i++)
#pragma unroll
                for (int j = 0; j < 4; j++) {
                    s[i][j] += qv[i].x * kv[j].x;
                    s[i][j] += qv[i].y * kv[j].y;
                    s[i][j] += qv[i].z * kv[j].z;
                    s[i][j] += qv[i].w * kv[j].w;
                }
        }

#pragma unroll
        for (int i = 0; i < 4; i++) {
            float mx = fmaxf(fmaxf(s[i][0], s[i][1]), fmaxf(s[i][2], s[i][3]));
#pragma unroll
            for (int off = 8; off > 0; off >>= 1)
                mx = fmaxf(mx, __shfl_xor_sync(0xffffffffu, mx, off));
            float mnew = fmaxf(mrow[i], mx);
            float p0 = __expf(s[i][0] - mnew);
            float p1 = __expf(s[i][1] - mnew);
            float p2 = __expf(s[i][2] - mnew);
            float p3 = __expf(s[i][3] - mnew);
            float ls = p0 + p1 + p2 + p3;
#pragma unroll
            for (int off = 8; off > 0; off >>= 1)
                ls += __shfl_xor_sync(0xffffffffu, ls, off);
            float alpha = __expf(mrow[i] - mnew);
            lrow[i] = lrow[i] * alpha + ls;
            mrow[i] = mnew;
#pragma unroll
            for (int j = 0; j < 4; j++) o[i][j] *= alpha;
            float4 pp; pp.x = p0; pp.y = p1; pp.z = p2; pp.w = p3;
            *(float4*)(Ps + (ty4 + i) * 68 + tx4) = pp;
        }
        __syncthreads();

#pragma unroll
        for (int k4 = 0; k4 < 16; k4++) {
            float4 p4[4], v4[4];
#pragma unroll
            for (int i = 0; i < 4; i++) p4[i] = *(const float4*)(Ps + (ty4 + i) * 68 + k4 * 4);
#pragma unroll
            for (int kk = 0; kk < 4; kk++) v4[kk] = *(const float4*)(Vs + (k4 * 4 + kk) * 68 + tx4);
#pragma unroll
            for (int i = 0; i < 4; i++) {
                o[i][0] += p4[i].x * v4[0].x + p4[i].y * v4[1].x + p4[i].z * v4[2].x + p4[i].w * v4[3].x;
                o[i][1] += p4[i].x * v4[0].y + p4[i].y * v4[1].y + p4[i].z * v4[2].y + p4[i].w * v4[3].y;
                o[i][2] += p4[i].x * v4[0].z + p4[i].y * v4[1].z + p4[i].z * v4[2].z + p4[i].w * v4[3].z;
                o[i][3] += p4[i].x * v4[0].w + p4[i].y * v4[1].w + p4[i].z * v4[2].w + p4[i].w * v4[3].w;
            }
        }
    }

#pragma unroll
    for (int i = 0; i < 4; i++) {
        float inv = 1.0f / lrow[i];
        float4 r;
        r.x = o[i][0] * inv; r.y = o[i][1] * inv;
        r.z = o[i][2] * inv; r.w = o[i][3] * inv;
        *(float4*)(att + (size_t)(b * SS + q0 + ty4 + i) * DD + h * HD + tx4) = r;
    }
}

// ---------------------------------------------------------------------------
// Windowed causal attention (unchanged)
// ---------------------------------------------------------------------------
template <int W>
__global__ __launch_bounds__(128) void window_attn_kernel(
    const float* __restrict__ qkv, float* __restrict__ att)
{
    __shared__ float Ks[80 * 65];
    __shared__ float Vs[80 * 65];

    const int tid = threadIdx.x;
    const int q0 = blockIdx.x * 64;
    const int bh = blockIdx.y;
    const int b = bh >> 3, h = bh & 7;
    const float* base = qkv + (size_t)b * SS * D3 + h * HD;

    for (int f4 = tid; f4 < 80 * 16; f4 += 128) {
        int r = f4 >> 4, c4 = f4 & 15;
        int s = q0 - 16 + r;
        if (s >= 0) {
            const float* src = base + (size_t)s * D3 + c4 * 4;
            float4 kv = *(const float4*)(src + 512);
            float4 vv = *(const float4*)(src + 1024);
            Ks[r * 65 + c4 * 4 + 0] = kv.x; Ks[r * 65 + c4 * 4 + 1] = kv.y;
            Ks[r * 65 + c4 * 4 + 2] = kv.z; Ks[r * 65 + c4 * 4 + 3] = kv.w;
            Vs[r * 65 + c4 * 4 + 0] = vv.x; Vs[r * 65 + c4 * 4 + 1] = vv.y;
            Vs[r * 65 + c4 * 4 + 2] = vv.z; Vs[r * 65 + c4 * 4 + 3] = vv.w;
        }
    }
    __syncthreads();

    const int ql = tid >> 1;
    const int half = tid & 1;
    const int q = q0 + ql;

    float qreg[32];
#pragma unroll
    for (int dd = 0; dd < 32; dd++)
        qreg[dd] = base[(size_t)q * D3 + 2 * dd + half] * 0.125f;

    float sc[W];
    float m = -1e30f;
#pragma unroll
    for (int w = 0; w < W; w++) {
        int k = q - w;
        int kr = ql + 16 - w;
        float dot = 0.0f;
        if (k >= 0) {
#pragma unroll
            for (int dd = 0; dd < 32; dd++)
                dot += qreg[dd] * Ks[kr * 65 + 2 * dd + half];
        }
        dot += __shfl_xor_sync(0xffffffffu, dot, 1);
        sc[w] = (k >= 0) ? dot : -1e30f;
        m = fmaxf(m, sc[w]);
    }

    float l = 0.0f;
    float p[W];
#pragma unroll
    for (int w = 0; w < W; w++) {
        p[w] = (q - w >= 0) ? __expf(sc[w] - m) : 0.0f;
        l += p[w];
    }

    float o[32];
#pragma unroll
    for (int dd = 0; dd < 32; dd++) o[dd] = 0.0f;
#pragma unroll
    for (int w = 0; w < W; w++) {
        int k = q - w;
        if (k >= 0) {
            int kr = ql + 16 - w;
#pragma unroll
            for (int dd = 0; dd < 32; dd++)
                o[dd] += p[w] * Vs[kr * 65 + 2 * dd + half];
        }
    }

    float inv = 1.0f / l;
    float* dst = att + (size_t)(b * SS + q) * DD + h * HD;
#pragma unroll
    for (int dd = 0; dd < 32; dd++)
        dst[2 * dd + half] = o[dd] * inv;
}

// ---------------------------------------------------------------------------
// Launch
// ---------------------------------------------------------------------------
extern "C" void kernel_launch(void* const* d_in, const int* in_sizes, int n_in,
                              void* d_out, int out_size)
{
    const float* x    = (const float*)d_in[0];   // [16,1024,512]
    const float* Wqkv = (const float*)d_in[1];   // [3,1536,512]
    const float* bqkv = (const float*)d_in[2];   // [3,1536]
    const float* Wo   = (const float*)d_in[3];   // [3,512,512]
    const float* bo   = (const float*)d_in[4];   // [3,512]
    const float* Wf   = (const float*)d_in[5];   // [512,1536]
    const float* bf   = (const float*)d_in[6];   // [512]
    float* out = (float*)d_out;

    float *qkv, *att, *comb;
    cudaGetSymbolAddress((void**)&qkv, g_qkv);
    cudaGetSymbolAddress((void**)&att, g_att);
    cudaGetSymbolAddress((void**)&comb, g_comb);

    cudaFuncSetAttribute(flash_full_kernel,
                         cudaFuncAttributeMaxDynamicSharedMemorySize, FLASH_SMEM);

    dim3 gemm_qkv_grid(D3 / 128, MM / 128);   // (12, 128)
    dim3 gemm_d_grid(DD / 128, MM / 128);     // (4, 128)
    dim3 attn_grid(SS / 64, BB * HH);         // (16, 128)

    for (int i = 0; i < 3; i++) {
        gemm_tc_kernel<<<gemm_qkv_grid, 256>>>(
            x, Wqkv + (size_t)i * D3 * DD, bqkv + (size_t)i * D3,
            qkv, DD, D3, 0);

        if (i == 0)
            window_attn_kernel<5><<<attn_grid, 128>>>(qkv, att);
        else if (i == 1)
            window_attn_kernel<10><<<attn_grid, 128>>>(qkv, att);
        else
            flash_full_kernel<<<attn_grid, 256, FLASH_SMEM>>>(qkv, att);

        gemm_tc_kernel<<<gemm_d_grid, 256>>>(
            att, Wo + (size_t)i * DD * DD, bo + (size_t)i * DD,
            comb, DD, D3, i * DD);
    }

    gemm_tc_kernel<<<gemm_d_grid, 256>>>(
        comb, Wf, bf, out, D3, DD, 0);
}

// round 6
// speedup vs baseline: 2.8881x; 1.4620x over previous
#include <cuda_runtime.h>
#include <cuda_bf16.h>
#include <cstdint>
#include <math.h>

// Problem constants
#define BB 16
#define SS 1024
#define DD 512
#define HH 8
#define HD 64
#define MM (BB * SS)          // 16384 rows
#define D3 (3 * DD)           // 1536

// ---------------------------------------------------------------------------
// Scratch (static device globals; no runtime allocation allowed)
// ---------------------------------------------------------------------------
__device__ float g_qkv[(size_t)MM * D3];            // fp32 qkv (window kernels)
__device__ __nv_bfloat16 g_qkvh[(size_t)MM * D3];   // bf16 hi copy (flash)
__device__ __nv_bfloat16 g_qkvl[(size_t)MM * D3];   // bf16 lo copy (flash)
__device__ float g_att[(size_t)MM * DD];
__device__ float g_comb[(size_t)MM * D3];

// ---------------------------------------------------------------------------
// Warp-level tensor core helpers (base sm_80+ PTX only — NO 'a'-suffix
// features; the harness PTX-targets plain sm_103 which rejects tcgen05).
// ---------------------------------------------------------------------------
__device__ __forceinline__ uint32_t smem_u32(const void* p) {
    uint32_t a;
    asm("{ .reg .u64 t; cvta.to.shared.u64 t, %1; cvt.u32.u64 %0, t; }" : "=r"(a) : "l"(p));
    return a;
}

__device__ __forceinline__ void ldsm4(uint32_t* r, uint32_t addr) {
    asm volatile("ldmatrix.sync.aligned.m8n8.x4.shared.b16 {%0,%1,%2,%3}, [%4];"
                 : "=r"(r[0]), "=r"(r[1]), "=r"(r[2]), "=r"(r[3]) : "r"(addr));
}

__device__ __forceinline__ void ldsm4t(uint32_t* r, uint32_t addr) {
    asm volatile("ldmatrix.sync.aligned.m8n8.x4.trans.shared.b16 {%0,%1,%2,%3}, [%4];"
                 : "=r"(r[0]), "=r"(r[1]), "=r"(r[2]), "=r"(r[3]) : "r"(addr));
}

// D = A(16x16) * B(16x8) + D, bf16 inputs, f32 accum.
__device__ __forceinline__ void mma16816(float* c, const uint32_t* a, const uint32_t* b) {
    asm volatile("mma.sync.aligned.m16n8k16.row.col.f32.bf16.bf16.f32 "
                 "{%0,%1,%2,%3}, {%4,%5,%6,%7}, {%8,%9}, {%0,%1,%2,%3};"
                 : "+f"(c[0]), "+f"(c[1]), "+f"(c[2]), "+f"(c[3])
                 : "r"(a[0]), "r"(a[1]), "r"(a[2]), "r"(a[3]), "r"(b[0]), "r"(b[1]));
}

__device__ __forceinline__ uint32_t pack_hi(float x, float y) {
    uint16_t a = __bfloat16_as_ushort(__float2bfloat16_rn(x));
    uint16_t b = __bfloat16_as_ushort(__float2bfloat16_rn(y));
    return (uint32_t)a | ((uint32_t)b << 16);
}
__device__ __forceinline__ uint32_t pack_lo(float x, float y) {
    float xh = __bfloat162float(__float2bfloat16_rn(x));
    float yh = __bfloat162float(__float2bfloat16_rn(y));
    uint16_t a = __bfloat16_as_ushort(__float2bfloat16_rn(x - xh));
    uint16_t b = __bfloat16_as_ushort(__float2bfloat16_rn(y - yh));
    return (uint32_t)a | ((uint32_t)b << 16);
}

// ---------------------------------------------------------------------------
// HMMA GEMM: C[m, col0+n] = sum_k A[m,k]*W[n,k] + bias[n]
// bf16 hi/lo 3-term split. Block tile 128x128, K chunks of 32.
// 8 warps = 4(m) x 2(n), warp tile 32x64. Optional bf16 hi/lo epilogue copy.
// ---------------------------------------------------------------------------
#define KC 32
#define PITCH 40                       // bf16 elements per smem row (80 bytes)

__global__ __launch_bounds__(256) void gemm_tc_kernel(
    const float* __restrict__ A, const float* __restrict__ W,
    const float* __restrict__ bias, float* __restrict__ C,
    __nv_bfloat16* __restrict__ Ch, __nv_bfloat16* __restrict__ Cl,
    int K, int ldc, int col0)
{
    __shared__ __align__(128) __nv_bfloat16 sAhi[128 * PITCH];
    __shared__ __align__(128) __nv_bfloat16 sAlo[128 * PITCH];
    __shared__ __align__(128) __nv_bfloat16 sWhi[128 * PITCH];
    __shared__ __align__(128) __nv_bfloat16 sWlo[128 * PITCH];

    const int tid = threadIdx.x;
    const int wid = tid >> 5, lane = tid & 31;
    const int m0 = blockIdx.y * 128;
    const int n0 = blockIdx.x * 128;
    const int warp_m = (wid & 3) * 32;
    const int warp_n = (wid >> 2) * 64;

    const uint32_t uAhi = smem_u32(sAhi), uAlo = smem_u32(sAlo);
    const uint32_t uWhi = smem_u32(sWhi), uWlo = smem_u32(sWlo);

    const int rowA = warp_m + (lane & 15);
    const int colA = (lane >> 4) << 3;
    const int aoff = rowA * (PITCH * 2) + colA * 2;
    const int bm = lane >> 3;
    const int rowB = warp_n + (lane & 7) + ((bm >> 1) << 3);
    const int colB = (bm & 1) << 3;
    const int boff = rowB * (PITCH * 2) + colB * 2;

    float acc[2][8][4];
#pragma unroll
    for (int mt = 0; mt < 2; mt++)
#pragma unroll
        for (int nt = 0; nt < 8; nt++)
#pragma unroll
            for (int i = 0; i < 4; i++) acc[mt][nt][i] = 0.0f;

    const float* Abase = A + (size_t)m0 * K;
    const float* Wbase = W + (size_t)n0 * K;
    const int nchunks = K / KC;

    for (int kt = 0; kt < nchunks; kt++) {
        const int k0 = kt * KC;
        __syncthreads();

#pragma unroll
        for (int l = 0; l < 4; l++) {
            int f4 = tid + l * 256;
            int row = f4 >> 3, c4 = f4 & 7;
            int so = row * PITCH + c4 * 4;

            float4 va = *(const float4*)(Abase + (size_t)row * K + k0 + c4 * 4);
            float4 vw = *(const float4*)(Wbase + (size_t)row * K + k0 + c4 * 4);

            uint2 p;
            p.x = pack_hi(va.x, va.y); p.y = pack_hi(va.z, va.w);
            *(uint2*)(sAhi + so) = p;
            p.x = pack_lo(va.x, va.y); p.y = pack_lo(va.z, va.w);
            *(uint2*)(sAlo + so) = p;
            p.x = pack_hi(vw.x, vw.y); p.y = pack_hi(vw.z, vw.w);
            *(uint2*)(sWhi + so) = p;
            p.x = pack_lo(vw.x, vw.y); p.y = pack_lo(vw.z, vw.w);
            *(uint2*)(sWlo + so) = p;
        }
        __syncthreads();

#pragma unroll
        for (int ks = 0; ks < 2; ks++) {
            const int kb = ks * 32;

            uint32_t aH[2][4], aL[2][4];
#pragma unroll
            for (int mt = 0; mt < 2; mt++) {
                ldsm4(aH[mt], uAhi + aoff + mt * 16 * (PITCH * 2) + kb);
                ldsm4(aL[mt], uAlo + aoff + mt * 16 * (PITCH * 2) + kb);
            }
            uint32_t bH[4][4], bL[4][4];
#pragma unroll
            for (int np = 0; np < 4; np++) {
                ldsm4(bH[np], uWhi + boff + np * 16 * (PITCH * 2) + kb);
                ldsm4(bL[np], uWlo + boff + np * 16 * (PITCH * 2) + kb);
            }

#pragma unroll
            for (int mt = 0; mt < 2; mt++)
#pragma unroll
                for (int np = 0; np < 4; np++) {
                    mma16816(acc[mt][2 * np],     aH[mt], bH[np]);
                    mma16816(acc[mt][2 * np],     aH[mt], bL[np]);
                    mma16816(acc[mt][2 * np],     aL[mt], bH[np]);
                    mma16816(acc[mt][2 * np + 1], aH[mt], bH[np] + 2);
                    mma16816(acc[mt][2 * np + 1], aH[mt], bL[np] + 2);
                    mma16816(acc[mt][2 * np + 1], aL[mt], bH[np] + 2);
                }
        }
    }

    const int g = lane >> 2, tg = lane & 3;
#pragma unroll
    for (int nt = 0; nt < 8; nt++) {
        const int ncol = warp_n + nt * 8 + tg * 2;
        const float b0 = bias[n0 + ncol], b1 = bias[n0 + ncol + 1];
#pragma unroll
        for (int mt = 0; mt < 2; mt++) {
            const int r0 = m0 + warp_m + mt * 16 + g;
#pragma unroll
            for (int hh = 0; hh < 2; hh++) {
                const int r = r0 + hh * 8;
                const float v0 = acc[mt][nt][2 * hh] + b0;
                const float v1 = acc[mt][nt][2 * hh + 1] + b1;
                const size_t idx = (size_t)r * ldc + col0 + n0 + ncol;
                float2 o; o.x = v0; o.y = v1;
                *(float2*)(C + idx) = o;
                if (Ch) {
                    *(uint32_t*)(Ch + idx) = pack_hi(v0, v1);
                    *(uint32_t*)(Cl + idx) = pack_lo(v0, v1);
                }
            }
        }
    }
}

// ---------------------------------------------------------------------------
// HMMA flash attention, full (no mask), bf16 hi/lo 3-term split.
// Reads bf16 qkv copies. Grid (S/64, B*H), block 128 (4 warps, 16 q-rows each).
// q at col h*64, k at 512+h*64, v at 1024+h*64; row pitch 1536.
// ---------------------------------------------------------------------------
#define FPITCH 72   // bf16 elements per smem row (144 B): conflict-free ldmatrix

__global__ __launch_bounds__(128) void flash_hmma_kernel(
    const __nv_bfloat16* __restrict__ qh, const __nv_bfloat16* __restrict__ ql,
    float* __restrict__ att)
{
    __shared__ __align__(128) __nv_bfloat16 sKh[64 * FPITCH];
    __shared__ __align__(128) __nv_bfloat16 sKl[64 * FPITCH];
    __shared__ __align__(128) __nv_bfloat16 sVh[64 * FPITCH];
    __shared__ __align__(128) __nv_bfloat16 sVl[64 * FPITCH];

    const int tid = threadIdx.x;
    const int warp = tid >> 5, lane = tid & 31;
    const int g = lane >> 2, t = lane & 3;
    const int q0 = blockIdx.x * 64;
    const int b = blockIdx.y >> 3, h = blockIdx.y & 7;

    const uint32_t uKh = smem_u32(sKh), uKl = smem_u32(sKl);
    const uint32_t uVh = smem_u32(sVh), uVl = smem_u32(sVl);

    // Q fragments in registers for the whole kernel (hi + lo), 4 k16 steps.
    const size_t rowQ0 = (size_t)(b * SS + q0 + warp * 16 + g) * D3 + h * HD;
    const size_t rowQ1 = rowQ0 + 8 * D3;
    uint32_t qH[4][4], qL[4][4];
#pragma unroll
    for (int ks = 0; ks < 4; ks++) {
        const int c = ks * 16 + 2 * t;
        qH[ks][0] = *(const uint32_t*)(qh + rowQ0 + c);
        qH[ks][1] = *(const uint32_t*)(qh + rowQ1 + c);
        qH[ks][2] = *(const uint32_t*)(qh + rowQ0 + c + 8);
        qH[ks][3] = *(const uint32_t*)(qh + rowQ1 + c + 8);
        qL[ks][0] = *(const uint32_t*)(ql + rowQ0 + c);
        qL[ks][1] = *(const uint32_t*)(ql + rowQ1 + c);
        qL[ks][2] = *(const uint32_t*)(ql + rowQ0 + c + 8);
        qL[ks][3] = *(const uint32_t*)(ql + rowQ1 + c + 8);
    }

    // ldmatrix per-lane offsets
    const int bm = lane >> 3;
    const int kboff = ((lane & 7) + ((bm >> 1) << 3)) * (FPITCH * 2) + ((bm & 1) << 3) * 2;
    const int vboff = ((lane & 7) + ((bm & 1) << 3)) * (FPITCH * 2) + (lane >> 4) * 16;

    float o[8][4];
    float mrow[2], lrow[2];
#pragma unroll
    for (int nt = 0; nt < 8; nt++)
#pragma unroll
        for (int i = 0; i < 4; i++) o[nt][i] = 0.0f;
    mrow[0] = mrow[1] = -1e30f;
    lrow[0] = lrow[1] = 0.0f;

    const size_t kvbase = (size_t)(b * SS) * D3 + h * HD;

    for (int kt = 0; kt < 16; kt++) {
        __syncthreads();
        const size_t tb = kvbase + (size_t)(kt * 64) * D3;
        // stage K/V hi/lo tiles (64 rows x 64 bf16 each = 512 uint4 per array)
#pragma unroll
        for (int l = 0; l < 4; l++) {
            int idx = tid + l * 128;
            int r = idx >> 3, c4 = idx & 7;
            size_t gsrc = tb + (size_t)r * D3 + c4 * 8;
            int sdst = r * FPITCH + c4 * 8;
            *(uint4*)(sKh + sdst) = *(const uint4*)(qh + gsrc + 512);
            *(uint4*)(sKl + sdst) = *(const uint4*)(ql + gsrc + 512);
            *(uint4*)(sVh + sdst) = *(const uint4*)(qh + gsrc + 1024);
            *(uint4*)(sVl + sdst) = *(const uint4*)(ql + gsrc + 1024);
        }
        __syncthreads();

        // S = Q K^T for this warp's 16 rows x 64 keys
        float s[8][4];
#pragma unroll
        for (int nt = 0; nt < 8; nt++)
#pragma unroll
            for (int i = 0; i < 4; i++) s[nt][i] = 0.0f;

#pragma unroll
        for (int ks = 0; ks < 4; ks++) {
            const int kb = ks * 32;
#pragma unroll
            for (int np = 0; np < 4; np++) {
                uint32_t kh[4], kl[4];
                ldsm4(kh, uKh + kboff + np * 16 * (FPITCH * 2) + kb);
                ldsm4(kl, uKl + kboff + np * 16 * (FPITCH * 2) + kb);
                mma16816(s[2 * np],     qH[ks], kh);
                mma16816(s[2 * np],     qH[ks], kl);
                mma16816(s[2 * np],     qL[ks], kh);
                mma16816(s[2 * np + 1], qH[ks], kh + 2);
                mma16816(s[2 * np + 1], qH[ks], kl + 2);
                mma16816(s[2 * np + 1], qL[ks], kh + 2);
            }
        }

        // online softmax (scale 0.125), rows g and g+8
#pragma unroll
        for (int r = 0; r < 2; r++) {
            float mx = -1e30f;
#pragma unroll
            for (int nt = 0; nt < 8; nt++) {
                s[nt][2 * r]     *= 0.125f;
                s[nt][2 * r + 1] *= 0.125f;
                mx = fmaxf(mx, fmaxf(s[nt][2 * r], s[nt][2 * r + 1]));
            }
            mx = fmaxf(mx, __shfl_xor_sync(0xffffffffu, mx, 1));
            mx = fmaxf(mx, __shfl_xor_sync(0xffffffffu, mx, 2));
            float mnew = fmaxf(mrow[r], mx);
            float alpha = __expf(mrow[r] - mnew);
            float ls = 0.0f;
#pragma unroll
            for (int nt = 0; nt < 8; nt++) {
                float p0 = __expf(s[nt][2 * r] - mnew);
                float p1 = __expf(s[nt][2 * r + 1] - mnew);
                s[nt][2 * r] = p0; s[nt][2 * r + 1] = p1;
                ls += p0 + p1;
            }
            ls += __shfl_xor_sync(0xffffffffu, ls, 1);
            ls += __shfl_xor_sync(0xffffffffu, ls, 2);
            lrow[r] = lrow[r] * alpha + ls;
            mrow[r] = mnew;
#pragma unroll
            for (int nt = 0; nt < 8; nt++) {
                o[nt][2 * r] *= alpha; o[nt][2 * r + 1] *= alpha;
            }
        }

        // P fragments (A-layout) from S accumulators, hi/lo split
        uint32_t pH[4][4], pL[4][4];
#pragma unroll
        for (int j = 0; j < 4; j++) {
            pH[j][0] = pack_hi(s[2 * j][0], s[2 * j][1]);
            pH[j][1] = pack_hi(s[2 * j][2], s[2 * j][3]);
            pH[j][2] = pack_hi(s[2 * j + 1][0], s[2 * j + 1][1]);
            pH[j][3] = pack_hi(s[2 * j + 1][2], s[2 * j + 1][3]);
            pL[j][0] = pack_lo(s[2 * j][0], s[2 * j][1]);
            pL[j][1] = pack_lo(s[2 * j][2], s[2 * j][3]);
            pL[j][2] = pack_lo(s[2 * j + 1][0], s[2 * j + 1][1]);
            pL[j][3] = pack_lo(s[2 * j + 1][2], s[2 * j + 1][3]);
        }

        // O += P V : j = key k16 step, np = d n16 pair
#pragma unroll
        for (int j = 0; j < 4; j++) {
            const int rb = j * 16 * (FPITCH * 2);
#pragma unroll
            for (int np = 0; np < 4; np++) {
                uint32_t vh[4], vl[4];
                ldsm4t(vh, uVh + vboff + rb + np * 32);
                ldsm4t(vl, uVl + vboff + rb + np * 32);
                mma16816(o[2 * np],     pH[j], vh);
                mma16816(o[2 * np],     pH[j], vl);
                mma16816(o[2 * np],     pL[j], vh);
                mma16816(o[2 * np + 1], pH[j], vh + 2);
                mma16816(o[2 * np + 1], pH[j], vl + 2);
                mma16816(o[2 * np + 1], pL[j], vh + 2);
            }
        }
    }

    // write O / l
    const float inv0 = 1.0f / lrow[0], inv1 = 1.0f / lrow[1];
    const size_t orow0 = (size_t)(b * SS + q0 + warp * 16 + g) * DD + h * HD;
    const size_t orow1 = orow0 + 8 * DD;
#pragma unroll
    for (int nt = 0; nt < 8; nt++) {
        const int c = nt * 8 + 2 * t;
        float2 w0; w0.x = o[nt][0] * inv0; w0.y = o[nt][1] * inv0;
        float2 w1; w1.x = o[nt][2] * inv1; w1.y = o[nt][3] * inv1;
        *(float2*)(att + orow0 + c) = w0;
        *(float2*)(att + orow1 + c) = w1;
    }
}

// ---------------------------------------------------------------------------
// Windowed causal attention (unchanged, fp32)
// ---------------------------------------------------------------------------
template <int W>
__global__ __launch_bounds__(128) void window_attn_kernel(
    const float* __restrict__ qkv, float* __restrict__ att)
{
    __shared__ float Ks[80 * 65];
    __shared__ float Vs[80 * 65];

    const int tid = threadIdx.x;
    const int q0 = blockIdx.x * 64;
    const int bh = blockIdx.y;
    const int b = bh >> 3, h = bh & 7;
    const float* base = qkv + (size_t)b * SS * D3 + h * HD;

    for (int f4 = tid; f4 < 80 * 16; f4 += 128) {
        int r = f4 >> 4, c4 = f4 & 15;
        int s = q0 - 16 + r;
        if (s >= 0) {
            const float* src = base + (size_t)s * D3 + c4 * 4;
            float4 kv = *(const float4*)(src + 512);
            float4 vv = *(const float4*)(src + 1024);
            Ks[r * 65 + c4 * 4 + 0] = kv.x; Ks[r * 65 + c4 * 4 + 1] = kv.y;
            Ks[r * 65 + c4 * 4 + 2] = kv.z; Ks[r * 65 + c4 * 4 + 3] = kv.w;
            Vs[r * 65 + c4 * 4 + 0] = vv.x; Vs[r * 65 + c4 * 4 + 1] = vv.y;
            Vs[r * 65 + c4 * 4 + 2] = vv.z; Vs[r * 65 + c4 * 4 + 3] = vv.w;
        }
    }
    __syncthreads();

    const int ql = tid >> 1;
    const int half = tid & 1;
    const int q = q0 + ql;

    float qreg[32];
#pragma unroll
    for (int dd = 0; dd < 32; dd++)
        qreg[dd] = base[(size_t)q * D3 + 2 * dd + half] * 0.125f;

    float sc[W];
    float m = -1e30f;
#pragma unroll
    for (int w = 0; w < W; w++) {
        int k = q - w;
        int kr = ql + 16 - w;
        float dot = 0.0f;
        if (k >= 0) {
#pragma unroll
            for (int dd = 0; dd < 32; dd++)
                dot += qreg[dd] * Ks[kr * 65 + 2 * dd + half];
        }
        dot += __shfl_xor_sync(0xffffffffu, dot, 1);
        sc[w] = (k >= 0) ? dot : -1e30f;
        m = fmaxf(m, sc[w]);
    }

    float l = 0.0f;
    float p[W];
#pragma unroll
    for (int w = 0; w < W; w++) {
        p[w] = (q - w >= 0) ? __expf(sc[w] - m) : 0.0f;
        l += p[w];
    }

    float o[32];
#pragma unroll
    for (int dd = 0; dd < 32; dd++) o[dd] = 0.0f;
#pragma unroll
    for (int w = 0; w < W; w++) {
        int k = q - w;
        if (k >= 0) {
            int kr = ql + 16 - w;
#pragma unroll
            for (int dd = 0; dd < 32; dd++)
                o[dd] += p[w] * Vs[kr * 65 + 2 * dd + half];
        }
    }

    float inv = 1.0f / l;
    float* dst = att + (size_t)(b * SS + q) * DD + h * HD;
#pragma unroll
    for (int dd = 0; dd < 32; dd++)
        dst[2 * dd + half] = o[dd] * inv;
}

// ---------------------------------------------------------------------------
// Launch
// ---------------------------------------------------------------------------
extern "C" void kernel_launch(void* const* d_in, const int* in_sizes, int n_in,
                              void* d_out, int out_size)
{
    const float* x    = (const float*)d_in[0];   // [16,1024,512]
    const float* Wqkv = (const float*)d_in[1];   // [3,1536,512]
    const float* bqkv = (const float*)d_in[2];   // [3,1536]
    const float* Wo   = (const float*)d_in[3];   // [3,512,512]
    const float* bo   = (const float*)d_in[4];   // [3,512]
    const float* Wf   = (const float*)d_in[5];   // [512,1536]
    const float* bf   = (const float*)d_in[6];   // [512]
    float* out = (float*)d_out;

    float *qkv, *att, *comb;
    __nv_bfloat16 *qkvh, *qkvl;
    cudaGetSymbolAddress((void**)&qkv, g_qkv);
    cudaGetSymbolAddress((void**)&att, g_att);
    cudaGetSymbolAddress((void**)&comb, g_comb);
    cudaGetSymbolAddress((void**)&qkvh, g_qkvh);
    cudaGetSymbolAddress((void**)&qkvl, g_qkvl);

    dim3 gemm_qkv_grid(D3 / 128, MM / 128);   // (12, 128)
    dim3 gemm_d_grid(DD / 128, MM / 128);     // (4, 128)
    dim3 attn_grid(SS / 64, BB * HH);         // (16, 128)

    for (int i = 0; i < 3; i++) {
        const bool is_flash = (i == 2);
        gemm_tc_kernel<<<gemm_qkv_grid, 256>>>(
            x, Wqkv + (size_t)i * D3 * DD, bqkv + (size_t)i * D3,
            qkv, is_flash ? qkvh : nullptr, is_flash ? qkvl : nullptr,
            DD, D3, 0);

        if (i == 0)
            window_attn_kernel<5><<<attn_grid, 128>>>(qkv, att);
        else if (i == 1)
            window_attn_kernel<10><<<attn_grid, 128>>>(qkv, att);
        else
            flash_hmma_kernel<<<attn_grid, 128>>>(qkvh, qkvl, att);

        gemm_tc_kernel<<<gemm_d_grid, 256>>>(
            att, Wo + (size_t)i * DD * DD, bo + (size_t)i * DD,
            comb, nullptr, nullptr, DD, D3, i * DD);
    }

    gemm_tc_kernel<<<gemm_d_grid, 256>>>(
        comb, Wf, bf, out, nullptr, nullptr, D3, DD, 0);
}

// round 7
// speedup vs baseline: 3.4786x; 1.2044x over previous
#include <cuda_runtime.h>
#include <cuda_bf16.h>
#include <cstdint>
#include <math.h>

// Problem constants
#define BB 16
#define SS 1024
#define DD 512
#define HH 8
#define HD 64
#define MM (BB * SS)          // 16384 rows
#define D3 (3 * DD)           // 1536

// ---------------------------------------------------------------------------
// Scratch (static device globals; no runtime allocation allowed)
// All intermediate tensors live as bf16 hi/lo pairs (same bytes as fp32).
// ---------------------------------------------------------------------------
__device__ __nv_bfloat16 g_xh[(size_t)MM * DD],  g_xl[(size_t)MM * DD];
__device__ __nv_bfloat16 g_qkvh[(size_t)MM * D3], g_qkvl[(size_t)MM * D3];
__device__ __nv_bfloat16 g_atth[(size_t)MM * DD], g_attl[(size_t)MM * DD];
__device__ __nv_bfloat16 g_combh[(size_t)MM * D3], g_combl[(size_t)MM * D3];
__device__ __nv_bfloat16 g_Wqkvh[(size_t)3 * D3 * DD], g_Wqkvl[(size_t)3 * D3 * DD];
__device__ __nv_bfloat16 g_Woh[(size_t)3 * DD * DD],  g_Wol[(size_t)3 * DD * DD];
__device__ __nv_bfloat16 g_Wfh[(size_t)DD * D3],  g_Wfl[(size_t)DD * D3];

// ---------------------------------------------------------------------------
// Helpers (base sm_80+ PTX only — NO 'a'-suffix features; harness PTX-targets
// plain sm_103 which rejects tcgen05/TMEM).
// ---------------------------------------------------------------------------
__device__ __forceinline__ uint32_t smem_u32(const void* p) {
    uint32_t a;
    asm("{ .reg .u64 t; cvta.to.shared.u64 t, %1; cvt.u32.u64 %0, t; }" : "=r"(a) : "l"(p));
    return a;
}

__device__ __forceinline__ void ldsm4(uint32_t* r, uint32_t addr) {
    asm volatile("ldmatrix.sync.aligned.m8n8.x4.shared.b16 {%0,%1,%2,%3}, [%4];"
                 : "=r"(r[0]), "=r"(r[1]), "=r"(r[2]), "=r"(r[3]) : "r"(addr));
}
__device__ __forceinline__ void ldsm4t(uint32_t* r, uint32_t addr) {
    asm volatile("ldmatrix.sync.aligned.m8n8.x4.trans.shared.b16 {%0,%1,%2,%3}, [%4];"
                 : "=r"(r[0]), "=r"(r[1]), "=r"(r[2]), "=r"(r[3]) : "r"(addr));
}
__device__ __forceinline__ void mma16816(float* c, const uint32_t* a, const uint32_t* b) {
    asm volatile("mma.sync.aligned.m16n8k16.row.col.f32.bf16.bf16.f32 "
                 "{%0,%1,%2,%3}, {%4,%5,%6,%7}, {%8,%9}, {%0,%1,%2,%3};"
                 : "+f"(c[0]), "+f"(c[1]), "+f"(c[2]), "+f"(c[3])
                 : "r"(a[0]), "r"(a[1]), "r"(a[2]), "r"(a[3]), "r"(b[0]), "r"(b[1]));
}
__device__ __forceinline__ void cp16(uint32_t saddr, const void* g) {
    asm volatile("cp.async.cg.shared.global [%0], [%1], 16;" :: "r"(saddr), "l"(g));
}
#define CP_COMMIT() asm volatile("cp.async.commit_group;" ::: "memory")
#define CP_WAIT1()  asm volatile("cp.async.wait_group 1;" ::: "memory")
#define CP_WAIT0()  asm volatile("cp.async.wait_group 0;" ::: "memory")

__device__ __forceinline__ uint32_t pack_hi(float x, float y) {
    uint16_t a = __bfloat16_as_ushort(__float2bfloat16_rn(x));
    uint16_t b = __bfloat16_as_ushort(__float2bfloat16_rn(y));
    return (uint32_t)a | ((uint32_t)b << 16);
}
__device__ __forceinline__ uint32_t pack_lo(float x, float y) {
    float xh = __bfloat162float(__float2bfloat16_rn(x));
    float yh = __bfloat162float(__float2bfloat16_rn(y));
    uint16_t a = __bfloat16_as_ushort(__float2bfloat16_rn(x - xh));
    uint16_t b = __bfloat16_as_ushort(__float2bfloat16_rn(y - yh));
    return (uint32_t)a | ((uint32_t)b << 16);
}
__device__ __forceinline__ float2 bf2sum(uint32_t h, uint32_t l) {
    __nv_bfloat162 hb = *reinterpret_cast<__nv_bfloat162*>(&h);
    __nv_bfloat162 lb = *reinterpret_cast<__nv_bfloat162*>(&l);
    float2 hf = __bfloat1622float2(hb), lf = __bfloat1622float2(lb);
    return make_float2(hf.x + lf.x, hf.y + lf.y);
}

// ---------------------------------------------------------------------------
// fp32 -> bf16 hi/lo conversion (grid-stride, float4 granularity)
// ---------------------------------------------------------------------------
__global__ __launch_bounds__(256) void convert_hilo_kernel(
    const float* __restrict__ src, __nv_bfloat16* __restrict__ h,
    __nv_bfloat16* __restrict__ l, int n4)
{
    int i = blockIdx.x * blockDim.x + threadIdx.x;
    if (i < n4) {
        float4 v = *(const float4*)(src + (size_t)i * 4);
        uint2 ph, pl;
        ph.x = pack_hi(v.x, v.y); ph.y = pack_hi(v.z, v.w);
        pl.x = pack_lo(v.x, v.y); pl.y = pack_lo(v.z, v.w);
        *(uint2*)(h + (size_t)i * 4) = ph;
        *(uint2*)(l + (size_t)i * 4) = pl;
    }
}

// ---------------------------------------------------------------------------
// HMMA GEMM, all-bf16 I/O: C[m, col0+n] = sum_k (Ah+Al)[m,k]*(Wh+Wl)[n,k] + bias[n]
// 3-term split: AhWh + AhWl + AlWh. Block tile 128x128, KC=32.
// 8 warps = 4(m) x 2(n), warp tile 32x64. 2-stage cp.async pipeline.
// Output: fp32 C (if non-null) or bf16 hi/lo pair Ch/Cl.
// ---------------------------------------------------------------------------
#define KC 32
#define PITCH 40                       // bf16 per smem row (80 B): ldmatrix conflict-free
#define TILE_E (128 * PITCH)           // elements per tile
#define STAGE_E (4 * TILE_E)           // Ah,Al,Wh,Wl per stage
#define GEMM_SMEM (2 * STAGE_E * 2)    // bytes (2 stages)

__global__ __launch_bounds__(256) void gemm_bf16_kernel(
    const __nv_bfloat16* __restrict__ Ah, const __nv_bfloat16* __restrict__ Al,
    const __nv_bfloat16* __restrict__ Wh, const __nv_bfloat16* __restrict__ Wl,
    const float* __restrict__ bias, float* __restrict__ C,
    __nv_bfloat16* __restrict__ Ch, __nv_bfloat16* __restrict__ Cl,
    int K, int ldc, int col0)
{
    extern __shared__ __nv_bfloat16 smem[];
    const uint32_t sbase = smem_u32(smem);

    const int tid = threadIdx.x;
    const int wid = tid >> 5, lane = tid & 31;
    const int m0 = blockIdx.y * 128;
    const int n0 = blockIdx.x * 128;
    const int warp_m = (wid & 3) * 32;
    const int warp_n = (wid >> 2) * 64;

    // ldmatrix per-lane offsets within a tile
    const int aoff = (warp_m + (lane & 15)) * (PITCH * 2) + (((lane >> 4) << 3) << 1);
    const int bm = lane >> 3;
    const int boff = (warp_n + (lane & 7) + ((bm >> 1) << 3)) * (PITCH * 2) + (((bm & 1) << 3) << 1);

    // cp.async per-thread mapping: 2 x 16B per tile per chunk
    const int crow0 = tid >> 2,        ccol0 = tid & 3;          // idx = tid
    const int crow1 = (tid + 256) >> 2, ccol1 = (tid + 256) & 3; // idx = tid+256

    const __nv_bfloat16* Abh = Ah + (size_t)m0 * K;
    const __nv_bfloat16* Abl = Al + (size_t)m0 * K;
    const __nv_bfloat16* Wbh = Wh + (size_t)n0 * K;
    const __nv_bfloat16* Wbl = Wl + (size_t)n0 * K;

    float acc[2][8][4];
#pragma unroll
    for (int mt = 0; mt < 2; mt++)
#pragma unroll
        for (int nt = 0; nt < 8; nt++)
#pragma unroll
            for (int i = 0; i < 4; i++) acc[mt][nt][i] = 0.0f;

    const int nchunks = K / KC;

    // prefetch helper (macro-ish lambda)
    auto prefetch = [&](int kt, int stg) {
        const int k0 = kt * KC;
        const uint32_t sb = sbase + stg * (STAGE_E * 2);
        // tile order: Ah, Al, Wh, Wl
        {
            uint32_t so = (uint32_t)(crow0 * (PITCH * 2) + ccol0 * 16);
            size_t go = (size_t)crow0 * K + k0 + ccol0 * 8;
            cp16(sb + so,                Abh + go);
            cp16(sb + TILE_E * 2 + so,   Abl + go);
            cp16(sb + TILE_E * 4 + so,   Wbh + go);
            cp16(sb + TILE_E * 6 + so,   Wbl + go);
        }
        {
            uint32_t so = (uint32_t)(crow1 * (PITCH * 2) + ccol1 * 16);
            size_t go = (size_t)crow1 * K + k0 + ccol1 * 8;
            cp16(sb + so,                Abh + go);
            cp16(sb + TILE_E * 2 + so,   Abl + go);
            cp16(sb + TILE_E * 4 + so,   Wbh + go);
            cp16(sb + TILE_E * 6 + so,   Wbl + go);
        }
    };

    prefetch(0, 0);
    CP_COMMIT();

    for (int kt = 0; kt < nchunks; kt++) {
        if (kt + 1 < nchunks) {
            prefetch(kt + 1, (kt + 1) & 1);
            CP_COMMIT();
            CP_WAIT1();
        } else {
            CP_WAIT0();
        }
        __syncthreads();

        const uint32_t sb = sbase + (kt & 1) * (STAGE_E * 2);
        const uint32_t uAh = sb, uAl = sb + TILE_E * 2;
        const uint32_t uWh = sb + TILE_E * 4, uWl = sb + TILE_E * 6;

#pragma unroll
        for (int ks = 0; ks < 2; ks++) {
            const int kb = ks * 32;

            uint32_t aH[2][4], aL[2][4];
#pragma unroll
            for (int mt = 0; mt < 2; mt++) {
                ldsm4(aH[mt], uAh + aoff + mt * 16 * (PITCH * 2) + kb);
                ldsm4(aL[mt], uAl + aoff + mt * 16 * (PITCH * 2) + kb);
            }
            uint32_t bH[4][4], bL[4][4];
#pragma unroll
            for (int np = 0; np < 4; np++) {
                ldsm4(bH[np], uWh + boff + np * 16 * (PITCH * 2) + kb);
                ldsm4(bL[np], uWl + boff + np * 16 * (PITCH * 2) + kb);
            }

#pragma unroll
            for (int mt = 0; mt < 2; mt++)
#pragma unroll
                for (int np = 0; np < 4; np++) {
                    mma16816(acc[mt][2 * np],     aH[mt], bH[np]);
                    mma16816(acc[mt][2 * np],     aH[mt], bL[np]);
                    mma16816(acc[mt][2 * np],     aL[mt], bH[np]);
                    mma16816(acc[mt][2 * np + 1], aH[mt], bH[np] + 2);
                    mma16816(acc[mt][2 * np + 1], aH[mt], bL[np] + 2);
                    mma16816(acc[mt][2 * np + 1], aL[mt], bH[np] + 2);
                }
        }
        __syncthreads();
    }

    // Epilogue
    const int g = lane >> 2, tg = lane & 3;
#pragma unroll
    for (int nt = 0; nt < 8; nt++) {
        const int ncol = warp_n + nt * 8 + tg * 2;
        const float b0 = bias[n0 + ncol], b1 = bias[n0 + ncol + 1];
#pragma unroll
        for (int mt = 0; mt < 2; mt++) {
            const int r0 = m0 + warp_m + mt * 16 + g;
#pragma unroll
            for (int hh = 0; hh < 2; hh++) {
                const int r = r0 + hh * 8;
                const float v0 = acc[mt][nt][2 * hh] + b0;
                const float v1 = acc[mt][nt][2 * hh + 1] + b1;
                const size_t idx = (size_t)r * ldc + col0 + n0 + ncol;
                if (C) {
                    float2 o; o.x = v0; o.y = v1;
                    *(float2*)(C + idx) = o;
                } else {
                    *(uint32_t*)(Ch + idx) = pack_hi(v0, v1);
                    *(uint32_t*)(Cl + idx) = pack_lo(v0, v1);
                }
            }
        }
    }
}

// ---------------------------------------------------------------------------
// HMMA flash attention, full (no mask), bf16 hi/lo 3-term split.
// Grid (S/64, B*H), block 128 (4 warps, 16 q-rows each). Writes att hi/lo.
// ---------------------------------------------------------------------------
#define FPITCH 72   // bf16 per smem row (144 B): conflict-free ldmatrix

__global__ __launch_bounds__(128) void flash_hmma_kernel(
    const __nv_bfloat16* __restrict__ qh, const __nv_bfloat16* __restrict__ ql,
    __nv_bfloat16* __restrict__ atth, __nv_bfloat16* __restrict__ attl)
{
    __shared__ __align__(128) __nv_bfloat16 sKh[64 * FPITCH];
    __shared__ __align__(128) __nv_bfloat16 sKl[64 * FPITCH];
    __shared__ __align__(128) __nv_bfloat16 sVh[64 * FPITCH];
    __shared__ __align__(128) __nv_bfloat16 sVl[64 * FPITCH];

    const int tid = threadIdx.x;
    const int warp = tid >> 5, lane = tid & 31;
    const int g = lane >> 2, t = lane & 3;
    const int q0 = blockIdx.x * 64;
    const int b = blockIdx.y >> 3, h = blockIdx.y & 7;

    const uint32_t uKh = smem_u32(sKh), uKl = smem_u32(sKl);
    const uint32_t uVh = smem_u32(sVh), uVl = smem_u32(sVl);

    const size_t rowQ0 = (size_t)(b * SS + q0 + warp * 16 + g) * D3 + h * HD;
    const size_t rowQ1 = rowQ0 + 8 * D3;
    uint32_t qH[4][4], qL[4][4];
#pragma unroll
    for (int ks = 0; ks < 4; ks++) {
        const int c = ks * 16 + 2 * t;
        qH[ks][0] = *(const uint32_t*)(qh + rowQ0 + c);
        qH[ks][1] = *(const uint32_t*)(qh + rowQ1 + c);
        qH[ks][2] = *(const uint32_t*)(qh + rowQ0 + c + 8);
        qH[ks][3] = *(const uint32_t*)(qh + rowQ1 + c + 8);
        qL[ks][0] = *(const uint32_t*)(ql + rowQ0 + c);
        qL[ks][1] = *(const uint32_t*)(ql + rowQ1 + c);
        qL[ks][2] = *(const uint32_t*)(ql + rowQ0 + c + 8);
        qL[ks][3] = *(const uint32_t*)(ql + rowQ1 + c + 8);
    }

    const int bm = lane >> 3;
    const int kboff = ((lane & 7) + ((bm >> 1) << 3)) * (FPITCH * 2) + ((bm & 1) << 3) * 2;
    const int vboff = ((lane & 7) + ((bm & 1) << 3)) * (FPITCH * 2) + (lane >> 4) * 16;

    float o[8][4];
    float mrow[2], lrow[2];
#pragma unroll
    for (int nt = 0; nt < 8; nt++)
#pragma unroll
        for (int i = 0; i < 4; i++) o[nt][i] = 0.0f;
    mrow[0] = mrow[1] = -1e30f;
    lrow[0] = lrow[1] = 0.0f;

    const size_t kvbase = (size_t)(b * SS) * D3 + h * HD;

    for (int kt = 0; kt < 16; kt++) {
        __syncthreads();
        const size_t tb = kvbase + (size_t)(kt * 64) * D3;
#pragma unroll
        for (int l = 0; l < 4; l++) {
            int idx = tid + l * 128;
            int r = idx >> 3, c4 = idx & 7;
            size_t gsrc = tb + (size_t)r * D3 + c4 * 8;
            int sdst = r * FPITCH + c4 * 8;
            *(uint4*)(sKh + sdst) = *(const uint4*)(qh + gsrc + 512);
            *(uint4*)(sKl + sdst) = *(const uint4*)(ql + gsrc + 512);
            *(uint4*)(sVh + sdst) = *(const uint4*)(qh + gsrc + 1024);
            *(uint4*)(sVl + sdst) = *(const uint4*)(ql + gsrc + 1024);
        }
        __syncthreads();

        float s[8][4];
#pragma unroll
        for (int nt = 0; nt < 8; nt++)
#pragma unroll
            for (int i = 0; i < 4; i++) s[nt][i] = 0.0f;

#pragma unroll
        for (int ks = 0; ks < 4; ks++) {
            const int kb = ks * 32;
#pragma unroll
            for (int np = 0; np < 4; np++) {
                uint32_t kh[4], kl[4];
                ldsm4(kh, uKh + kboff + np * 16 * (FPITCH * 2) + kb);
                ldsm4(kl, uKl + kboff + np * 16 * (FPITCH * 2) + kb);
                mma16816(s[2 * np],     qH[ks], kh);
                mma16816(s[2 * np],     qH[ks], kl);
                mma16816(s[2 * np],     qL[ks], kh);
                mma16816(s[2 * np + 1], qH[ks], kh + 2);
                mma16816(s[2 * np + 1], qH[ks], kl + 2);
                mma16816(s[2 * np + 1], qL[ks], kh + 2);
            }
        }

#pragma unroll
        for (int r = 0; r < 2; r++) {
            float mx = -1e30f;
#pragma unroll
            for (int nt = 0; nt < 8; nt++) {
                s[nt][2 * r]     *= 0.125f;
                s[nt][2 * r + 1] *= 0.125f;
                mx = fmaxf(mx, fmaxf(s[nt][2 * r], s[nt][2 * r + 1]));
            }
            mx = fmaxf(mx, __shfl_xor_sync(0xffffffffu, mx, 1));
            mx = fmaxf(mx, __shfl_xor_sync(0xffffffffu, mx, 2));
            float mnew = fmaxf(mrow[r], mx);
            float alpha = __expf(mrow[r] - mnew);
            float ls = 0.0f;
#pragma unroll
            for (int nt = 0; nt < 8; nt++) {
                float p0 = __expf(s[nt][2 * r] - mnew);
                float p1 = __expf(s[nt][2 * r + 1] - mnew);
                s[nt][2 * r] = p0; s[nt][2 * r + 1] = p1;
                ls += p0 + p1;
            }
            ls += __shfl_xor_sync(0xffffffffu, ls, 1);
            ls += __shfl_xor_sync(0xffffffffu, ls, 2);
            lrow[r] = lrow[r] * alpha + ls;
            mrow[r] = mnew;
#pragma unroll
            for (int nt = 0; nt < 8; nt++) {
                o[nt][2 * r] *= alpha; o[nt][2 * r + 1] *= alpha;
            }
        }

        uint32_t pH[4][4], pL[4][4];
#pragma unroll
        for (int j = 0; j < 4; j++) {
            pH[j][0] = pack_hi(s[2 * j][0], s[2 * j][1]);
            pH[j][1] = pack_hi(s[2 * j][2], s[2 * j][3]);
            pH[j][2] = pack_hi(s[2 * j + 1][0], s[2 * j + 1][1]);
            pH[j][3] = pack_hi(s[2 * j + 1][2], s[2 * j + 1][3]);
            pL[j][0] = pack_lo(s[2 * j][0], s[2 * j][1]);
            pL[j][1] = pack_lo(s[2 * j][2], s[2 * j][3]);
            pL[j][2] = pack_lo(s[2 * j + 1][0], s[2 * j + 1][1]);
            pL[j][3] = pack_lo(s[2 * j + 1][2], s[2 * j + 1][3]);
        }

#pragma unroll
        for (int j = 0; j < 4; j++) {
            const int rb = j * 16 * (FPITCH * 2);
#pragma unroll
            for (int np = 0; np < 4; np++) {
                uint32_t vh[4], vl[4];
                ldsm4t(vh, uVh + vboff + rb + np * 32);
                ldsm4t(vl, uVl + vboff + rb + np * 32);
                mma16816(o[2 * np],     pH[j], vh);
                mma16816(o[2 * np],     pH[j], vl);
                mma16816(o[2 * np],     pL[j], vh);
                mma16816(o[2 * np + 1], pH[j], vh + 2);
                mma16816(o[2 * np + 1], pH[j], vl + 2);
                mma16816(o[2 * np + 1], pL[j], vh + 2);
            }
        }
    }

    const float inv0 = 1.0f / lrow[0], inv1 = 1.0f / lrow[1];
    const size_t orow0 = (size_t)(b * SS + q0 + warp * 16 + g) * DD + h * HD;
    const size_t orow1 = orow0 + 8 * DD;
#pragma unroll
    for (int nt = 0; nt < 8; nt++) {
        const int c = nt * 8 + 2 * t;
        const float a0 = o[nt][0] * inv0, a1 = o[nt][1] * inv0;
        const float b0 = o[nt][2] * inv1, b1 = o[nt][3] * inv1;
        *(uint32_t*)(atth + orow0 + c) = pack_hi(a0, a1);
        *(uint32_t*)(attl + orow0 + c) = pack_lo(a0, a1);
        *(uint32_t*)(atth + orow1 + c) = pack_hi(b0, b1);
        *(uint32_t*)(attl + orow1 + c) = pack_lo(b0, b1);
    }
}

// ---------------------------------------------------------------------------
// Windowed causal attention (fp32 math on hi+lo reconstructed inputs).
// Writes att as bf16 hi/lo.
// ---------------------------------------------------------------------------
template <int W>
__global__ __launch_bounds__(128) void window_attn_kernel(
    const __nv_bfloat16* __restrict__ qh, const __nv_bfloat16* __restrict__ ql,
    __nv_bfloat16* __restrict__ atth, __nv_bfloat16* __restrict__ attl)
{
    __shared__ float Ks[80 * 65];
    __shared__ float Vs[80 * 65];

    const int tid = threadIdx.x;
    const int q0 = blockIdx.x * 64;
    const int bh = blockIdx.y;
    const int b = bh >> 3, h = bh & 7;
    const size_t base = (size_t)b * SS * D3 + h * HD;

    for (int e8 = tid; e8 < 80 * 8; e8 += 128) {
        int r = e8 >> 3, c8 = e8 & 7;
        int s = q0 - 16 + r;
        if (s >= 0) {
            size_t src = base + (size_t)s * D3 + c8 * 8;
            uint4 kh = *(const uint4*)(qh + src + 512);
            uint4 kl = *(const uint4*)(ql + src + 512);
            uint4 vh = *(const uint4*)(qh + src + 1024);
            uint4 vl = *(const uint4*)(ql + src + 1024);
            float* kd = Ks + r * 65 + c8 * 8;
            float* vd = Vs + r * 65 + c8 * 8;
            float2 f;
            f = bf2sum(kh.x, kl.x); kd[0] = f.x; kd[1] = f.y;
            f = bf2sum(kh.y, kl.y); kd[2] = f.x; kd[3] = f.y;
            f = bf2sum(kh.z, kl.z); kd[4] = f.x; kd[5] = f.y;
            f = bf2sum(kh.w, kl.w); kd[6] = f.x; kd[7] = f.y;
            f = bf2sum(vh.x, vl.x); vd[0] = f.x; vd[1] = f.y;
            f = bf2sum(vh.y, vl.y); vd[2] = f.x; vd[3] = f.y;
            f = bf2sum(vh.z, vl.z); vd[4] = f.x; vd[5] = f.y;
            f = bf2sum(vh.w, vl.w); vd[6] = f.x; vd[7] = f.y;
        }
    }
    __syncthreads();

    const int qlid = tid >> 1;
    const int half = tid & 1;
    const int q = q0 + qlid;

    float qreg[32];
#pragma unroll
    for (int dd = 0; dd < 32; dd++) {
        size_t idx = base + (size_t)q * D3 + 2 * dd + half;
        qreg[dd] = (__bfloat162float(qh[idx]) + __bfloat162float(ql[idx])) * 0.125f;
    }

    float sc[W];
    float m = -1e30f;
#pragma unroll
    for (int w = 0; w < W; w++) {
        int k = q - w;
        int kr = qlid + 16 - w;
        float dot = 0.0f;
        if (k >= 0) {
#pragma unroll
            for (int dd = 0; dd < 32; dd++)
                dot += qreg[dd] * Ks[kr * 65 + 2 * dd + half];
        }
        dot += __shfl_xor_sync(0xffffffffu, dot, 1);
        sc[w] = (k >= 0) ? dot : -1e30f;
        m = fmaxf(m, sc[w]);
    }

    float l = 0.0f;
    float p[W];
#pragma unroll
    for (int w = 0; w < W; w++) {
        p[w] = (q - w >= 0) ? __expf(sc[w] - m) : 0.0f;
        l += p[w];
    }

    float o[32];
#pragma unroll
    for (int dd = 0; dd < 32; dd++) o[dd] = 0.0f;
#pragma unroll
    for (int w = 0; w < W; w++) {
        int k = q - w;
        if (k >= 0) {
            int kr = qlid + 16 - w;
#pragma unroll
            for (int dd = 0; dd < 32; dd++)
                o[dd] += p[w] * Vs[kr * 65 + 2 * dd + half];
        }
    }

    float inv = 1.0f / l;
    const size_t drow = (size_t)(b * SS + q) * DD + h * HD;
#pragma unroll
    for (int dd = 0; dd < 32; dd++) {
        float v = o[dd] * inv;
        __nv_bfloat16 hv = __float2bfloat16_rn(v);
        atth[drow + 2 * dd + half] = hv;
        attl[drow + 2 * dd + half] = __float2bfloat16_rn(v - __bfloat162float(hv));
    }
}

// ---------------------------------------------------------------------------
// Launch
// ---------------------------------------------------------------------------
extern "C" void kernel_launch(void* const* d_in, const int* in_sizes, int n_in,
                              void* d_out, int out_size)
{
    const float* x    = (const float*)d_in[0];   // [16,1024,512]
    const float* Wqkv = (const float*)d_in[1];   // [3,1536,512]
    const float* bqkv = (const float*)d_in[2];   // [3,1536]
    const float* Wo   = (const float*)d_in[3];   // [3,512,512]
    const float* bo   = (const float*)d_in[4];   // [3,512]
    const float* Wf   = (const float*)d_in[5];   // [512,1536]
    const float* bf   = (const float*)d_in[6];   // [512]
    float* out = (float*)d_out;

    __nv_bfloat16 *xh, *xl, *qkvh, *qkvl, *atth, *attl, *combh, *combl;
    __nv_bfloat16 *Wqkvh, *Wqkvl, *Woh, *Wol, *Wfh, *Wfl;
    cudaGetSymbolAddress((void**)&xh, g_xh);
    cudaGetSymbolAddress((void**)&xl, g_xl);
    cudaGetSymbolAddress((void**)&qkvh, g_qkvh);
    cudaGetSymbolAddress((void**)&qkvl, g_qkvl);
    cudaGetSymbolAddress((void**)&atth, g_atth);
    cudaGetSymbolAddress((void**)&attl, g_attl);
    cudaGetSymbolAddress((void**)&combh, g_combh);
    cudaGetSymbolAddress((void**)&combl, g_combl);
    cudaGetSymbolAddress((void**)&Wqkvh, g_Wqkvh);
    cudaGetSymbolAddress((void**)&Wqkvl, g_Wqkvl);
    cudaGetSymbolAddress((void**)&Woh, g_Woh);
    cudaGetSymbolAddress((void**)&Wol, g_Wol);
    cudaGetSymbolAddress((void**)&Wfh, g_Wfh);
    cudaGetSymbolAddress((void**)&Wfl, g_Wfl);

    cudaFuncSetAttribute(gemm_bf16_kernel,
                         cudaFuncAttributeMaxDynamicSharedMemorySize, GEMM_SMEM);

    // One-time conversions (cheap; re-done every call for determinism)
    {
        int n4;
        n4 = MM * DD / 4;
        convert_hilo_kernel<<<(n4 + 255) / 256, 256>>>(x, xh, xl, n4);
        n4 = 3 * D3 * DD / 4;
        convert_hilo_kernel<<<(n4 + 255) / 256, 256>>>(Wqkv, Wqkvh, Wqkvl, n4);
        n4 = 3 * DD * DD / 4;
        convert_hilo_kernel<<<(n4 + 255) / 256, 256>>>(Wo, Woh, Wol, n4);
        n4 = DD * D3 / 4;
        convert_hilo_kernel<<<(n4 + 255) / 256, 256>>>(Wf, Wfh, Wfl, n4);
    }

    dim3 gemm_qkv_grid(D3 / 128, MM / 128);   // (12, 128)
    dim3 gemm_d_grid(DD / 128, MM / 128);     // (4, 128)
    dim3 attn_grid(SS / 64, BB * HH);         // (16, 128)

    for (int i = 0; i < 3; i++) {
        gemm_bf16_kernel<<<gemm_qkv_grid, 256, GEMM_SMEM>>>(
            xh, xl, Wqkvh + (size_t)i * D3 * DD, Wqkvl + (size_t)i * D3 * DD,
            bqkv + (size_t)i * D3, nullptr, qkvh, qkvl, DD, D3, 0);

        if (i == 0)
            window_attn_kernel<5><<<attn_grid, 128>>>(qkvh, qkvl, atth, attl);
        else if (i == 1)
            window_attn_kernel<10><<<attn_grid, 128>>>(qkvh, qkvl, atth, attl);
        else
            flash_hmma_kernel<<<attn_grid, 128>>>(qkvh, qkvl, atth, attl);

        gemm_bf16_kernel<<<gemm_d_grid, 256, GEMM_SMEM>>>(
            atth, attl, Woh + (size_t)i * DD * DD, Wol + (size_t)i * DD * DD,
            bo + (size_t)i * DD, nullptr, combh, combl, DD, D3, i * DD);
    }

    gemm_bf16_kernel<<<gemm_d_grid, 256, GEMM_SMEM>>>(
        combh, combl, Wfh, Wfl, bf, out, nullptr, nullptr, D3, DD, 0);
}

// round 8
// speedup vs baseline: 3.6386x; 1.0460x over previous
#include <cuda_runtime.h>
#include <cuda_bf16.h>
#include <cstdint>
#include <math.h>

// Problem constants
#define BB 16
#define SS 1024
#define DD 512
#define HH 8
#define HD 64
#define MM (BB * SS)          // 16384 rows
#define D3 (3 * DD)           // 1536
#define QP (3 * D3)           // 4608 packed qkv width (3 branches)
#define OP D3                 // 1536 att/comb width

// ---------------------------------------------------------------------------
// Scratch (static device globals; no runtime allocation allowed)
// All intermediates are bf16 hi/lo pairs.
// ---------------------------------------------------------------------------
__device__ __nv_bfloat16 g_xh[(size_t)MM * DD],   g_xl[(size_t)MM * DD];
__device__ __nv_bfloat16 g_qkvh[(size_t)MM * QP], g_qkvl[(size_t)MM * QP];
__device__ __nv_bfloat16 g_atth[(size_t)MM * OP], g_attl[(size_t)MM * OP];
__device__ __nv_bfloat16 g_combh[(size_t)MM * OP], g_combl[(size_t)MM * OP];
__device__ __nv_bfloat16 g_Wqkvh[(size_t)3 * D3 * DD], g_Wqkvl[(size_t)3 * D3 * DD];
__device__ __nv_bfloat16 g_Woh[(size_t)3 * DD * DD],   g_Wol[(size_t)3 * DD * DD];
__device__ __nv_bfloat16 g_Wfh[(size_t)DD * D3],   g_Wfl[(size_t)DD * D3];

// ---------------------------------------------------------------------------
// Helpers (base sm_80+ PTX only — NO 'a'-suffix features)
// ---------------------------------------------------------------------------
__device__ __forceinline__ uint32_t smem_u32(const void* p) {
    uint32_t a;
    asm("{ .reg .u64 t; cvta.to.shared.u64 t, %1; cvt.u32.u64 %0, t; }" : "=r"(a) : "l"(p));
    return a;
}
__device__ __forceinline__ void ldsm4(uint32_t* r, uint32_t addr) {
    asm volatile("ldmatrix.sync.aligned.m8n8.x4.shared.b16 {%0,%1,%2,%3}, [%4];"
                 : "=r"(r[0]), "=r"(r[1]), "=r"(r[2]), "=r"(r[3]) : "r"(addr));
}
__device__ __forceinline__ void ldsm4t(uint32_t* r, uint32_t addr) {
    asm volatile("ldmatrix.sync.aligned.m8n8.x4.trans.shared.b16 {%0,%1,%2,%3}, [%4];"
                 : "=r"(r[0]), "=r"(r[1]), "=r"(r[2]), "=r"(r[3]) : "r"(addr));
}
__device__ __forceinline__ void mma16816(float* c, const uint32_t* a, const uint32_t* b) {
    asm volatile("mma.sync.aligned.m16n8k16.row.col.f32.bf16.bf16.f32 "
                 "{%0,%1,%2,%3}, {%4,%5,%6,%7}, {%8,%9}, {%0,%1,%2,%3};"
                 : "+f"(c[0]), "+f"(c[1]), "+f"(c[2]), "+f"(c[3])
                 : "r"(a[0]), "r"(a[1]), "r"(a[2]), "r"(a[3]), "r"(b[0]), "r"(b[1]));
}
__device__ __forceinline__ void cp16(uint32_t saddr, const void* g) {
    asm volatile("cp.async.cg.shared.global [%0], [%1], 16;" :: "r"(saddr), "l"(g));
}
#define CP_COMMIT() asm volatile("cp.async.commit_group;" ::: "memory")
#define CP_WAIT1()  asm volatile("cp.async.wait_group 1;" ::: "memory")
#define CP_WAIT0()  asm volatile("cp.async.wait_group 0;" ::: "memory")

__device__ __forceinline__ uint32_t pack_hi(float x, float y) {
    uint16_t a = __bfloat16_as_ushort(__float2bfloat16_rn(x));
    uint16_t b = __bfloat16_as_ushort(__float2bfloat16_rn(y));
    return (uint32_t)a | ((uint32_t)b << 16);
}
__device__ __forceinline__ uint32_t pack_lo(float x, float y) {
    float xh = __bfloat162float(__float2bfloat16_rn(x));
    float yh = __bfloat162float(__float2bfloat16_rn(y));
    uint16_t a = __bfloat16_as_ushort(__float2bfloat16_rn(x - xh));
    uint16_t b = __bfloat16_as_ushort(__float2bfloat16_rn(y - yh));
    return (uint32_t)a | ((uint32_t)b << 16);
}
__device__ __forceinline__ float2 bf2sum(uint32_t h, uint32_t l) {
    __nv_bfloat162 hb = *reinterpret_cast<__nv_bfloat162*>(&h);
    __nv_bfloat162 lb = *reinterpret_cast<__nv_bfloat162*>(&l);
    float2 hf = __bfloat1622float2(hb), lf = __bfloat1622float2(lb);
    return make_float2(hf.x + lf.x, hf.y + lf.y);
}

// ---------------------------------------------------------------------------
// fp32 -> bf16 hi/lo conversion
// ---------------------------------------------------------------------------
__global__ __launch_bounds__(256) void convert_hilo_kernel(
    const float* __restrict__ src, __nv_bfloat16* __restrict__ h,
    __nv_bfloat16* __restrict__ l, int n4)
{
    int i = blockIdx.x * blockDim.x + threadIdx.x;
    if (i < n4) {
        float4 v = *(const float4*)(src + (size_t)i * 4);
        uint2 ph, pl;
        ph.x = pack_hi(v.x, v.y); ph.y = pack_hi(v.z, v.w);
        pl.x = pack_lo(v.x, v.y); pl.y = pack_lo(v.z, v.w);
        *(uint2*)(h + (size_t)i * 4) = ph;
        *(uint2*)(l + (size_t)i * 4) = pl;
    }
}

// ---------------------------------------------------------------------------
// HMMA GEMM, bf16 hi/lo 3-term split, batched over blockIdx.z.
// Block tile 128x256, KC=32, 8 warps = 2(m) x 4(n), warp tile 64x64.
// Per-z offsets: A col, W base, bias, C col (block-diagonal batched Wo case).
// ---------------------------------------------------------------------------
#define KC 32
#define PITCH 40                         // bf16 per smem row (80 B)
#define A_EL (128 * PITCH)               // 5120 elements per A tile
#define W_EL (256 * PITCH)               // 10240 elements per W tile
#define OFF_AL (A_EL * 2)                // byte offsets inside a stage
#define OFF_WH (A_EL * 4)
#define OFF_WL (A_EL * 4 + W_EL * 2)
#define STAGE_B ((A_EL * 2 + W_EL * 2) * 2)   // 61440 bytes per stage
#define GEMM_SMEM (2 * STAGE_B)               // 122880 bytes

__global__ __launch_bounds__(256, 1) void gemm_bf16_kernel(
    const __nv_bfloat16* __restrict__ Ah, const __nv_bfloat16* __restrict__ Al,
    const __nv_bfloat16* __restrict__ Wh, const __nv_bfloat16* __restrict__ Wl,
    const float* __restrict__ bias, float* __restrict__ C,
    __nv_bfloat16* __restrict__ Ch, __nv_bfloat16* __restrict__ Cl,
    int K, int lda, int ldc, int col0,
    int aColZ, int wZ, int biasZ, int cColZ)
{
    extern __shared__ __nv_bfloat16 smem[];
    const uint32_t sbase = smem_u32(smem);

    const int tid = threadIdx.x;
    const int wid = tid >> 5, lane = tid & 31;
    const int z = blockIdx.z;
    const int m0 = blockIdx.y * 128;
    const int n0 = blockIdx.x * 256;
    const int warp_m = (wid & 1) * 64;
    const int warp_n = (wid >> 1) * 64;

    const __nv_bfloat16* Abh = Ah + (size_t)m0 * lda + (size_t)z * aColZ;
    const __nv_bfloat16* Abl = Al + (size_t)m0 * lda + (size_t)z * aColZ;
    const __nv_bfloat16* Wbh = Wh + (size_t)z * wZ + (size_t)n0 * K;
    const __nv_bfloat16* Wbl = Wl + (size_t)z * wZ + (size_t)n0 * K;
    const float* biasz = bias + (size_t)z * biasZ;
    const int ccol0 = col0 + z * cColZ;

    // ldmatrix per-lane offsets within a tile
    const int aoff = (warp_m + (lane & 15)) * (PITCH * 2) + (((lane >> 4) << 3) << 1);
    const int bm = lane >> 3;
    const int boff = (warp_n + (lane & 7) + ((bm >> 1) << 3)) * (PITCH * 2) + (((bm & 1) << 3) << 1);

    float acc[4][8][4];
#pragma unroll
    for (int mt = 0; mt < 4; mt++)
#pragma unroll
        for (int nt = 0; nt < 8; nt++)
#pragma unroll
            for (int i = 0; i < 4; i++) acc[mt][nt][i] = 0.0f;

    const int nchunks = K / KC;

    auto prefetch = [&](int kt, int stg) {
        const int k0 = kt * KC;
        const uint32_t sb = sbase + stg * STAGE_B;
#pragma unroll
        for (int j = 0; j < 2; j++) {        // A: 128 rows x 4 x 16B per array
            int idx = tid + j * 256;
            int row = idx >> 2, c = idx & 3;
            uint32_t so = (uint32_t)(row * (PITCH * 2) + c * 16);
            size_t go = (size_t)row * lda + k0 + c * 8;
            cp16(sb + so,          Abh + go);
            cp16(sb + OFF_AL + so, Abl + go);
        }
#pragma unroll
        for (int j = 0; j < 4; j++) {        // W: 256 rows x 4 x 16B per array
            int idx = tid + j * 256;
            int row = idx >> 2, c = idx & 3;
            uint32_t so = (uint32_t)(row * (PITCH * 2) + c * 16);
            size_t go = (size_t)row * K + k0 + c * 8;
            cp16(sb + OFF_WH + so, Wbh + go);
            cp16(sb + OFF_WL + so, Wbl + go);
        }
    };

    prefetch(0, 0);
    CP_COMMIT();

    for (int kt = 0; kt < nchunks; kt++) {
        if (kt + 1 < nchunks) {
            prefetch(kt + 1, (kt + 1) & 1);
            CP_COMMIT();
            CP_WAIT1();
        } else {
            CP_WAIT0();
        }
        __syncthreads();

        const uint32_t sb = sbase + (kt & 1) * STAGE_B;
        const uint32_t uAh = sb, uAl = sb + OFF_AL;
        const uint32_t uWh = sb + OFF_WH, uWl = sb + OFF_WL;

#pragma unroll
        for (int ks = 0; ks < 2; ks++) {
            const int kb = ks * 32;

            uint32_t aH[4][4], aL[4][4];
#pragma unroll
            for (int mt = 0; mt < 4; mt++) {
                ldsm4(aH[mt], uAh + aoff + mt * 16 * (PITCH * 2) + kb);
                ldsm4(aL[mt], uAl + aoff + mt * 16 * (PITCH * 2) + kb);
            }
#pragma unroll
            for (int np = 0; np < 4; np++) {
                uint32_t bH[4], bL[4];
                ldsm4(bH, uWh + boff + np * 16 * (PITCH * 2) + kb);
                ldsm4(bL, uWl + boff + np * 16 * (PITCH * 2) + kb);
#pragma unroll
                for (int mt = 0; mt < 4; mt++) {
                    mma16816(acc[mt][2 * np],     aH[mt], bH);
                    mma16816(acc[mt][2 * np],     aH[mt], bL);
                    mma16816(acc[mt][2 * np],     aL[mt], bH);
                    mma16816(acc[mt][2 * np + 1], aH[mt], bH + 2);
                    mma16816(acc[mt][2 * np + 1], aH[mt], bL + 2);
                    mma16816(acc[mt][2 * np + 1], aL[mt], bH + 2);
                }
            }
        }
        __syncthreads();
    }

    // Epilogue
    const int g = lane >> 2, tg = lane & 3;
#pragma unroll
    for (int nt = 0; nt < 8; nt++) {
        const int ncol = warp_n + nt * 8 + tg * 2;
        const float b0 = biasz[n0 + ncol], b1 = biasz[n0 + ncol + 1];
#pragma unroll
        for (int mt = 0; mt < 4; mt++) {
            const int r0 = m0 + warp_m + mt * 16 + g;
#pragma unroll
            for (int hh = 0; hh < 2; hh++) {
                const int r = r0 + hh * 8;
                const float v0 = acc[mt][nt][2 * hh] + b0;
                const float v1 = acc[mt][nt][2 * hh + 1] + b1;
                const size_t idx = (size_t)r * ldc + ccol0 + n0 + ncol;
                if (C) {
                    float2 o; o.x = v0; o.y = v1;
                    *(float2*)(C + idx) = o;
                } else {
                    *(uint32_t*)(Ch + idx) = pack_hi(v0, v1);
                    *(uint32_t*)(Cl + idx) = pack_lo(v0, v1);
                }
            }
        }
    }
}

// ---------------------------------------------------------------------------
// HMMA flash attention (branch 2 of packed qkv). Grid (S/64, B*H), block 128.
// qkv row pitch QP=4608, branch col 3072; out pitch OP=1536, col 1024.
// ---------------------------------------------------------------------------
#define FPITCH 72

__global__ __launch_bounds__(128) void flash_hmma_kernel(
    const __nv_bfloat16* __restrict__ qh, const __nv_bfloat16* __restrict__ ql,
    __nv_bfloat16* __restrict__ atth, __nv_bfloat16* __restrict__ attl)
{
    __shared__ __align__(128) __nv_bfloat16 sKh[64 * FPITCH];
    __shared__ __align__(128) __nv_bfloat16 sKl[64 * FPITCH];
    __shared__ __align__(128) __nv_bfloat16 sVh[64 * FPITCH];
    __shared__ __align__(128) __nv_bfloat16 sVl[64 * FPITCH];

    const int tid = threadIdx.x;
    const int warp = tid >> 5, lane = tid & 31;
    const int g = lane >> 2, t = lane & 3;
    const int q0 = blockIdx.x * 64;
    const int b = blockIdx.y >> 3, h = blockIdx.y & 7;

    const uint32_t uKh = smem_u32(sKh), uKl = smem_u32(sKl);
    const uint32_t uVh = smem_u32(sVh), uVl = smem_u32(sVl);

    const size_t rowQ0 = (size_t)(b * SS + q0 + warp * 16 + g) * QP + 2 * D3 + h * HD;
    const size_t rowQ1 = rowQ0 + (size_t)8 * QP;
    uint32_t qH[4][4], qL[4][4];
#pragma unroll
    for (int ks = 0; ks < 4; ks++) {
        const int c = ks * 16 + 2 * t;
        qH[ks][0] = *(const uint32_t*)(qh + rowQ0 + c);
        qH[ks][1] = *(const uint32_t*)(qh + rowQ1 + c);
        qH[ks][2] = *(const uint32_t*)(qh + rowQ0 + c + 8);
        qH[ks][3] = *(const uint32_t*)(qh + rowQ1 + c + 8);
        qL[ks][0] = *(const uint32_t*)(ql + rowQ0 + c);
        qL[ks][1] = *(const uint32_t*)(ql + rowQ1 + c);
        qL[ks][2] = *(const uint32_t*)(ql + rowQ0 + c + 8);
        qL[ks][3] = *(const uint32_t*)(ql + rowQ1 + c + 8);
    }

    const int bm = lane >> 3;
    const int kboff = ((lane & 7) + ((bm >> 1) << 3)) * (FPITCH * 2) + ((bm & 1) << 3) * 2;
    const int vboff = ((lane & 7) + ((bm & 1) << 3)) * (FPITCH * 2) + (lane >> 4) * 16;

    float o[8][4];
    float mrow[2], lrow[2];
#pragma unroll
    for (int nt = 0; nt < 8; nt++)
#pragma unroll
        for (int i = 0; i < 4; i++) o[nt][i] = 0.0f;
    mrow[0] = mrow[1] = -1e30f;
    lrow[0] = lrow[1] = 0.0f;

    const size_t kvbase = (size_t)(b * SS) * QP + 2 * D3 + h * HD;

    for (int kt = 0; kt < 16; kt++) {
        __syncthreads();
        const size_t tb = kvbase + (size_t)(kt * 64) * QP;
#pragma unroll
        for (int l = 0; l < 4; l++) {
            int idx = tid + l * 128;
            int r = idx >> 3, c4 = idx & 7;
            size_t gsrc = tb + (size_t)r * QP + c4 * 8;
            int sdst = r * FPITCH + c4 * 8;
            *(uint4*)(sKh + sdst) = *(const uint4*)(qh + gsrc + 512);
            *(uint4*)(sKl + sdst) = *(const uint4*)(ql + gsrc + 512);
            *(uint4*)(sVh + sdst) = *(const uint4*)(qh + gsrc + 1024);
            *(uint4*)(sVl + sdst) = *(const uint4*)(ql + gsrc + 1024);
        }
        __syncthreads();

        float s[8][4];
#pragma unroll
        for (int nt = 0; nt < 8; nt++)
#pragma unroll
            for (int i = 0; i < 4; i++) s[nt][i] = 0.0f;

#pragma unroll
        for (int ks = 0; ks < 4; ks++) {
            const int kb = ks * 32;
#pragma unroll
            for (int np = 0; np < 4; np++) {
                uint32_t kh[4], kl[4];
                ldsm4(kh, uKh + kboff + np * 16 * (FPITCH * 2) + kb);
                ldsm4(kl, uKl + kboff + np * 16 * (FPITCH * 2) + kb);
                mma16816(s[2 * np],     qH[ks], kh);
                mma16816(s[2 * np],     qH[ks], kl);
                mma16816(s[2 * np],     qL[ks], kh);
                mma16816(s[2 * np + 1], qH[ks], kh + 2);
                mma16816(s[2 * np + 1], qH[ks], kl + 2);
                mma16816(s[2 * np + 1], qL[ks], kh + 2);
            }
        }

#pragma unroll
        for (int r = 0; r < 2; r++) {
            float mx = -1e30f;
#pragma unroll
            for (int nt = 0; nt < 8; nt++) {
                s[nt][2 * r]     *= 0.125f;
                s[nt][2 * r + 1] *= 0.125f;
                mx = fmaxf(mx, fmaxf(s[nt][2 * r], s[nt][2 * r + 1]));
            }
            mx = fmaxf(mx, __shfl_xor_sync(0xffffffffu, mx, 1));
            mx = fmaxf(mx, __shfl_xor_sync(0xffffffffu, mx, 2));
            float mnew = fmaxf(mrow[r], mx);
            float alpha = __expf(mrow[r] - mnew);
            float ls = 0.0f;
#pragma unroll
            for (int nt = 0; nt < 8; nt++) {
                float p0 = __expf(s[nt][2 * r] - mnew);
                float p1 = __expf(s[nt][2 * r + 1] - mnew);
                s[nt][2 * r] = p0; s[nt][2 * r + 1] = p1;
                ls += p0 + p1;
            }
            ls += __shfl_xor_sync(0xffffffffu, ls, 1);
            ls += __shfl_xor_sync(0xffffffffu, ls, 2);
            lrow[r] = lrow[r] * alpha + ls;
            mrow[r] = mnew;
#pragma unroll
            for (int nt = 0; nt < 8; nt++) {
                o[nt][2 * r] *= alpha; o[nt][2 * r + 1] *= alpha;
            }
        }

        uint32_t pH[4][4], pL[4][4];
#pragma unroll
        for (int j = 0; j < 4; j++) {
            pH[j][0] = pack_hi(s[2 * j][0], s[2 * j][1]);
            pH[j][1] = pack_hi(s[2 * j][2], s[2 * j][3]);
            pH[j][2] = pack_hi(s[2 * j + 1][0], s[2 * j + 1][1]);
            pH[j][3] = pack_hi(s[2 * j + 1][2], s[2 * j + 1][3]);
            pL[j][0] = pack_lo(s[2 * j][0], s[2 * j][1]);
            pL[j][1] = pack_lo(s[2 * j][2], s[2 * j][3]);
            pL[j][2] = pack_lo(s[2 * j + 1][0], s[2 * j + 1][1]);
            pL[j][3] = pack_lo(s[2 * j + 1][2], s[2 * j + 1][3]);
        }

#pragma unroll
        for (int j = 0; j < 4; j++) {
            const int rb = j * 16 * (FPITCH * 2);
#pragma unroll
            for (int np = 0; np < 4; np++) {
                uint32_t vh[4], vl[4];
                ldsm4t(vh, uVh + vboff + rb + np * 32);
                ldsm4t(vl, uVl + vboff + rb + np * 32);
                mma16816(o[2 * np],     pH[j], vh);
                mma16816(o[2 * np],     pH[j], vl);
                mma16816(o[2 * np],     pL[j], vh);
                mma16816(o[2 * np + 1], pH[j], vh + 2);
                mma16816(o[2 * np + 1], pH[j], vl + 2);
                mma16816(o[2 * np + 1], pL[j], vh + 2);
            }
        }
    }

    const float inv0 = 1.0f / lrow[0], inv1 = 1.0f / lrow[1];
    const size_t orow0 = (size_t)(b * SS + q0 + warp * 16 + g) * OP + 2 * DD + h * HD;
    const size_t orow1 = orow0 + (size_t)8 * OP;
#pragma unroll
    for (int nt = 0; nt < 8; nt++) {
        const int c = nt * 8 + 2 * t;
        const float a0 = o[nt][0] * inv0, a1 = o[nt][1] * inv0;
        const float b0 = o[nt][2] * inv1, b1 = o[nt][3] * inv1;
        *(uint32_t*)(atth + orow0 + c) = pack_hi(a0, a1);
        *(uint32_t*)(attl + orow0 + c) = pack_lo(a0, a1);
        *(uint32_t*)(atth + orow1 + c) = pack_hi(b0, b1);
        *(uint32_t*)(attl + orow1 + c) = pack_lo(b0, b1);
    }
}

// ---------------------------------------------------------------------------
// Windowed causal attention, both branches in one launch (blockIdx.z = branch).
// Branch br reads packed qkv at col br*1536, writes att at col br*512.
// ---------------------------------------------------------------------------
template <int W>
__device__ __forceinline__ void window_body(
    const __nv_bfloat16* __restrict__ qh, const __nv_bfloat16* __restrict__ ql,
    __nv_bfloat16* __restrict__ atth, __nv_bfloat16* __restrict__ attl,
    float* Ks, float* Vs, int br)
{
    const int tid = threadIdx.x;
    const int q0 = blockIdx.x * 64;
    const int bh = blockIdx.y;
    const int b = bh >> 3, h = bh & 7;
    const size_t base = (size_t)b * SS * QP + (size_t)br * D3 + h * HD;

    for (int e8 = tid; e8 < 80 * 8; e8 += 128) {
        int r = e8 >> 3, c8 = e8 & 7;
        int s = q0 - 16 + r;
        if (s >= 0) {
            size_t src = base + (size_t)s * QP + c8 * 8;
            uint4 kh = *(const uint4*)(qh + src + 512);
            uint4 kl = *(const uint4*)(ql + src + 512);
            uint4 vh = *(const uint4*)(qh + src + 1024);
            uint4 vl = *(const uint4*)(ql + src + 1024);
            float* kd = Ks + r * 65 + c8 * 8;
            float* vd = Vs + r * 65 + c8 * 8;
            float2 f;
            f = bf2sum(kh.x, kl.x); kd[0] = f.x; kd[1] = f.y;
            f = bf2sum(kh.y, kl.y); kd[2] = f.x; kd[3] = f.y;
            f = bf2sum(kh.z, kl.z); kd[4] = f.x; kd[5] = f.y;
            f = bf2sum(kh.w, kl.w); kd[6] = f.x; kd[7] = f.y;
            f = bf2sum(vh.x, vl.x); vd[0] = f.x; vd[1] = f.y;
            f = bf2sum(vh.y, vl.y); vd[2] = f.x; vd[3] = f.y;
            f = bf2sum(vh.z, vl.z); vd[4] = f.x; vd[5] = f.y;
            f = bf2sum(vh.w, vl.w); vd[6] = f.x; vd[7] = f.y;
        }
    }
    __syncthreads();

    const int qlid = tid >> 1;
    const int half = tid & 1;
    const int q = q0 + qlid;

    float qreg[32];
#pragma unroll
    for (int dd = 0; dd < 32; dd++) {
        size_t idx = base + (size_t)q * QP + 2 * dd + half;
        qreg[dd] = (__bfloat162float(qh[idx]) + __bfloat162float(ql[idx])) * 0.125f;
    }

    float sc[W];
    float m = -1e30f;
#pragma unroll
    for (int w = 0; w < W; w++) {
        int k = q - w;
        int kr = qlid + 16 - w;
        float dot = 0.0f;
        if (k >= 0) {
#pragma unroll
            for (int dd = 0; dd < 32; dd++)
                dot += qreg[dd] * Ks[kr * 65 + 2 * dd + half];
        }
        dot += __shfl_xor_sync(0xffffffffu, dot, 1);
        sc[w] = (k >= 0) ? dot : -1e30f;
        m = fmaxf(m, sc[w]);
    }

    float l = 0.0f;
    float p[W];
#pragma unroll
    for (int w = 0; w < W; w++) {
        p[w] = (q - w >= 0) ? __expf(sc[w] - m) : 0.0f;
        l += p[w];
    }

    float o[32];
#pragma unroll
    for (int dd = 0; dd < 32; dd++) o[dd] = 0.0f;
#pragma unroll
    for (int w = 0; w < W; w++) {
        int k = q - w;
        if (k >= 0) {
            int kr = qlid + 16 - w;
#pragma unroll
            for (int dd = 0; dd < 32; dd++)
                o[dd] += p[w] * Vs[kr * 65 + 2 * dd + half];
        }
    }

    float inv = 1.0f / l;
    const size_t drow = (size_t)(b * SS + q) * OP + (size_t)br * DD + h * HD;
#pragma unroll
    for (int dd = 0; dd < 32; dd++) {
        float v = o[dd] * inv;
        __nv_bfloat16 hv = __float2bfloat16_rn(v);
        atth[drow + 2 * dd + half] = hv;
        attl[drow + 2 * dd + half] = __float2bfloat16_rn(v - __bfloat162float(hv));
    }
}

__global__ __launch_bounds__(128) void window_attn_kernel(
    const __nv_bfloat16* __restrict__ qh, const __nv_bfloat16* __restrict__ ql,
    __nv_bfloat16* __restrict__ atth, __nv_bfloat16* __restrict__ attl)
{
    __shared__ float Ks[80 * 65];
    __shared__ float Vs[80 * 65];
    if (blockIdx.z == 0)
        window_body<5>(qh, ql, atth, attl, Ks, Vs, 0);
    else
        window_body<10>(qh, ql, atth, attl, Ks, Vs, 1);
}

// ---------------------------------------------------------------------------
// Launch
// ---------------------------------------------------------------------------
extern "C" void kernel_launch(void* const* d_in, const int* in_sizes, int n_in,
                              void* d_out, int out_size)
{
    const float* x    = (const float*)d_in[0];   // [16,1024,512]
    const float* Wqkv = (const float*)d_in[1];   // [3,1536,512] = [4608,512]
    const float* bqkv = (const float*)d_in[2];   // [3,1536] = [4608]
    const float* Wo   = (const float*)d_in[3];   // [3,512,512]
    const float* bo   = (const float*)d_in[4];   // [3,512]
    const float* Wf   = (const float*)d_in[5];   // [512,1536]
    const float* bf   = (const float*)d_in[6];   // [512]
    float* out = (float*)d_out;

    __nv_bfloat16 *xh, *xl, *qkvh, *qkvl, *atth, *attl, *combh, *combl;
    __nv_bfloat16 *Wqkvh, *Wqkvl, *Woh, *Wol, *Wfh, *Wfl;
    cudaGetSymbolAddress((void**)&xh, g_xh);
    cudaGetSymbolAddress((void**)&xl, g_xl);
    cudaGetSymbolAddress((void**)&qkvh, g_qkvh);
    cudaGetSymbolAddress((void**)&qkvl, g_qkvl);
    cudaGetSymbolAddress((void**)&atth, g_atth);
    cudaGetSymbolAddress((void**)&attl, g_attl);
    cudaGetSymbolAddress((void**)&combh, g_combh);
    cudaGetSymbolAddress((void**)&combl, g_combl);
    cudaGetSymbolAddress((void**)&Wqkvh, g_Wqkvh);
    cudaGetSymbolAddress((void**)&Wqkvl, g_Wqkvl);
    cudaGetSymbolAddress((void**)&Woh, g_Woh);
    cudaGetSymbolAddress((void**)&Wol, g_Wol);
    cudaGetSymbolAddress((void**)&Wfh, g_Wfh);
    cudaGetSymbolAddress((void**)&Wfl, g_Wfl);

    cudaFuncSetAttribute(gemm_bf16_kernel,
                         cudaFuncAttributeMaxDynamicSharedMemorySize, GEMM_SMEM);

    // Conversions
    {
        int n4;
        n4 = MM * DD / 4;
        convert_hilo_kernel<<<(n4 + 255) / 256, 256>>>(x, xh, xl, n4);
        n4 = 3 * D3 * DD / 4;
        convert_hilo_kernel<<<(n4 + 255) / 256, 256>>>(Wqkv, Wqkvh, Wqkvl, n4);
        n4 = 3 * DD * DD / 4;
        convert_hilo_kernel<<<(n4 + 255) / 256, 256>>>(Wo, Woh, Wol, n4);
        n4 = DD * D3 / 4;
        convert_hilo_kernel<<<(n4 + 255) / 256, 256>>>(Wf, Wfh, Wfl, n4);
    }

    // 1) All three QKV projections as one GEMM: [MM,512] x [4608,512]^T -> [MM,4608]
    {
        dim3 grid(QP / 256, MM / 128, 1);
        gemm_bf16_kernel<<<grid, 256, GEMM_SMEM>>>(
            xh, xl, Wqkvh, Wqkvl, bqkv, nullptr, qkvh, qkvl,
            DD, DD, QP, 0, 0, 0, 0, 0);
    }

    // 2) Attention: both windows (one launch) + flash
    {
        dim3 wgrid(SS / 64, BB * HH, 2);
        window_attn_kernel<<<wgrid, 128>>>(qkvh, qkvl, atth, attl);
        dim3 fgrid(SS / 64, BB * HH, 1);
        flash_hmma_kernel<<<fgrid, 128>>>(qkvh, qkvl, atth, attl);
    }

    // 3) Batched out-projections: comb[:, z*512+n] = att[:, z*512+k] @ Wo[z]^T + bo[z]
    {
        dim3 grid(DD / 256, MM / 128, 3);
        gemm_bf16_kernel<<<grid, 256, GEMM_SMEM>>>(
            atth, attl, Woh, Wol, bo, nullptr, combh, combl,
            DD, OP, OP, 0, DD, DD * DD, DD, DD);
    }

    // 4) Final projection: [MM,1536] x [512,1536]^T -> [MM,512] (fp32 out)
    {
        dim3 grid(DD / 256, MM / 128, 1);
        gemm_bf16_kernel<<<grid, 256, GEMM_SMEM>>>(
            combh, combl, Wfh, Wfl, bf, out, nullptr, nullptr,
            D3, D3, DD, 0, 0, 0, 0, 0);
    }
}

// round 10
// speedup vs baseline: 3.9898x; 1.0965x over previous
#include <cuda_runtime.h>
#include <cuda_bf16.h>
#include <cstdint>
#include <math.h>

// Problem constants
#define BB 16
#define SS 1024
#define DD 512
#define HH 8
#define HD 64
#define MM (BB * SS)          // 16384 rows
#define D3 (3 * DD)           // 1536
#define QP (3 * D3)           // 4608 packed qkv width (3 branches)
#define OP D3                 // 1536 att/comb width

// ---------------------------------------------------------------------------
// Scratch (static device globals; no runtime allocation allowed)
// ---------------------------------------------------------------------------
__device__ __nv_bfloat16 g_xh[(size_t)MM * DD],   g_xl[(size_t)MM * DD];
__device__ __nv_bfloat16 g_qkvh[(size_t)MM * QP], g_qkvl[(size_t)MM * QP];
__device__ __nv_bfloat16 g_atth[(size_t)MM * OP], g_attl[(size_t)MM * OP];
__device__ __nv_bfloat16 g_combh[(size_t)MM * OP], g_combl[(size_t)MM * OP];
__device__ __nv_bfloat16 g_Wqkvh[(size_t)3 * D3 * DD], g_Wqkvl[(size_t)3 * D3 * DD];
__device__ __nv_bfloat16 g_Woh[(size_t)3 * DD * DD],   g_Wol[(size_t)3 * DD * DD];
__device__ __nv_bfloat16 g_Wfh[(size_t)DD * D3],   g_Wfl[(size_t)DD * D3];

// ---------------------------------------------------------------------------
// Helpers (base sm_80+ PTX only — NO 'a'-suffix features)
// ---------------------------------------------------------------------------
__device__ __forceinline__ uint32_t smem_u32(const void* p) {
    uint32_t a;
    asm("{ .reg .u64 t; cvta.to.shared.u64 t, %1; cvt.u32.u64 %0, t; }" : "=r"(a) : "l"(p));
    return a;
}
__device__ __forceinline__ void ldsm4(uint32_t* r, uint32_t addr) {
    asm volatile("ldmatrix.sync.aligned.m8n8.x4.shared.b16 {%0,%1,%2,%3}, [%4];"
                 : "=r"(r[0]), "=r"(r[1]), "=r"(r[2]), "=r"(r[3]) : "r"(addr));
}
__device__ __forceinline__ void ldsm4t(uint32_t* r, uint32_t addr) {
    asm volatile("ldmatrix.sync.aligned.m8n8.x4.trans.shared.b16 {%0,%1,%2,%3}, [%4];"
                 : "=r"(r[0]), "=r"(r[1]), "=r"(r[2]), "=r"(r[3]) : "r"(addr));
}
__device__ __forceinline__ void mma16816(float* c, const uint32_t* a, const uint32_t* b) {
    asm volatile("mma.sync.aligned.m16n8k16.row.col.f32.bf16.bf16.f32 "
                 "{%0,%1,%2,%3}, {%4,%5,%6,%7}, {%8,%9}, {%0,%1,%2,%3};"
                 : "+f"(c[0]), "+f"(c[1]), "+f"(c[2]), "+f"(c[3])
                 : "r"(a[0]), "r"(a[1]), "r"(a[2]), "r"(a[3]), "r"(b[0]), "r"(b[1]));
}
__device__ __forceinline__ void cp16(uint32_t saddr, const void* g) {
    asm volatile("cp.async.cg.shared.global [%0], [%1], 16;" :: "r"(saddr), "l"(g));
}
#define CP_COMMIT() asm volatile("cp.async.commit_group;" ::: "memory")
#define CP_WAIT1()  asm volatile("cp.async.wait_group 1;" ::: "memory")
#define CP_WAIT0()  asm volatile("cp.async.wait_group 0;" ::: "memory")

__device__ __forceinline__ uint32_t pack_hi(float x, float y) {
    uint16_t a = __bfloat16_as_ushort(__float2bfloat16_rn(x));
    uint16_t b = __bfloat16_as_ushort(__float2bfloat16_rn(y));
    return (uint32_t)a | ((uint32_t)b << 16);
}
__device__ __forceinline__ uint32_t pack_lo(float x, float y) {
    float xh = __bfloat162float(__float2bfloat16_rn(x));
    float yh = __bfloat162float(__float2bfloat16_rn(y));
    uint16_t a = __bfloat16_as_ushort(__float2bfloat16_rn(x - xh));
    uint16_t b = __bfloat16_as_ushort(__float2bfloat16_rn(y - yh));
    return (uint32_t)a | ((uint32_t)b << 16);
}
__device__ __forceinline__ float2 bf2sum(uint32_t h, uint32_t l) {
    __nv_bfloat162 hb = *reinterpret_cast<__nv_bfloat162*>(&h);
    __nv_bfloat162 lb = *reinterpret_cast<__nv_bfloat162*>(&l);
    float2 hf = __bfloat1622float2(hb), lf = __bfloat1622float2(lb);
    return make_float2(hf.x + lf.x, hf.y + lf.y);
}

// ---------------------------------------------------------------------------
// fp32 -> bf16 hi/lo conversion
// ---------------------------------------------------------------------------
__global__ __launch_bounds__(256) void convert_hilo_kernel(
    const float* __restrict__ src, __nv_bfloat16* __restrict__ h,
    __nv_bfloat16* __restrict__ l, int n4)
{
    int i = blockIdx.x * blockDim.x + threadIdx.x;
    if (i < n4) {
        float4 v = *(const float4*)(src + (size_t)i * 4);
        uint2 ph, pl;
        ph.x = pack_hi(v.x, v.y); ph.y = pack_hi(v.z, v.w);
        pl.x = pack_lo(v.x, v.y); pl.y = pack_lo(v.z, v.w);
        *(uint2*)(h + (size_t)i * 4) = ph;
        *(uint2*)(l + (size_t)i * 4) = pl;
    }
}

// ---------------------------------------------------------------------------
// HMMA GEMM, bf16 hi/lo 3-term split, batched over blockIdx.z.
// Block tile 128x256, KC=32, 8 warps = 2(m) x 4(n), warp tile 64x64.
// 3-stage cp.async pipeline, one __syncthreads per chunk.
// ---------------------------------------------------------------------------
#define KC 32
#define PITCH 40                         // bf16 per smem row (80 B)
#define A_EL (128 * PITCH)               // 5120 elements per A tile
#define W_EL (256 * PITCH)               // 10240 elements per W tile
#define OFF_AL (A_EL * 2)                // byte offsets inside a stage
#define OFF_WH (A_EL * 4)
#define OFF_WL (A_EL * 4 + W_EL * 2)
#define STAGE_B ((A_EL * 2 + W_EL * 2) * 2)   // 61440 bytes per stage
#define GEMM_SMEM (3 * STAGE_B)               // 184320 bytes (3 stages)

__global__ __launch_bounds__(256, 1) void gemm_bf16_kernel(
    const __nv_bfloat16* __restrict__ Ah, const __nv_bfloat16* __restrict__ Al,
    const __nv_bfloat16* __restrict__ Wh, const __nv_bfloat16* __restrict__ Wl,
    const float* __restrict__ bias, float* __restrict__ C,
    __nv_bfloat16* __restrict__ Ch, __nv_bfloat16* __restrict__ Cl,
    int K, int lda, int ldc, int col0,
    int aColZ, int wZ, int biasZ, int cColZ)
{
    extern __shared__ __nv_bfloat16 smem[];
    const uint32_t sbase = smem_u32(smem);

    const int tid = threadIdx.x;
    const int wid = tid >> 5, lane = tid & 31;
    const int z = blockIdx.z;
    const int m0 = blockIdx.y * 128;
    const int n0 = blockIdx.x * 256;
    const int warp_m = (wid & 1) * 64;
    const int warp_n = (wid >> 1) * 64;

    const __nv_bfloat16* Abh = Ah + (size_t)m0 * lda + (size_t)z * aColZ;
    const __nv_bfloat16* Abl = Al + (size_t)m0 * lda + (size_t)z * aColZ;
    const __nv_bfloat16* Wbh = Wh + (size_t)z * wZ + (size_t)n0 * K;
    const __nv_bfloat16* Wbl = Wl + (size_t)z * wZ + (size_t)n0 * K;
    const float* biasz = bias + (size_t)z * biasZ;
    const int ccol0 = col0 + z * cColZ;

    const int aoff = (warp_m + (lane & 15)) * (PITCH * 2) + (((lane >> 4) << 3) << 1);
    const int bm = lane >> 3;
    const int boff = (warp_n + (lane & 7) + ((bm >> 1) << 3)) * (PITCH * 2) + (((bm & 1) << 3) << 1);

    float acc[4][8][4];
#pragma unroll
    for (int mt = 0; mt < 4; mt++)
#pragma unroll
        for (int nt = 0; nt < 8; nt++)
#pragma unroll
            for (int i = 0; i < 4; i++) acc[mt][nt][i] = 0.0f;

    const int nchunks = K / KC;

    auto prefetch = [&](int kt, int stg) {
        const int k0 = kt * KC;
        const uint32_t sb = sbase + stg * STAGE_B;
#pragma unroll
        for (int j = 0; j < 2; j++) {        // A: 128 rows x 4 x 16B per array
            int idx = tid + j * 256;
            int row = idx >> 2, c = idx & 3;
            uint32_t so = (uint32_t)(row * (PITCH * 2) + c * 16);
            size_t go = (size_t)row * lda + k0 + c * 8;
            cp16(sb + so,          Abh + go);
            cp16(sb + OFF_AL + so, Abl + go);
        }
#pragma unroll
        for (int j = 0; j < 4; j++) {        // W: 256 rows x 4 x 16B per array
            int idx = tid + j * 256;
            int row = idx >> 2, c = idx & 3;
            uint32_t so = (uint32_t)(row * (PITCH * 2) + c * 16);
            size_t go = (size_t)row * K + k0 + c * 8;
            cp16(sb + OFF_WH + so, Wbh + go);
            cp16(sb + OFF_WL + so, Wbl + go);
        }
    };

    prefetch(0, 0);
    CP_COMMIT();
    prefetch(1, 1);
    CP_COMMIT();

    int stg = 0;
    for (int kt = 0; kt < nchunks; kt++) {
        if (kt + 1 < nchunks) { CP_WAIT1(); } else { CP_WAIT0(); }
        __syncthreads();   // all warps past compute of kt-1; stage (kt+2)%3 free

        if (kt + 2 < nchunks) {
            int ns = stg + 2; if (ns >= 3) ns -= 3;
            prefetch(kt + 2, ns);
            CP_COMMIT();
        }

        const uint32_t sb = sbase + stg * STAGE_B;
        const uint32_t uAh = sb, uAl = sb + OFF_AL;
        const uint32_t uWh = sb + OFF_WH, uWl = sb + OFF_WL;

#pragma unroll
        for (int ks = 0; ks < 2; ks++) {
            const int kb = ks * 32;

            uint32_t aH[4][4], aL[4][4];
#pragma unroll
            for (int mt = 0; mt < 4; mt++) {
                ldsm4(aH[mt], uAh + aoff + mt * 16 * (PITCH * 2) + kb);
                ldsm4(aL[mt], uAl + aoff + mt * 16 * (PITCH * 2) + kb);
            }
#pragma unroll
            for (int np = 0; np < 4; np++) {
                uint32_t bH[4], bL[4];
                ldsm4(bH, uWh + boff + np * 16 * (PITCH * 2) + kb);
                ldsm4(bL, uWl + boff + np * 16 * (PITCH * 2) + kb);
#pragma unroll
                for (int mt = 0; mt < 4; mt++) {
                    mma16816(acc[mt][2 * np],     aH[mt], bH);
                    mma16816(acc[mt][2 * np],     aH[mt], bL);
                    mma16816(acc[mt][2 * np],     aL[mt], bH);
                    mma16816(acc[mt][2 * np + 1], aH[mt], bH + 2);
                    mma16816(acc[mt][2 * np + 1], aH[mt], bL + 2);
                    mma16816(acc[mt][2 * np + 1], aL[mt], bH + 2);
                }
            }
        }
        if (++stg >= 3) stg = 0;
    }

    // Epilogue
    const int g = lane >> 2, tg = lane & 3;
#pragma unroll
    for (int nt = 0; nt < 8; nt++) {
        const int ncol = warp_n + nt * 8 + tg * 2;
        const float b0 = biasz[n0 + ncol], b1 = biasz[n0 + ncol + 1];
#pragma unroll
        for (int mt = 0; mt < 4; mt++) {
            const int r0 = m0 + warp_m + mt * 16 + g;
#pragma unroll
            for (int hh = 0; hh < 2; hh++) {
                const int r = r0 + hh * 8;
                const float v0 = acc[mt][nt][2 * hh] + b0;
                const float v1 = acc[mt][nt][2 * hh + 1] + b1;
                const size_t idx = (size_t)r * ldc + ccol0 + n0 + ncol;
                if (C) {
                    float2 o; o.x = v0; o.y = v1;
                    *(float2*)(C + idx) = o;
                } else {
                    *(uint32_t*)(Ch + idx) = pack_hi(v0, v1);
                    *(uint32_t*)(Cl + idx) = pack_lo(v0, v1);
                }
            }
        }
    }
}

// ---------------------------------------------------------------------------
// HMMA flash attention (branch 2 of packed qkv). Grid (S/64, B*H), block 128.
// 2-stage cp.async K/V staging. Dynamic smem 73728 B.
// ---------------------------------------------------------------------------
#define FPITCH 72
#define FTILE_B (64 * FPITCH * 2)         // 9216 bytes per tile
#define FSTAGE_B (4 * FTILE_B)            // 36864 bytes per stage (Kh,Kl,Vh,Vl)
#define FLASH_SMEM (2 * FSTAGE_B)         // 73728 bytes

__global__ __launch_bounds__(128) void flash_hmma_kernel(
    const __nv_bfloat16* __restrict__ qh, const __nv_bfloat16* __restrict__ ql,
    __nv_bfloat16* __restrict__ atth, __nv_bfloat16* __restrict__ attl)
{
    extern __shared__ __nv_bfloat16 fsm[];
    const uint32_t sbase = smem_u32(fsm);

    const int tid = threadIdx.x;
    const int warp = tid >> 5, lane = tid & 31;
    const int g = lane >> 2, t = lane & 3;
    const int q0 = blockIdx.x * 64;
    const int b = blockIdx.y >> 3, h = blockIdx.y & 7;

    const size_t rowQ0 = (size_t)(b * SS + q0 + warp * 16 + g) * QP + 2 * D3 + h * HD;
    const size_t rowQ1 = rowQ0 + (size_t)8 * QP;
    uint32_t qH[4][4], qL[4][4];
#pragma unroll
    for (int ks = 0; ks < 4; ks++) {
        const int c = ks * 16 + 2 * t;
        qH[ks][0] = *(const uint32_t*)(qh + rowQ0 + c);
        qH[ks][1] = *(const uint32_t*)(qh + rowQ1 + c);
        qH[ks][2] = *(const uint32_t*)(qh + rowQ0 + c + 8);
        qH[ks][3] = *(const uint32_t*)(qh + rowQ1 + c + 8);
        qL[ks][0] = *(const uint32_t*)(ql + rowQ0 + c);
        qL[ks][1] = *(const uint32_t*)(ql + rowQ1 + c);
        qL[ks][2] = *(const uint32_t*)(ql + rowQ0 + c + 8);
        qL[ks][3] = *(const uint32_t*)(ql + rowQ1 + c + 8);
    }

    const int bm = lane >> 3;
    const int kboff = ((lane & 7) + ((bm >> 1) << 3)) * (FPITCH * 2) + ((bm & 1) << 3) * 2;
    const int vboff = ((lane & 7) + ((bm & 1) << 3)) * (FPITCH * 2) + (lane >> 4) * 16;

    float o[8][4];
    float mrow[2], lrow[2];
#pragma unroll
    for (int nt = 0; nt < 8; nt++)
#pragma unroll
        for (int i = 0; i < 4; i++) o[nt][i] = 0.0f;
    mrow[0] = mrow[1] = -1e30f;
    lrow[0] = lrow[1] = 0.0f;

    const size_t kvbase = (size_t)(b * SS) * QP + 2 * D3 + h * HD;

    auto prefetch_kv = [&](int kt, int stg) {
        const size_t tb = kvbase + (size_t)(kt * 64) * QP;
        const uint32_t sb = sbase + stg * FSTAGE_B;
#pragma unroll
        for (int l = 0; l < 4; l++) {
            int idx = tid + l * 128;
            int r = idx >> 3, c4 = idx & 7;
            size_t gsrc = tb + (size_t)r * QP + c4 * 8;
            uint32_t sdst = (uint32_t)(r * (FPITCH * 2) + c4 * 16);
            cp16(sb + sdst,               qh + gsrc + 512);
            cp16(sb + FTILE_B + sdst,     ql + gsrc + 512);
            cp16(sb + 2 * FTILE_B + sdst, qh + gsrc + 1024);
            cp16(sb + 3 * FTILE_B + sdst, ql + gsrc + 1024);
        }
    };

    prefetch_kv(0, 0);
    CP_COMMIT();

    for (int kt = 0; kt < 16; kt++) {
        if (kt + 1 < 16) {
            prefetch_kv(kt + 1, (kt + 1) & 1);
            CP_COMMIT();
            CP_WAIT1();
        } else {
            CP_WAIT0();
        }
        __syncthreads();

        const uint32_t sb = sbase + (kt & 1) * FSTAGE_B;
        const uint32_t uKh = sb, uKl = sb + FTILE_B;
        const uint32_t uVh = sb + 2 * FTILE_B, uVl = sb + 3 * FTILE_B;

        float s[8][4];
#pragma unroll
        for (int nt = 0; nt < 8; nt++)
#pragma unroll
            for (int i = 0; i < 4; i++) s[nt][i] = 0.0f;

#pragma unroll
        for (int ks = 0; ks < 4; ks++) {
            const int kb = ks * 32;
#pragma unroll
            for (int np = 0; np < 4; np++) {
                uint32_t kh[4], kl[4];
                ldsm4(kh, uKh + kboff + np * 16 * (FPITCH * 2) + kb);
                ldsm4(kl, uKl + kboff + np * 16 * (FPITCH * 2) + kb);
                mma16816(s[2 * np],     qH[ks], kh);
                mma16816(s[2 * np],     qH[ks], kl);
                mma16816(s[2 * np],     qL[ks], kh);
                mma16816(s[2 * np + 1], qH[ks], kh + 2);
                mma16816(s[2 * np + 1], qH[ks], kl + 2);
                mma16816(s[2 * np + 1], qL[ks], kh + 2);
            }
        }

#pragma unroll
        for (int r = 0; r < 2; r++) {
            float mx = -1e30f;
#pragma unroll
            for (int nt = 0; nt < 8; nt++) {
                s[nt][2 * r]     *= 0.125f;
                s[nt][2 * r + 1] *= 0.125f;
                mx = fmaxf(mx, fmaxf(s[nt][2 * r], s[nt][2 * r + 1]));
            }
            mx = fmaxf(mx, __shfl_xor_sync(0xffffffffu, mx, 1));
            mx = fmaxf(mx, __shfl_xor_sync(0xffffffffu, mx, 2));
            float mnew = fmaxf(mrow[r], mx);
            float alpha = __expf(mrow[r] - mnew);
            float ls = 0.0f;
#pragma unroll
            for (int nt = 0; nt < 8; nt++) {
                float p0 = __expf(s[nt][2 * r] - mnew);
                float p1 = __expf(s[nt][2 * r + 1] - mnew);
                s[nt][2 * r] = p0; s[nt][2 * r + 1] = p1;
                ls += p0 + p1;
            }
            ls += __shfl_xor_sync(0xffffffffu, ls, 1);
            ls += __shfl_xor_sync(0xffffffffu, ls, 2);
            lrow[r] = lrow[r] * alpha + ls;
            mrow[r] = mnew;
#pragma unroll
            for (int nt = 0; nt < 8; nt++) {
                o[nt][2 * r] *= alpha; o[nt][2 * r + 1] *= alpha;
            }
        }

        uint32_t pH[4][4], pL[4][4];
#pragma unroll
        for (int j = 0; j < 4; j++) {
            pH[j][0] = pack_hi(s[2 * j][0], s[2 * j][1]);
            pH[j][1] = pack_hi(s[2 * j][2], s[2 * j][3]);
            pH[j][2] = pack_hi(s[2 * j + 1][0], s[2 * j + 1][1]);
            pH[j][3] = pack_hi(s[2 * j + 1][2], s[2 * j + 1][3]);
            pL[j][0] = pack_lo(s[2 * j][0], s[2 * j][1]);
            pL[j][1] = pack_lo(s[2 * j][2], s[2 * j][3]);
            pL[j][2] = pack_lo(s[2 * j + 1][0], s[2 * j + 1][1]);
            pL[j][3] = pack_lo(s[2 * j + 1][2], s[2 * j + 1][3]);
        }

#pragma unroll
        for (int j = 0; j < 4; j++) {
            const int rb = j * 16 * (FPITCH * 2);
#pragma unroll
            for (int np = 0; np < 4; np++) {
                uint32_t vh[4], vl[4];
                ldsm4t(vh, uVh + vboff + rb + np * 32);
                ldsm4t(vl, uVl + vboff + rb + np * 32);
                mma16816(o[2 * np],     pH[j], vh);
                mma16816(o[2 * np],     pH[j], vl);
                mma16816(o[2 * np],     pL[j], vh);
                mma16816(o[2 * np + 1], pH[j], vh + 2);
                mma16816(o[2 * np + 1], pH[j], vl + 2);
                mma16816(o[2 * np + 1], pL[j], vh + 2);
            }
        }
        __syncthreads();   // all warps done reading this stage before next prefetch overwrites it
    }

    const float inv0 = 1.0f / lrow[0], inv1 = 1.0f / lrow[1];
    const size_t orow0 = (size_t)(b * SS + q0 + warp * 16 + g) * OP + 2 * DD + h * HD;
    const size_t orow1 = orow0 + (size_t)8 * OP;
#pragma unroll
    for (int nt = 0; nt < 8; nt++) {
        const int c = nt * 8 + 2 * t;
        const float a0 = o[nt][0] * inv0, a1 = o[nt][1] * inv0;
        const float b0 = o[nt][2] * inv1, b1 = o[nt][3] * inv1;
        *(uint32_t*)(atth + orow0 + c) = pack_hi(a0, a1);
        *(uint32_t*)(attl + orow0 + c) = pack_lo(a0, a1);
        *(uint32_t*)(atth + orow1 + c) = pack_hi(b0, b1);
        *(uint32_t*)(attl + orow1 + c) = pack_lo(b0, b1);
    }
}

// ---------------------------------------------------------------------------
// Windowed causal attention, fully coalesced: Q and output staged via smem.
// Dynamic smem: Qs/Os 64x65 f32, Ks/Vs 80x65 f32. blockIdx.z = branch.
// ---------------------------------------------------------------------------
#define WQS 0
#define WKS (64 * 65)
#define WVS (WKS + 80 * 65)
#define WIN_SMEM ((WVS + 80 * 65) * 4)   // 58240 bytes

template <int W>
__device__ __forceinline__ void window_body(
    const __nv_bfloat16* __restrict__ qh, const __nv_bfloat16* __restrict__ ql,
    __nv_bfloat16* __restrict__ atth, __nv_bfloat16* __restrict__ attl,
    float* wsm, int br)
{
    float* Qs = wsm + WQS;    // reused as output buffer after qreg extraction
    float* Ks = wsm + WKS;
    float* Vs = wsm + WVS;

    const int tid = threadIdx.x;
    const int q0 = blockIdx.x * 64;
    const int bh = blockIdx.y;
    const int b = bh >> 3, h = bh & 7;
    const size_t base = (size_t)b * SS * QP + (size_t)br * D3 + h * HD;

    // Stage Q rows q0..q0+63 (coalesced uint4 hi+lo -> fp32)
    for (int e8 = tid; e8 < 64 * 8; e8 += 128) {
        int r = e8 >> 3, c8 = e8 & 7;
        size_t src = base + (size_t)(q0 + r) * QP + c8 * 8;
        uint4 xh4 = *(const uint4*)(qh + src);
        uint4 xl4 = *(const uint4*)(ql + src);
        float* qd = Qs + r * 65 + c8 * 8;
        float2 f;
        f = bf2sum(xh4.x, xl4.x); qd[0] = f.x; qd[1] = f.y;
        f = bf2sum(xh4.y, xl4.y); qd[2] = f.x; qd[3] = f.y;
        f = bf2sum(xh4.z, xl4.z); qd[4] = f.x; qd[5] = f.y;
        f = bf2sum(xh4.w, xl4.w); qd[6] = f.x; qd[7] = f.y;
    }
    // Stage K/V rows q0-16+r, r=0..79
    for (int e8 = tid; e8 < 80 * 8; e8 += 128) {
        int r = e8 >> 3, c8 = e8 & 7;
        int s = q0 - 16 + r;
        if (s >= 0) {
            size_t src = base + (size_t)s * QP + c8 * 8;
            uint4 kh = *(const uint4*)(qh + src + 512);
            uint4 kl = *(const uint4*)(ql + src + 512);
            uint4 vh = *(const uint4*)(qh + src + 1024);
            uint4 vl = *(const uint4*)(ql + src + 1024);
            float* kd = Ks + r * 65 + c8 * 8;
            float* vd = Vs + r * 65 + c8 * 8;
            float2 f;
            f = bf2sum(kh.x, kl.x); kd[0] = f.x; kd[1] = f.y;
            f = bf2sum(kh.y, kl.y); kd[2] = f.x; kd[3] = f.y;
            f = bf2sum(kh.z, kl.z); kd[4] = f.x; kd[5] = f.y;
            f = bf2sum(kh.w, kl.w); kd[6] = f.x; kd[7] = f.y;
            f = bf2sum(vh.x, vl.x); vd[0] = f.x; vd[1] = f.y;
            f = bf2sum(vh.y, vl.y); vd[2] = f.x; vd[3] = f.y;
            f = bf2sum(vh.z, vl.z); vd[4] = f.x; vd[5] = f.y;
            f = bf2sum(vh.w, vl.w); vd[6] = f.x; vd[7] = f.y;
        }
    }
    __syncthreads();

    const int qlid = tid >> 1;
    const int half = tid & 1;
    const int q = q0 + qlid;

    float qreg[32];
#pragma unroll
    for (int dd = 0; dd < 32; dd++)
        qreg[dd] = Qs[qlid * 65 + 2 * dd + half] * 0.125f;
    __syncthreads();   // all Qs reads done before Qs is reused as output

    float sc[W];
    float m = -1e30f;
#pragma unroll
    for (int w = 0; w < W; w++) {
        int k = q - w;
        int kr = qlid + 16 - w;
        float dot = 0.0f;
        if (k >= 0) {
#pragma unroll
            for (int dd = 0; dd < 32; dd++)
                dot += qreg[dd] * Ks[kr * 65 + 2 * dd + half];
        }
        dot += __shfl_xor_sync(0xffffffffu, dot, 1);
        sc[w] = (k >= 0) ? dot : -1e30f;
        m = fmaxf(m, sc[w]);
    }

    float l = 0.0f;
    float p[W];
#pragma unroll
    for (int w = 0; w < W; w++) {
        p[w] = (q - w >= 0) ? __expf(sc[w] - m) : 0.0f;
        l += p[w];
    }

    float o[32];
#pragma unroll
    for (int dd = 0; dd < 32; dd++) o[dd] = 0.0f;
#pragma unroll
    for (int w = 0; w < W; w++) {
        int k = q - w;
        if (k >= 0) {
            int kr = qlid + 16 - w;
#pragma unroll
            for (int dd = 0; dd < 32; dd++)
                o[dd] += p[w] * Vs[kr * 65 + 2 * dd + half];
        }
    }

    // Write scaled output into Qs, then store coalesced
    float inv = 1.0f / l;
#pragma unroll
    for (int dd = 0; dd < 32; dd++)
        Qs[qlid * 65 + 2 * dd + half] = o[dd] * inv;
    __syncthreads();

    const size_t obase = (size_t)(b * SS + q0) * OP + (size_t)br * DD + h * HD;
    for (int e8 = tid; e8 < 64 * 8; e8 += 128) {
        int r = e8 >> 3, c8 = e8 & 7;
        const float* row = Qs + r * 65 + c8 * 8;
        uint4 hv, lv;
        hv.x = pack_hi(row[0], row[1]); lv.x = pack_lo(row[0], row[1]);
        hv.y = pack_hi(row[2], row[3]); lv.y = pack_lo(row[2], row[3]);
        hv.z = pack_hi(row[4], row[5]); lv.z = pack_lo(row[4], row[5]);
        hv.w = pack_hi(row[6], row[7]); lv.w = pack_lo(row[6], row[7]);
        size_t drow = obase + (size_t)r * OP + c8 * 8;
        *(uint4*)(atth + drow) = hv;
        *(uint4*)(attl + drow) = lv;
    }
}

__global__ __launch_bounds__(128) void window_attn_kernel(
    const __nv_bfloat16* __restrict__ qh, const __nv_bfloat16* __restrict__ ql,
    __nv_bfloat16* __restrict__ atth, __nv_bfloat16* __restrict__ attl)
{
    extern __shared__ float wsm[];
    if (blockIdx.z == 0)
        window_body<5>(qh, ql, atth, attl, wsm, 0);
    else
        window_body<10>(qh, ql, atth, attl, wsm, 1);
}

// ---------------------------------------------------------------------------
// Launch
// ---------------------------------------------------------------------------
extern "C" void kernel_launch(void* const* d_in, const int* in_sizes, int n_in,
                              void* d_out, int out_size)
{
    const float* x    = (const float*)d_in[0];   // [16,1024,512]
    const float* Wqkv = (const float*)d_in[1];   // [3,1536,512] = [4608,512]
    const float* bqkv = (const float*)d_in[2];   // [4608]
    const float* Wo   = (const float*)d_in[3];   // [3,512,512]
    const float* bo   = (const float*)d_in[4];   // [3,512]
    const float* Wf   = (const float*)d_in[5];   // [512,1536]
    const float* bf   = (const float*)d_in[6];   // [512]
    float* out = (float*)d_out;

    __nv_bfloat16 *xh, *xl, *qkvh, *qkvl, *atth, *attl, *combh, *combl;
    __nv_bfloat16 *Wqkvh, *Wqkvl, *Woh, *Wol, *Wfh, *Wfl;
    cudaGetSymbolAddress((void**)&xh, g_xh);
    cudaGetSymbolAddress((void**)&xl, g_xl);
    cudaGetSymbolAddress((void**)&qkvh, g_qkvh);
    cudaGetSymbolAddress((void**)&qkvl, g_qkvl);
    cudaGetSymbolAddress((void**)&atth, g_atth);
    cudaGetSymbolAddress((void**)&attl, g_attl);
    cudaGetSymbolAddress((void**)&combh, g_combh);
    cudaGetSymbolAddress((void**)&combl, g_combl);
    cudaGetSymbolAddress((void**)&Wqkvh, g_Wqkvh);
    cudaGetSymbolAddress((void**)&Wqkvl, g_Wqkvl);
    cudaGetSymbolAddress((void**)&Woh, g_Woh);
    cudaGetSymbolAddress((void**)&Wol, g_Wol);
    cudaGetSymbolAddress((void**)&Wfh, g_Wfh);
    cudaGetSymbolAddress((void**)&Wfl, g_Wfl);

    cudaFuncSetAttribute(gemm_bf16_kernel,
                         cudaFuncAttributeMaxDynamicSharedMemorySize, GEMM_SMEM);
    cudaFuncSetAttribute(flash_hmma_kernel,
                         cudaFuncAttributeMaxDynamicSharedMemorySize, FLASH_SMEM);
    cudaFuncSetAttribute(window_attn_kernel,
                         cudaFuncAttributeMaxDynamicSharedMemorySize, WIN_SMEM);

    // Conversions
    {
        int n4;
        n4 = MM * DD / 4;
        convert_hilo_kernel<<<(n4 + 255) / 256, 256>>>(x, xh, xl, n4);
        n4 = 3 * D3 * DD / 4;
        convert_hilo_kernel<<<(n4 + 255) / 256, 256>>>(Wqkv, Wqkvh, Wqkvl, n4);
        n4 = 3 * DD * DD / 4;
        convert_hilo_kernel<<<(n4 + 255) / 256, 256>>>(Wo, Woh, Wol, n4);
        n4 = DD * D3 / 4;
        convert_hilo_kernel<<<(n4 + 255) / 256, 256>>>(Wf, Wfh, Wfl, n4);
    }

    // 1) All three QKV projections as one GEMM
    {
        dim3 grid(QP / 256, MM / 128, 1);
        gemm_bf16_kernel<<<grid, 256, GEMM_SMEM>>>(
            xh, xl, Wqkvh, Wqkvl, bqkv, nullptr, qkvh, qkvl,
            DD, DD, QP, 0, 0, 0, 0, 0);
    }

    // 2) Attention: both windows (one launch) + flash
    {
        dim3 wgrid(SS / 64, BB * HH, 2);
        window_attn_kernel<<<wgrid, 128, WIN_SMEM>>>(qkvh, qkvl, atth, attl);
        dim3 fgrid(SS / 64, BB * HH, 1);
        flash_hmma_kernel<<<fgrid, 128, FLASH_SMEM>>>(qkvh, qkvl, atth, attl);
    }

    // 3) Batched out-projections
    {
        dim3 grid(DD / 256, MM / 128, 3);
        gemm_bf16_kernel<<<grid, 256, GEMM_SMEM>>>(
            atth, attl, Woh, Wol, bo, nullptr, combh, combl,
            DD, OP, OP, 0, DD, DD * DD, DD, DD);
    }

    // 4) Final projection (fp32 out)
    {
        dim3 grid(DD / 256, MM / 128, 1);
        gemm_bf16_kernel<<<grid, 256, GEMM_SMEM>>>(
            combh, combl, Wfh, Wfl, bf, out, nullptr, nullptr,
            D3, D3, DD, 0, 0, 0, 0, 0);
    }
}

// round 11
// speedup vs baseline: 4.0086x; 1.0047x over previous
#include <cuda_runtime.h>
#include <cuda_bf16.h>
#include <cstdint>
#include <math.h>

// Problem constants
#define BB 16
#define SS 1024
#define DD 512
#define HH 8
#define HD 64
#define MM (BB * SS)          // 16384 rows
#define D3 (3 * DD)           // 1536
#define QP (3 * D3)           // 4608 packed qkv width (3 branches)
#define OP D3                 // 1536 att/comb width

// ---------------------------------------------------------------------------
// Scratch (static device globals; no runtime allocation allowed)
// ---------------------------------------------------------------------------
__device__ __nv_bfloat16 g_xh[(size_t)MM * DD],   g_xl[(size_t)MM * DD];
__device__ __nv_bfloat16 g_qkvh[(size_t)MM * QP], g_qkvl[(size_t)MM * QP];
__device__ __nv_bfloat16 g_atth[(size_t)MM * OP], g_attl[(size_t)MM * OP];
__device__ __nv_bfloat16 g_combh[(size_t)MM * OP], g_combl[(size_t)MM * OP];
__device__ __nv_bfloat16 g_Wqkvh[(size_t)3 * D3 * DD], g_Wqkvl[(size_t)3 * D3 * DD];
__device__ __nv_bfloat16 g_Woh[(size_t)3 * DD * DD],   g_Wol[(size_t)3 * DD * DD];
__device__ __nv_bfloat16 g_Wfh[(size_t)DD * D3],   g_Wfl[(size_t)DD * D3];

// ---------------------------------------------------------------------------
// Helpers (base sm_80+ PTX only — NO 'a'-suffix features)
// ---------------------------------------------------------------------------
__device__ __forceinline__ uint32_t smem_u32(const void* p) {
    uint32_t a;
    asm("{ .reg .u64 t; cvta.to.shared.u64 t, %1; cvt.u32.u64 %0, t; }" : "=r"(a) : "l"(p));
    return a;
}
__device__ __forceinline__ void ldsm4(uint32_t* r, uint32_t addr) {
    asm volatile("ldmatrix.sync.aligned.m8n8.x4.shared.b16 {%0,%1,%2,%3}, [%4];"
                 : "=r"(r[0]), "=r"(r[1]), "=r"(r[2]), "=r"(r[3]) : "r"(addr));
}
__device__ __forceinline__ void ldsm4t(uint32_t* r, uint32_t addr) {
    asm volatile("ldmatrix.sync.aligned.m8n8.x4.trans.shared.b16 {%0,%1,%2,%3}, [%4];"
                 : "=r"(r[0]), "=r"(r[1]), "=r"(r[2]), "=r"(r[3]) : "r"(addr));
}
__device__ __forceinline__ void mma16816(float* c, const uint32_t* a, const uint32_t* b) {
    asm volatile("mma.sync.aligned.m16n8k16.row.col.f32.bf16.bf16.f32 "
                 "{%0,%1,%2,%3}, {%4,%5,%6,%7}, {%8,%9}, {%0,%1,%2,%3};"
                 : "+f"(c[0]), "+f"(c[1]), "+f"(c[2]), "+f"(c[3])
                 : "r"(a[0]), "r"(a[1]), "r"(a[2]), "r"(a[3]), "r"(b[0]), "r"(b[1]));
}
__device__ __forceinline__ void cp16(uint32_t saddr, const void* g) {
    asm volatile("cp.async.cg.shared.global [%0], [%1], 16;" :: "r"(saddr), "l"(g));
}
#define CP_COMMIT() asm volatile("cp.async.commit_group;" ::: "memory")
#define CP_WAIT1()  asm volatile("cp.async.wait_group 1;" ::: "memory")
#define CP_WAIT0()  asm volatile("cp.async.wait_group 0;" ::: "memory")

__device__ __forceinline__ uint32_t pack_hi(float x, float y) {
    uint16_t a = __bfloat16_as_ushort(__float2bfloat16_rn(x));
    uint16_t b = __bfloat16_as_ushort(__float2bfloat16_rn(y));
    return (uint32_t)a | ((uint32_t)b << 16);
}
__device__ __forceinline__ uint32_t pack_lo(float x, float y) {
    float xh = __bfloat162float(__float2bfloat16_rn(x));
    float yh = __bfloat162float(__float2bfloat16_rn(y));
    uint16_t a = __bfloat16_as_ushort(__float2bfloat16_rn(x - xh));
    uint16_t b = __bfloat16_as_ushort(__float2bfloat16_rn(y - yh));
    return (uint32_t)a | ((uint32_t)b << 16);
}
__device__ __forceinline__ float2 bf2sum(uint32_t h, uint32_t l) {
    __nv_bfloat162 hb = *reinterpret_cast<__nv_bfloat162*>(&h);
    __nv_bfloat162 lb = *reinterpret_cast<__nv_bfloat162*>(&l);
    float2 hf = __bfloat1622float2(hb), lf = __bfloat1622float2(lb);
    return make_float2(hf.x + lf.x, hf.y + lf.y);
}

// ---------------------------------------------------------------------------
// fp32 -> bf16 hi/lo conversion
// ---------------------------------------------------------------------------
__global__ __launch_bounds__(256) void convert_hilo_kernel(
    const float* __restrict__ src, __nv_bfloat16* __restrict__ h,
    __nv_bfloat16* __restrict__ l, int n4)
{
    int i = blockIdx.x * blockDim.x + threadIdx.x;
    if (i < n4) {
        float4 v = *(const float4*)(src + (size_t)i * 4);
        uint2 ph, pl;
        ph.x = pack_hi(v.x, v.y); ph.y = pack_hi(v.z, v.w);
        pl.x = pack_lo(v.x, v.y); pl.y = pack_lo(v.z, v.w);
        *(uint2*)(h + (size_t)i * 4) = ph;
        *(uint2*)(l + (size_t)i * 4) = pl;
    }
}

// ---------------------------------------------------------------------------
// HMMA GEMM, bf16 hi/lo 3-term split, batched over blockIdx.z.
// Block tile 128x256, KC=32, 8 warps = 2(m) x 4(n), warp tile 64x64.
// 3-stage cp.async pipeline. TERM-MAJOR MMA ordering: per k16 step all
// fragments are hoisted, then three passes (hi*hi, hi*lo, lo*hi) each issue
// 32 MMAs to distinct accumulators -> accumulator reuse distance 32.
// ---------------------------------------------------------------------------
#define KC 32
#define PITCH 40                         // bf16 per smem row (80 B)
#define A_EL (128 * PITCH)               // 5120 elements per A tile
#define W_EL (256 * PITCH)               // 10240 elements per W tile
#define OFF_AL (A_EL * 2)                // byte offsets inside a stage
#define OFF_WH (A_EL * 4)
#define OFF_WL (A_EL * 4 + W_EL * 2)
#define STAGE_B ((A_EL * 2 + W_EL * 2) * 2)   // 61440 bytes per stage
#define GEMM_SMEM (3 * STAGE_B)               // 184320 bytes (3 stages)

__global__ __launch_bounds__(256, 1) void gemm_bf16_kernel(
    const __nv_bfloat16* __restrict__ Ah, const __nv_bfloat16* __restrict__ Al,
    const __nv_bfloat16* __restrict__ Wh, const __nv_bfloat16* __restrict__ Wl,
    const float* __restrict__ bias, float* __restrict__ C,
    __nv_bfloat16* __restrict__ Ch, __nv_bfloat16* __restrict__ Cl,
    int K, int lda, int ldc, int col0,
    int aColZ, int wZ, int biasZ, int cColZ)
{
    extern __shared__ __nv_bfloat16 smem[];
    const uint32_t sbase = smem_u32(smem);

    const int tid = threadIdx.x;
    const int wid = tid >> 5, lane = tid & 31;
    const int z = blockIdx.z;
    const int m0 = blockIdx.y * 128;
    const int n0 = blockIdx.x * 256;
    const int warp_m = (wid & 1) * 64;
    const int warp_n = (wid >> 1) * 64;

    const __nv_bfloat16* Abh = Ah + (size_t)m0 * lda + (size_t)z * aColZ;
    const __nv_bfloat16* Abl = Al + (size_t)m0 * lda + (size_t)z * aColZ;
    const __nv_bfloat16* Wbh = Wh + (size_t)z * wZ + (size_t)n0 * K;
    const __nv_bfloat16* Wbl = Wl + (size_t)z * wZ + (size_t)n0 * K;
    const float* biasz = bias + (size_t)z * biasZ;
    const int ccol0 = col0 + z * cColZ;

    const int aoff = (warp_m + (lane & 15)) * (PITCH * 2) + (((lane >> 4) << 3) << 1);
    const int bm = lane >> 3;
    const int boff = (warp_n + (lane & 7) + ((bm >> 1) << 3)) * (PITCH * 2) + (((bm & 1) << 3) << 1);

    float acc[4][8][4];
#pragma unroll
    for (int mt = 0; mt < 4; mt++)
#pragma unroll
        for (int nt = 0; nt < 8; nt++)
#pragma unroll
            for (int i = 0; i < 4; i++) acc[mt][nt][i] = 0.0f;

    const int nchunks = K / KC;

    auto prefetch = [&](int kt, int stg) {
        const int k0 = kt * KC;
        const uint32_t sb = sbase + stg * STAGE_B;
#pragma unroll
        for (int j = 0; j < 2; j++) {        // A: 128 rows x 4 x 16B per array
            int idx = tid + j * 256;
            int row = idx >> 2, c = idx & 3;
            uint32_t so = (uint32_t)(row * (PITCH * 2) + c * 16);
            size_t go = (size_t)row * lda + k0 + c * 8;
            cp16(sb + so,          Abh + go);
            cp16(sb + OFF_AL + so, Abl + go);
        }
#pragma unroll
        for (int j = 0; j < 4; j++) {        // W: 256 rows x 4 x 16B per array
            int idx = tid + j * 256;
            int row = idx >> 2, c = idx & 3;
            uint32_t so = (uint32_t)(row * (PITCH * 2) + c * 16);
            size_t go = (size_t)row * K + k0 + c * 8;
            cp16(sb + OFF_WH + so, Wbh + go);
            cp16(sb + OFF_WL + so, Wbl + go);
        }
    };

    prefetch(0, 0);
    CP_COMMIT();
    prefetch(1, 1);
    CP_COMMIT();

    int stg = 0;
    for (int kt = 0; kt < nchunks; kt++) {
        if (kt + 1 < nchunks) { CP_WAIT1(); } else { CP_WAIT0(); }
        __syncthreads();   // all warps past compute of kt-1; stage (kt+2)%3 free

        if (kt + 2 < nchunks) {
            int ns = stg + 2; if (ns >= 3) ns -= 3;
            prefetch(kt + 2, ns);
            CP_COMMIT();
        }

        const uint32_t sb = sbase + stg * STAGE_B;
        const uint32_t uAh = sb, uAl = sb + OFF_AL;
        const uint32_t uWh = sb + OFF_WH, uWl = sb + OFF_WL;

#pragma unroll
        for (int ks = 0; ks < 2; ks++) {
            const int kb = ks * 32;

            // Hoist ALL fragments for this k16 step (16 LDSM)
            uint32_t aH[4][4], aL[4][4], bH[4][4], bL[4][4];
#pragma unroll
            for (int mt = 0; mt < 4; mt++) {
                ldsm4(aH[mt], uAh + aoff + mt * 16 * (PITCH * 2) + kb);
                ldsm4(aL[mt], uAl + aoff + mt * 16 * (PITCH * 2) + kb);
            }
#pragma unroll
            for (int np = 0; np < 4; np++) {
                ldsm4(bH[np], uWh + boff + np * 16 * (PITCH * 2) + kb);
                ldsm4(bL[np], uWl + boff + np * 16 * (PITCH * 2) + kb);
            }

            // Pass 1: hi*hi — 32 MMAs, all distinct accumulators
#pragma unroll
            for (int mt = 0; mt < 4; mt++)
#pragma unroll
                for (int np = 0; np < 4; np++) {
                    mma16816(acc[mt][2 * np],     aH[mt], bH[np]);
                    mma16816(acc[mt][2 * np + 1], aH[mt], bH[np] + 2);
                }
            // Pass 2: hi*lo
#pragma unroll
            for (int mt = 0; mt < 4; mt++)
#pragma unroll
                for (int np = 0; np < 4; np++) {
                    mma16816(acc[mt][2 * np],     aH[mt], bL[np]);
                    mma16816(acc[mt][2 * np + 1], aH[mt], bL[np] + 2);
                }
            // Pass 3: lo*hi
#pragma unroll
            for (int mt = 0; mt < 4; mt++)
#pragma unroll
                for (int np = 0; np < 4; np++) {
                    mma16816(acc[mt][2 * np],     aL[mt], bH[np]);
                    mma16816(acc[mt][2 * np + 1], aL[mt], bH[np] + 2);
                }
        }
        if (++stg >= 3) stg = 0;
    }

    // Epilogue
    const int g = lane >> 2, tg = lane & 3;
#pragma unroll
    for (int nt = 0; nt < 8; nt++) {
        const int ncol = warp_n + nt * 8 + tg * 2;
        const float b0 = biasz[n0 + ncol], b1 = biasz[n0 + ncol + 1];
#pragma unroll
        for (int mt = 0; mt < 4; mt++) {
            const int r0 = m0 + warp_m + mt * 16 + g;
#pragma unroll
            for (int hh = 0; hh < 2; hh++) {
                const int r = r0 + hh * 8;
                const float v0 = acc[mt][nt][2 * hh] + b0;
                const float v1 = acc[mt][nt][2 * hh + 1] + b1;
                const size_t idx = (size_t)r * ldc + ccol0 + n0 + ncol;
                if (C) {
                    float2 o; o.x = v0; o.y = v1;
                    *(float2*)(C + idx) = o;
                } else {
                    *(uint32_t*)(Ch + idx) = pack_hi(v0, v1);
                    *(uint32_t*)(Cl + idx) = pack_lo(v0, v1);
                }
            }
        }
    }
}

// ---------------------------------------------------------------------------
// HMMA flash attention (branch 2 of packed qkv). Grid (S/64, B*H), block 128.
// 2-stage cp.async K/V staging. Term-major MMA ordering in QK^T and PV.
// ---------------------------------------------------------------------------
#define FPITCH 72
#define FTILE_B (64 * FPITCH * 2)         // 9216 bytes per tile
#define FSTAGE_B (4 * FTILE_B)            // 36864 bytes per stage (Kh,Kl,Vh,Vl)
#define FLASH_SMEM (2 * FSTAGE_B)         // 73728 bytes

__global__ __launch_bounds__(128) void flash_hmma_kernel(
    const __nv_bfloat16* __restrict__ qh, const __nv_bfloat16* __restrict__ ql,
    __nv_bfloat16* __restrict__ atth, __nv_bfloat16* __restrict__ attl)
{
    extern __shared__ __nv_bfloat16 fsm[];
    const uint32_t sbase = smem_u32(fsm);

    const int tid = threadIdx.x;
    const int warp = tid >> 5, lane = tid & 31;
    const int g = lane >> 2, t = lane & 3;
    const int q0 = blockIdx.x * 64;
    const int b = blockIdx.y >> 3, h = blockIdx.y & 7;

    const size_t rowQ0 = (size_t)(b * SS + q0 + warp * 16 + g) * QP + 2 * D3 + h * HD;
    const size_t rowQ1 = rowQ0 + (size_t)8 * QP;
    uint32_t qH[4][4], qL[4][4];
#pragma unroll
    for (int ks = 0; ks < 4; ks++) {
        const int c = ks * 16 + 2 * t;
        qH[ks][0] = *(const uint32_t*)(qh + rowQ0 + c);
        qH[ks][1] = *(const uint32_t*)(qh + rowQ1 + c);
        qH[ks][2] = *(const uint32_t*)(qh + rowQ0 + c + 8);
        qH[ks][3] = *(const uint32_t*)(qh + rowQ1 + c + 8);
        qL[ks][0] = *(const uint32_t*)(ql + rowQ0 + c);
        qL[ks][1] = *(const uint32_t*)(ql + rowQ1 + c);
        qL[ks][2] = *(const uint32_t*)(ql + rowQ0 + c + 8);
        qL[ks][3] = *(const uint32_t*)(ql + rowQ1 + c + 8);
    }

    const int bm = lane >> 3;
    const int kboff = ((lane & 7) + ((bm >> 1) << 3)) * (FPITCH * 2) + ((bm & 1) << 3) * 2;
    const int vboff = ((lane & 7) + ((bm & 1) << 3)) * (FPITCH * 2) + (lane >> 4) * 16;

    float o[8][4];
    float mrow[2], lrow[2];
#pragma unroll
    for (int nt = 0; nt < 8; nt++)
#pragma unroll
        for (int i = 0; i < 4; i++) o[nt][i] = 0.0f;
    mrow[0] = mrow[1] = -1e30f;
    lrow[0] = lrow[1] = 0.0f;

    const size_t kvbase = (size_t)(b * SS) * QP + 2 * D3 + h * HD;

    auto prefetch_kv = [&](int kt, int stg) {
        const size_t tb = kvbase + (size_t)(kt * 64) * QP;
        const uint32_t sb = sbase + stg * FSTAGE_B;
#pragma unroll
        for (int l = 0; l < 4; l++) {
            int idx = tid + l * 128;
            int r = idx >> 3, c4 = idx & 7;
            size_t gsrc = tb + (size_t)r * QP + c4 * 8;
            uint32_t sdst = (uint32_t)(r * (FPITCH * 2) + c4 * 16);
            cp16(sb + sdst,               qh + gsrc + 512);
            cp16(sb + FTILE_B + sdst,     ql + gsrc + 512);
            cp16(sb + 2 * FTILE_B + sdst, qh + gsrc + 1024);
            cp16(sb + 3 * FTILE_B + sdst, ql + gsrc + 1024);
        }
    };

    prefetch_kv(0, 0);
    CP_COMMIT();

    for (int kt = 0; kt < 16; kt++) {
        if (kt + 1 < 16) {
            prefetch_kv(kt + 1, (kt + 1) & 1);
            CP_COMMIT();
            CP_WAIT1();
        } else {
            CP_WAIT0();
        }
        __syncthreads();

        const uint32_t sb = sbase + (kt & 1) * FSTAGE_B;
        const uint32_t uKh = sb, uKl = sb + FTILE_B;
        const uint32_t uVh = sb + 2 * FTILE_B, uVl = sb + 3 * FTILE_B;

        float s[8][4];
#pragma unroll
        for (int nt = 0; nt < 8; nt++)
#pragma unroll
            for (int i = 0; i < 4; i++) s[nt][i] = 0.0f;

#pragma unroll
        for (int ks = 0; ks < 4; ks++) {
            const int kb = ks * 32;
            uint32_t kh[4][4], kl[4][4];
#pragma unroll
            for (int np = 0; np < 4; np++) {
                ldsm4(kh[np], uKh + kboff + np * 16 * (FPITCH * 2) + kb);
                ldsm4(kl[np], uKl + kboff + np * 16 * (FPITCH * 2) + kb);
            }
            // term-major passes: 8 distinct accumulators per pass
#pragma unroll
            for (int np = 0; np < 4; np++) {
                mma16816(s[2 * np],     qH[ks], kh[np]);
                mma16816(s[2 * np + 1], qH[ks], kh[np] + 2);
            }
#pragma unroll
            for (int np = 0; np < 4; np++) {
                mma16816(s[2 * np],     qH[ks], kl[np]);
                mma16816(s[2 * np + 1], qH[ks], kl[np] + 2);
            }
#pragma unroll
            for (int np = 0; np < 4; np++) {
                mma16816(s[2 * np],     qL[ks], kh[np]);
                mma16816(s[2 * np + 1], qL[ks], kh[np] + 2);
            }
        }

#pragma unroll
        for (int r = 0; r < 2; r++) {
            float mx = -1e30f;
#pragma unroll
            for (int nt = 0; nt < 8; nt++) {
                s[nt][2 * r]     *= 0.125f;
                s[nt][2 * r + 1] *= 0.125f;
                mx = fmaxf(mx, fmaxf(s[nt][2 * r], s[nt][2 * r + 1]));
            }
            mx = fmaxf(mx, __shfl_xor_sync(0xffffffffu, mx, 1));
            mx = fmaxf(mx, __shfl_xor_sync(0xffffffffu, mx, 2));
            float mnew = fmaxf(mrow[r], mx);
            float alpha = __expf(mrow[r] - mnew);
            float ls = 0.0f;
#pragma unroll
            for (int nt = 0; nt < 8; nt++) {
                float p0 = __expf(s[nt][2 * r] - mnew);
                float p1 = __expf(s[nt][2 * r + 1] - mnew);
                s[nt][2 * r] = p0; s[nt][2 * r + 1] = p1;
                ls += p0 + p1;
            }
            ls += __shfl_xor_sync(0xffffffffu, ls, 1);
            ls += __shfl_xor_sync(0xffffffffu, ls, 2);
            lrow[r] = lrow[r] * alpha + ls;
            mrow[r] = mnew;
#pragma unroll
            for (int nt = 0; nt < 8; nt++) {
                o[nt][2 * r] *= alpha; o[nt][2 * r + 1] *= alpha;
            }
        }

        uint32_t pH[4][4], pL[4][4];
#pragma unroll
        for (int j = 0; j < 4; j++) {
            pH[j][0] = pack_hi(s[2 * j][0], s[2 * j][1]);
            pH[j][1] = pack_hi(s[2 * j][2], s[2 * j][3]);
            pH[j][2] = pack_hi(s[2 * j + 1][0], s[2 * j + 1][1]);
            pH[j][3] = pack_hi(s[2 * j + 1][2], s[2 * j + 1][3]);
            pL[j][0] = pack_lo(s[2 * j][0], s[2 * j][1]);
            pL[j][1] = pack_lo(s[2 * j][2], s[2 * j][3]);
            pL[j][2] = pack_lo(s[2 * j + 1][0], s[2 * j + 1][1]);
            pL[j][3] = pack_lo(s[2 * j + 1][2], s[2 * j + 1][3]);
        }

#pragma unroll
        for (int j = 0; j < 4; j++) {
            const int rb = j * 16 * (FPITCH * 2);
            uint32_t vh[4][4], vl[4][4];
#pragma unroll
            for (int np = 0; np < 4; np++) {
                ldsm4t(vh[np], uVh + vboff + rb + np * 32);
                ldsm4t(vl[np], uVl + vboff + rb + np * 32);
            }
#pragma unroll
            for (int np = 0; np < 4; np++) {
                mma16816(o[2 * np],     pH[j], vh[np]);
                mma16816(o[2 * np + 1], pH[j], vh[np] + 2);
            }
#pragma unroll
            for (int np = 0; np < 4; np++) {
                mma16816(o[2 * np],     pH[j], vl[np]);
                mma16816(o[2 * np + 1], pH[j], vl[np] + 2);
            }
#pragma unroll
            for (int np = 0; np < 4; np++) {
                mma16816(o[2 * np],     pL[j], vh[np]);
                mma16816(o[2 * np + 1], pL[j], vh[np] + 2);
            }
        }
        __syncthreads();   // all warps done reading this stage before next prefetch overwrites it
    }

    const float inv0 = 1.0f / lrow[0], inv1 = 1.0f / lrow[1];
    const size_t orow0 = (size_t)(b * SS + q0 + warp * 16 + g) * OP + 2 * DD + h * HD;
    const size_t orow1 = orow0 + (size_t)8 * OP;
#pragma unroll
    for (int nt = 0; nt < 8; nt++) {
        const int c = nt * 8 + 2 * t;
        const float a0 = o[nt][0] * inv0, a1 = o[nt][1] * inv0;
        const float b0 = o[nt][2] * inv1, b1 = o[nt][3] * inv1;
        *(uint32_t*)(atth + orow0 + c) = pack_hi(a0, a1);
        *(uint32_t*)(attl + orow0 + c) = pack_lo(a0, a1);
        *(uint32_t*)(atth + orow1 + c) = pack_hi(b0, b1);
        *(uint32_t*)(attl + orow1 + c) = pack_lo(b0, b1);
    }
}

// ---------------------------------------------------------------------------
// Windowed causal attention, fully coalesced (unchanged from R10)
// ---------------------------------------------------------------------------
#define WQS 0
#define WKS (64 * 65)
#define WVS (WKS + 80 * 65)
#define WIN_SMEM ((WVS + 80 * 65) * 4)   // 58240 bytes

template <int W>
__device__ __forceinline__ void window_body(
    const __nv_bfloat16* __restrict__ qh, const __nv_bfloat16* __restrict__ ql,
    __nv_bfloat16* __restrict__ atth, __nv_bfloat16* __restrict__ attl,
    float* wsm, int br)
{
    float* Qs = wsm + WQS;
    float* Ks = wsm + WKS;
    float* Vs = wsm + WVS;

    const int tid = threadIdx.x;
    const int q0 = blockIdx.x * 64;
    const int bh = blockIdx.y;
    const int b = bh >> 3, h = bh & 7;
    const size_t base = (size_t)b * SS * QP + (size_t)br * D3 + h * HD;

    for (int e8 = tid; e8 < 64 * 8; e8 += 128) {
        int r = e8 >> 3, c8 = e8 & 7;
        size_t src = base + (size_t)(q0 + r) * QP + c8 * 8;
        uint4 xh4 = *(const uint4*)(qh + src);
        uint4 xl4 = *(const uint4*)(ql + src);
        float* qd = Qs + r * 65 + c8 * 8;
        float2 f;
        f = bf2sum(xh4.x, xl4.x); qd[0] = f.x; qd[1] = f.y;
        f = bf2sum(xh4.y, xl4.y); qd[2] = f.x; qd[3] = f.y;
        f = bf2sum(xh4.z, xl4.z); qd[4] = f.x; qd[5] = f.y;
        f = bf2sum(xh4.w, xl4.w); qd[6] = f.x; qd[7] = f.y;
    }
    for (int e8 = tid; e8 < 80 * 8; e8 += 128) {
        int r = e8 >> 3, c8 = e8 & 7;
        int s = q0 - 16 + r;
        if (s >= 0) {
            size_t src = base + (size_t)s * QP + c8 * 8;
            uint4 kh = *(const uint4*)(qh + src + 512);
            uint4 kl = *(const uint4*)(ql + src + 512);
            uint4 vh = *(const uint4*)(qh + src + 1024);
            uint4 vl = *(const uint4*)(ql + src + 1024);
            float* kd = Ks + r * 65 + c8 * 8;
            float* vd = Vs + r * 65 + c8 * 8;
            float2 f;
            f = bf2sum(kh.x, kl.x); kd[0] = f.x; kd[1] = f.y;
            f = bf2sum(kh.y, kl.y); kd[2] = f.x; kd[3] = f.y;
            f = bf2sum(kh.z, kl.z); kd[4] = f.x; kd[5] = f.y;
            f = bf2sum(kh.w, kl.w); kd[6] = f.x; kd[7] = f.y;
            f = bf2sum(vh.x, vl.x); vd[0] = f.x; vd[1] = f.y;
            f = bf2sum(vh.y, vl.y); vd[2] = f.x; vd[3] = f.y;
            f = bf2sum(vh.z, vl.z); vd[4] = f.x; vd[5] = f.y;
            f = bf2sum(vh.w, vl.w); vd[6] = f.x; vd[7] = f.y;
        }
    }
    __syncthreads();

    const int qlid = tid >> 1;
    const int half = tid & 1;
    const int q = q0 + qlid;

    float qreg[32];
#pragma unroll
    for (int dd = 0; dd < 32; dd++)
        qreg[dd] = Qs[qlid * 65 + 2 * dd + half] * 0.125f;
    __syncthreads();

    float sc[W];
    float m = -1e30f;
#pragma unroll
    for (int w = 0; w < W; w++) {
        int k = q - w;
        int kr = qlid + 16 - w;
        float dot = 0.0f;
        if (k >= 0) {
#pragma unroll
            for (int dd = 0; dd < 32; dd++)
                dot += qreg[dd] * Ks[kr * 65 + 2 * dd + half];
        }
        dot += __shfl_xor_sync(0xffffffffu, dot, 1);
        sc[w] = (k >= 0) ? dot : -1e30f;
        m = fmaxf(m, sc[w]);
    }

    float l = 0.0f;
    float p[W];
#pragma unroll
    for (int w = 0; w < W; w++) {
        p[w] = (q - w >= 0) ? __expf(sc[w] - m) : 0.0f;
        l += p[w];
    }

    float o[32];
#pragma unroll
    for (int dd = 0; dd < 32; dd++) o[dd] = 0.0f;
#pragma unroll
    for (int w = 0; w < W; w++) {
        int k = q - w;
        if (k >= 0) {
            int kr = qlid + 16 - w;
#pragma unroll
            for (int dd = 0; dd < 32; dd++)
                o[dd] += p[w] * Vs[kr * 65 + 2 * dd + half];
        }
    }

    float inv = 1.0f / l;
#pragma unroll
    for (int dd = 0; dd < 32; dd++)
        Qs[qlid * 65 + 2 * dd + half] = o[dd] * inv;
    __syncthreads();

    const size_t obase = (size_t)(b * SS + q0) * OP + (size_t)br * DD + h * HD;
    for (int e8 = tid; e8 < 64 * 8; e8 += 128) {
        int r = e8 >> 3, c8 = e8 & 7;
        const float* row = Qs + r * 65 + c8 * 8;
        uint4 hv, lv;
        hv.x = pack_hi(row[0], row[1]); lv.x = pack_lo(row[0], row[1]);
        hv.y = pack_hi(row[2], row[3]); lv.y = pack_lo(row[2], row[3]);
        hv.z = pack_hi(row[4], row[5]); lv.z = pack_lo(row[4], row[5]);
        hv.w = pack_hi(row[6], row[7]); lv.w = pack_lo(row[6], row[7]);
        size_t drow = obase + (size_t)r * OP + c8 * 8;
        *(uint4*)(atth + drow) = hv;
        *(uint4*)(attl + drow) = lv;
    }
}

__global__ __launch_bounds__(128) void window_attn_kernel(
    const __nv_bfloat16* __restrict__ qh, const __nv_bfloat16* __restrict__ ql,
    __nv_bfloat16* __restrict__ atth, __nv_bfloat16* __restrict__ attl)
{
    extern __shared__ float wsm[];
    if (blockIdx.z == 0)
        window_body<5>(qh, ql, atth, attl, wsm, 0);
    else
        window_body<10>(qh, ql, atth, attl, wsm, 1);
}

// ---------------------------------------------------------------------------
// Launch
// ---------------------------------------------------------------------------
extern "C" void kernel_launch(void* const* d_in, const int* in_sizes, int n_in,
                              void* d_out, int out_size)
{
    const float* x    = (const float*)d_in[0];   // [16,1024,512]
    const float* Wqkv = (const float*)d_in[1];   // [3,1536,512] = [4608,512]
    const float* bqkv = (const float*)d_in[2];   // [4608]
    const float* Wo   = (const float*)d_in[3];   // [3,512,512]
    const float* bo   = (const float*)d_in[4];   // [3,512]
    const float* Wf   = (const float*)d_in[5];   // [512,1536]
    const float* bf   = (const float*)d_in[6];   // [512]
    float* out = (float*)d_out;

    __nv_bfloat16 *xh, *xl, *qkvh, *qkvl, *atth, *attl, *combh, *combl;
    __nv_bfloat16 *Wqkvh, *Wqkvl, *Woh, *Wol, *Wfh, *Wfl;
    cudaGetSymbolAddress((void**)&xh, g_xh);
    cudaGetSymbolAddress((void**)&xl, g_xl);
    cudaGetSymbolAddress((void**)&qkvh, g_qkvh);
    cudaGetSymbolAddress((void**)&qkvl, g_qkvl);
    cudaGetSymbolAddress((void**)&atth, g_atth);
    cudaGetSymbolAddress((void**)&attl, g_attl);
    cudaGetSymbolAddress((void**)&combh, g_combh);
    cudaGetSymbolAddress((void**)&combl, g_combl);
    cudaGetSymbolAddress((void**)&Wqkvh, g_Wqkvh);
    cudaGetSymbolAddress((void**)&Wqkvl, g_Wqkvl);
    cudaGetSymbolAddress((void**)&Woh, g_Woh);
    cudaGetSymbolAddress((void**)&Wol, g_Wol);
    cudaGetSymbolAddress((void**)&Wfh, g_Wfh);
    cudaGetSymbolAddress((void**)&Wfl, g_Wfl);

    cudaFuncSetAttribute(gemm_bf16_kernel,
                         cudaFuncAttributeMaxDynamicSharedMemorySize, GEMM_SMEM);
    cudaFuncSetAttribute(flash_hmma_kernel,
                         cudaFuncAttributeMaxDynamicSharedMemorySize, FLASH_SMEM);
    cudaFuncSetAttribute(window_attn_kernel,
                         cudaFuncAttributeMaxDynamicSharedMemorySize, WIN_SMEM);

    // Conversions
    {
        int n4;
        n4 = MM * DD / 4;
        convert_hilo_kernel<<<(n4 + 255) / 256, 256>>>(x, xh, xl, n4);
        n4 = 3 * D3 * DD / 4;
        convert_hilo_kernel<<<(n4 + 255) / 256, 256>>>(Wqkv, Wqkvh, Wqkvl, n4);
        n4 = 3 * DD * DD / 4;
        convert_hilo_kernel<<<(n4 + 255) / 256, 256>>>(Wo, Woh, Wol, n4);
        n4 = DD * D3 / 4;
        convert_hilo_kernel<<<(n4 + 255) / 256, 256>>>(Wf, Wfh, Wfl, n4);
    }

    // 1) All three QKV projections as one GEMM
    {
        dim3 grid(QP / 256, MM / 128, 1);
        gemm_bf16_kernel<<<grid, 256, GEMM_SMEM>>>(
            xh, xl, Wqkvh, Wqkvl, bqkv, nullptr, qkvh, qkvl,
            DD, DD, QP, 0, 0, 0, 0, 0);
    }

    // 2) Attention: both windows (one launch) + flash
    {
        dim3 wgrid(SS / 64, BB * HH, 2);
        window_attn_kernel<<<wgrid, 128, WIN_SMEM>>>(qkvh, qkvl, atth, attl);
        dim3 fgrid(SS / 64, BB * HH, 1);
        flash_hmma_kernel<<<fgrid, 128, FLASH_SMEM>>>(qkvh, qkvl, atth, attl);
    }

    // 3) Batched out-projections
    {
        dim3 grid(DD / 256, MM / 128, 3);
        gemm_bf16_kernel<<<grid, 256, GEMM_SMEM>>>(
            atth, attl, Woh, Wol, bo, nullptr, combh, combl,
            DD, OP, OP, 0, DD, DD * DD, DD, DD);
    }

    // 4) Final projection (fp32 out)
    {
        dim3 grid(DD / 256, MM / 128, 1);
        gemm_bf16_kernel<<<grid, 256, GEMM_SMEM>>>(
            combh, combl, Wfh, Wfl, bf, out, nullptr, nullptr,
            D3, D3, DD, 0, 0, 0, 0, 0);
    }
}

// round 15
// speedup vs baseline: 4.0373x; 1.0071x over previous
#include <cuda_runtime.h>
#include <cuda_bf16.h>
#include <cstdint>
#include <math.h>

// Problem constants
#define BB 16
#define SS 1024
#define DD 512
#define HH 8
#define HD 64
#define MM (BB * SS)          // 16384 rows
#define D3 (3 * DD)           // 1536
#define QP (3 * D3)           // 4608 packed qkv width (3 branches)
#define OP D3                 // 1536 att/comb width

// ---------------------------------------------------------------------------
// Scratch (static device globals; no runtime allocation allowed)
// ---------------------------------------------------------------------------
__device__ __nv_bfloat16 g_xh[(size_t)MM * DD],   g_xl[(size_t)MM * DD];
__device__ __nv_bfloat16 g_qkvh[(size_t)MM * QP], g_qkvl[(size_t)MM * QP];
__device__ __nv_bfloat16 g_atth[(size_t)MM * OP], g_attl[(size_t)MM * OP];
__device__ __nv_bfloat16 g_combh[(size_t)MM * OP], g_combl[(size_t)MM * OP];
__device__ __nv_bfloat16 g_Wqkvh[(size_t)3 * D3 * DD], g_Wqkvl[(size_t)3 * D3 * DD];
__device__ __nv_bfloat16 g_Woh[(size_t)3 * DD * DD],   g_Wol[(size_t)3 * DD * DD];
__device__ __nv_bfloat16 g_Wfh[(size_t)DD * D3],   g_Wfl[(size_t)DD * D3];

// ---------------------------------------------------------------------------
// Helpers (base sm_80+ PTX only — NO 'a'-suffix features)
// ---------------------------------------------------------------------------
__device__ __forceinline__ uint32_t smem_u32(const void* p) {
    uint32_t a;
    asm("{ .reg .u64 t; cvta.to.shared.u64 t, %1; cvt.u32.u64 %0, t; }" : "=r"(a) : "l"(p));
    return a;
}
__device__ __forceinline__ void ldsm4(uint32_t* r, uint32_t addr) {
    asm volatile("ldmatrix.sync.aligned.m8n8.x4.shared.b16 {%0,%1,%2,%3}, [%4];"
                 : "=r"(r[0]), "=r"(r[1]), "=r"(r[2]), "=r"(r[3]) : "r"(addr));
}
__device__ __forceinline__ void ldsm4t(uint32_t* r, uint32_t addr) {
    asm volatile("ldmatrix.sync.aligned.m8n8.x4.trans.shared.b16 {%0,%1,%2,%3}, [%4];"
                 : "=r"(r[0]), "=r"(r[1]), "=r"(r[2]), "=r"(r[3]) : "r"(addr));
}
__device__ __forceinline__ void mma16816(float* c, const uint32_t* a, const uint32_t* b) {
    asm volatile("mma.sync.aligned.m16n8k16.row.col.f32.bf16.bf16.f32 "
                 "{%0,%1,%2,%3}, {%4,%5,%6,%7}, {%8,%9}, {%0,%1,%2,%3};"
                 : "+f"(c[0]), "+f"(c[1]), "+f"(c[2]), "+f"(c[3])
                 : "r"(a[0]), "r"(a[1]), "r"(a[2]), "r"(a[3]), "r"(b[0]), "r"(b[1]));
}
__device__ __forceinline__ void cp16(uint32_t saddr, const void* g) {
    asm volatile("cp.async.cg.shared.global [%0], [%1], 16;" :: "r"(saddr), "l"(g));
}
#define CP_COMMIT() asm volatile("cp.async.commit_group;" ::: "memory")
#define CP_WAIT1()  asm volatile("cp.async.wait_group 1;" ::: "memory")
#define CP_WAIT0()  asm volatile("cp.async.wait_group 0;" ::: "memory")

__device__ __forceinline__ uint32_t pack_hi(float x, float y) {
    uint16_t a = __bfloat16_as_ushort(__float2bfloat16_rn(x));
    uint16_t b = __bfloat16_as_ushort(__float2bfloat16_rn(y));
    return (uint32_t)a | ((uint32_t)b << 16);
}
__device__ __forceinline__ uint32_t pack_lo(float x, float y) {
    float xh = __bfloat162float(__float2bfloat16_rn(x));
    float yh = __bfloat162float(__float2bfloat16_rn(y));
    uint16_t a = __bfloat16_as_ushort(__float2bfloat16_rn(x - xh));
    uint16_t b = __bfloat16_as_ushort(__float2bfloat16_rn(y - yh));
    return (uint32_t)a | ((uint32_t)b << 16);
}
__device__ __forceinline__ float2 bf2sum(uint32_t h, uint32_t l) {
    __nv_bfloat162 hb = *reinterpret_cast<__nv_bfloat162*>(&h);
    __nv_bfloat162 lb = *reinterpret_cast<__nv_bfloat162*>(&l);
    float2 hf = __bfloat1622float2(hb), lf = __bfloat1622float2(lb);
    return make_float2(hf.x + lf.x, hf.y + lf.y);
}

// ---------------------------------------------------------------------------
// fp32 -> bf16 hi/lo conversion
// ---------------------------------------------------------------------------
__global__ __launch_bounds__(256) void convert_hilo_kernel(
    const float* __restrict__ src, __nv_bfloat16* __restrict__ h,
    __nv_bfloat16* __restrict__ l, int n4)
{
    int i = blockIdx.x * blockDim.x + threadIdx.x;
    if (i < n4) {
        float4 v = *(const float4*)(src + (size_t)i * 4);
        uint2 ph, pl;
        ph.x = pack_hi(v.x, v.y); ph.y = pack_hi(v.z, v.w);
        pl.x = pack_lo(v.x, v.y); pl.y = pack_lo(v.z, v.w);
        *(uint2*)(h + (size_t)i * 4) = ph;
        *(uint2*)(l + (size_t)i * 4) = pl;
    }
}

// ---------------------------------------------------------------------------
// HMMA GEMM, bf16 hi/lo 3-term split, batched over blockIdx.z.
// Block tile 128x256, KC=32, 8 warps = 2(m) x 4(n), warp tile 64x64.
// 3-stage cp.async pipeline, term-major MMA ordering. (Unchanged from R11.)
// ---------------------------------------------------------------------------
#define KC 32
#define PITCH 40                         // bf16 per smem row (80 B)
#define A_EL (128 * PITCH)               // 5120 elements per A tile
#define W_EL (256 * PITCH)               // 10240 elements per W tile
#define OFF_AL (A_EL * 2)                // byte offsets inside a stage
#define OFF_WH (A_EL * 4)
#define OFF_WL (A_EL * 4 + W_EL * 2)
#define STAGE_B ((A_EL * 2 + W_EL * 2) * 2)   // 61440 bytes per stage
#define GEMM_SMEM (3 * STAGE_B)               // 184320 bytes (3 stages)

__global__ __launch_bounds__(256, 1) void gemm_bf16_kernel(
    const __nv_bfloat16* __restrict__ Ah, const __nv_bfloat16* __restrict__ Al,
    const __nv_bfloat16* __restrict__ Wh, const __nv_bfloat16* __restrict__ Wl,
    const float* __restrict__ bias, float* __restrict__ C,
    __nv_bfloat16* __restrict__ Ch, __nv_bfloat16* __restrict__ Cl,
    int K, int lda, int ldc, int col0,
    int aColZ, int wZ, int biasZ, int cColZ)
{
    extern __shared__ __nv_bfloat16 smem[];
    const uint32_t sbase = smem_u32(smem);

    const int tid = threadIdx.x;
    const int wid = tid >> 5, lane = tid & 31;
    const int z = blockIdx.z;
    const int m0 = blockIdx.y * 128;
    const int n0 = blockIdx.x * 256;
    const int warp_m = (wid & 1) * 64;
    const int warp_n = (wid >> 1) * 64;

    const __nv_bfloat16* Abh = Ah + (size_t)m0 * lda + (size_t)z * aColZ;
    const __nv_bfloat16* Abl = Al + (size_t)m0 * lda + (size_t)z * aColZ;
    const __nv_bfloat16* Wbh = Wh + (size_t)z * wZ + (size_t)n0 * K;
    const __nv_bfloat16* Wbl = Wl + (size_t)z * wZ + (size_t)n0 * K;
    const float* biasz = bias + (size_t)z * biasZ;
    const int ccol0 = col0 + z * cColZ;

    const int aoff = (warp_m + (lane & 15)) * (PITCH * 2) + (((lane >> 4) << 3) << 1);
    const int bm = lane >> 3;
    const int boff = (warp_n + (lane & 7) + ((bm >> 1) << 3)) * (PITCH * 2) + (((bm & 1) << 3) << 1);

    float acc[4][8][4];
#pragma unroll
    for (int mt = 0; mt < 4; mt++)
#pragma unroll
        for (int nt = 0; nt < 8; nt++)
#pragma unroll
            for (int i = 0; i < 4; i++) acc[mt][nt][i] = 0.0f;

    const int nchunks = K / KC;

    auto prefetch = [&](int kt, int stg) {
        const int k0 = kt * KC;
        const uint32_t sb = sbase + stg * STAGE_B;
#pragma unroll
        for (int j = 0; j < 2; j++) {
            int idx = tid + j * 256;
            int row = idx >> 2, c = idx & 3;
            uint32_t so = (uint32_t)(row * (PITCH * 2) + c * 16);
            size_t go = (size_t)row * lda + k0 + c * 8;
            cp16(sb + so,          Abh + go);
            cp16(sb + OFF_AL + so, Abl + go);
        }
#pragma unroll
        for (int j = 0; j < 4; j++) {
            int idx = tid + j * 256;
            int row = idx >> 2, c = idx & 3;
            uint32_t so = (uint32_t)(row * (PITCH * 2) + c * 16);
            size_t go = (size_t)row * K + k0 + c * 8;
            cp16(sb + OFF_WH + so, Wbh + go);
            cp16(sb + OFF_WL + so, Wbl + go);
        }
    };

    prefetch(0, 0);
    CP_COMMIT();
    prefetch(1, 1);
    CP_COMMIT();

    int stg = 0;
    for (int kt = 0; kt < nchunks; kt++) {
        if (kt + 1 < nchunks) { CP_WAIT1(); } else { CP_WAIT0(); }
        __syncthreads();

        if (kt + 2 < nchunks) {
            int ns = stg + 2; if (ns >= 3) ns -= 3;
            prefetch(kt + 2, ns);
            CP_COMMIT();
        }

        const uint32_t sb = sbase + stg * STAGE_B;
        const uint32_t uAh = sb, uAl = sb + OFF_AL;
        const uint32_t uWh = sb + OFF_WH, uWl = sb + OFF_WL;

#pragma unroll
        for (int ks = 0; ks < 2; ks++) {
            const int kb = ks * 32;

            uint32_t aH[4][4], aL[4][4], bH[4][4], bL[4][4];
#pragma unroll
            for (int mt = 0; mt < 4; mt++) {
                ldsm4(aH[mt], uAh + aoff + mt * 16 * (PITCH * 2) + kb);
                ldsm4(aL[mt], uAl + aoff + mt * 16 * (PITCH * 2) + kb);
            }
#pragma unroll
            for (int np = 0; np < 4; np++) {
                ldsm4(bH[np], uWh + boff + np * 16 * (PITCH * 2) + kb);
                ldsm4(bL[np], uWl + boff + np * 16 * (PITCH * 2) + kb);
            }

#pragma unroll
            for (int mt = 0; mt < 4; mt++)
#pragma unroll
                for (int np = 0; np < 4; np++) {
                    mma16816(acc[mt][2 * np],     aH[mt], bH[np]);
                    mma16816(acc[mt][2 * np + 1], aH[mt], bH[np] + 2);
                }
#pragma unroll
            for (int mt = 0; mt < 4; mt++)
#pragma unroll
                for (int np = 0; np < 4; np++) {
                    mma16816(acc[mt][2 * np],     aH[mt], bL[np]);
                    mma16816(acc[mt][2 * np + 1], aH[mt], bL[np] + 2);
                }
#pragma unroll
            for (int mt = 0; mt < 4; mt++)
#pragma unroll
                for (int np = 0; np < 4; np++) {
                    mma16816(acc[mt][2 * np],     aL[mt], bH[np]);
                    mma16816(acc[mt][2 * np + 1], aL[mt], bH[np] + 2);
                }
        }
        if (++stg >= 3) stg = 0;
    }

    // Epilogue
    const int g = lane >> 2, tg = lane & 3;
#pragma unroll
    for (int nt = 0; nt < 8; nt++) {
        const int ncol = warp_n + nt * 8 + tg * 2;
        const float b0 = biasz[n0 + ncol], b1 = biasz[n0 + ncol + 1];
#pragma unroll
        for (int mt = 0; mt < 4; mt++) {
            const int r0 = m0 + warp_m + mt * 16 + g;
#pragma unroll
            for (int hh = 0; hh < 2; hh++) {
                const int r = r0 + hh * 8;
                const float v0 = acc[mt][nt][2 * hh] + b0;
                const float v1 = acc[mt][nt][2 * hh + 1] + b1;
                const size_t idx = (size_t)r * ldc + ccol0 + n0 + ncol;
                if (C) {
                    float2 o; o.x = v0; o.y = v1;
                    *(float2*)(C + idx) = o;
                } else {
                    *(uint32_t*)(Ch + idx) = pack_hi(v0, v1);
                    *(uint32_t*)(Cl + idx) = pack_lo(v0, v1);
                }
            }
        }
    }
}

// ---------------------------------------------------------------------------
// Flash attention body (branch 2 of packed qkv). 128 threads.
// 2-stage cp.async K/V staging, term-major MMAs. (Body = R11's kernel.)
// ---------------------------------------------------------------------------
#define FPITCH 72
#define FTILE_B (64 * FPITCH * 2)         // 9216 bytes per tile
#define FSTAGE_B (4 * FTILE_B)            // 36864 bytes per stage (Kh,Kl,Vh,Vl)
#define FLASH_SMEM (2 * FSTAGE_B)         // 73728 bytes

__device__ void flash_body(
    const __nv_bfloat16* __restrict__ qh, const __nv_bfloat16* __restrict__ ql,
    __nv_bfloat16* __restrict__ atth, __nv_bfloat16* __restrict__ attl,
    __nv_bfloat16* fsm)
{
    const uint32_t sbase = smem_u32(fsm);

    const int tid = threadIdx.x;
    const int warp = tid >> 5, lane = tid & 31;
    const int g = lane >> 2, t = lane & 3;
    const int q0 = blockIdx.x * 64;
    const int b = blockIdx.y >> 3, h = blockIdx.y & 7;

    const size_t rowQ0 = (size_t)(b * SS + q0 + warp * 16 + g) * QP + 2 * D3 + h * HD;
    const size_t rowQ1 = rowQ0 + (size_t)8 * QP;
    uint32_t qH[4][4], qL[4][4];
#pragma unroll
    for (int ks = 0; ks < 4; ks++) {
        const int c = ks * 16 + 2 * t;
        qH[ks][0] = *(const uint32_t*)(qh + rowQ0 + c);
        qH[ks][1] = *(const uint32_t*)(qh + rowQ1 + c);
        qH[ks][2] = *(const uint32_t*)(qh + rowQ0 + c + 8);
        qH[ks][3] = *(const uint32_t*)(qh + rowQ1 + c + 8);
        qL[ks][0] = *(const uint32_t*)(ql + rowQ0 + c);
        qL[ks][1] = *(const uint32_t*)(ql + rowQ1 + c);
        qL[ks][2] = *(const uint32_t*)(ql + rowQ0 + c + 8);
        qL[ks][3] = *(const uint32_t*)(ql + rowQ1 + c + 8);
    }

    const int bm = lane >> 3;
    const int kboff = ((lane & 7) + ((bm >> 1) << 3)) * (FPITCH * 2) + ((bm & 1) << 3) * 2;
    const int vboff = ((lane & 7) + ((bm & 1) << 3)) * (FPITCH * 2) + (lane >> 4) * 16;

    float o[8][4];
    float mrow[2], lrow[2];
#pragma unroll
    for (int nt = 0; nt < 8; nt++)
#pragma unroll
        for (int i = 0; i < 4; i++) o[nt][i] = 0.0f;
    mrow[0] = mrow[1] = -1e30f;
    lrow[0] = lrow[1] = 0.0f;

    const size_t kvbase = (size_t)(b * SS) * QP + 2 * D3 + h * HD;

    auto prefetch_kv = [&](int kt, int stg) {
        const size_t tb = kvbase + (size_t)(kt * 64) * QP;
        const uint32_t sb = sbase + stg * FSTAGE_B;
#pragma unroll
        for (int l = 0; l < 4; l++) {
            int idx = tid + l * 128;
            int r = idx >> 3, c4 = idx & 7;
            size_t gsrc = tb + (size_t)r * QP + c4 * 8;
            uint32_t sdst = (uint32_t)(r * (FPITCH * 2) + c4 * 16);
            cp16(sb + sdst,               qh + gsrc + 512);
            cp16(sb + FTILE_B + sdst,     ql + gsrc + 512);
            cp16(sb + 2 * FTILE_B + sdst, qh + gsrc + 1024);
            cp16(sb + 3 * FTILE_B + sdst, ql + gsrc + 1024);
        }
    };

    prefetch_kv(0, 0);
    CP_COMMIT();

    for (int kt = 0; kt < 16; kt++) {
        if (kt + 1 < 16) {
            prefetch_kv(kt + 1, (kt + 1) & 1);
            CP_COMMIT();
            CP_WAIT1();
        } else {
            CP_WAIT0();
        }
        __syncthreads();

        const uint32_t sb = sbase + (kt & 1) * FSTAGE_B;
        const uint32_t uKh = sb, uKl = sb + FTILE_B;
        const uint32_t uVh = sb + 2 * FTILE_B, uVl = sb + 3 * FTILE_B;

        float s[8][4];
#pragma unroll
        for (int nt = 0; nt < 8; nt++)
#pragma unroll
            for (int i = 0; i < 4; i++) s[nt][i] = 0.0f;

#pragma unroll
        for (int ks = 0; ks < 4; ks++) {
            const int kb = ks * 32;
            uint32_t kh[4][4], kl[4][4];
#pragma unroll
            for (int np = 0; np < 4; np++) {
                ldsm4(kh[np], uKh + kboff + np * 16 * (FPITCH * 2) + kb);
                ldsm4(kl[np], uKl + kboff + np * 16 * (FPITCH * 2) + kb);
            }
#pragma unroll
            for (int np = 0; np < 4; np++) {
                mma16816(s[2 * np],     qH[ks], kh[np]);
                mma16816(s[2 * np + 1], qH[ks], kh[np] + 2);
            }
#pragma unroll
            for (int np = 0; np < 4; np++) {
                mma16816(s[2 * np],     qH[ks], kl[np]);
                mma16816(s[2 * np + 1], qH[ks], kl[np] + 2);
            }
#pragma unroll
            for (int np = 0; np < 4; np++) {
                mma16816(s[2 * np],     qL[ks], kh[np]);
                mma16816(s[2 * np + 1], qL[ks], kh[np] + 2);
            }
        }

#pragma unroll
        for (int r = 0; r < 2; r++) {
            float mx = -1e30f;
#pragma unroll
            for (int nt = 0; nt < 8; nt++) {
                s[nt][2 * r]     *= 0.125f;
                s[nt][2 * r + 1] *= 0.125f;
                mx = fmaxf(mx, fmaxf(s[nt][2 * r], s[nt][2 * r + 1]));
            }
            mx = fmaxf(mx, __shfl_xor_sync(0xffffffffu, mx, 1));
            mx = fmaxf(mx, __shfl_xor_sync(0xffffffffu, mx, 2));
            float mnew = fmaxf(mrow[r], mx);
            float alpha = __expf(mrow[r] - mnew);
            float ls = 0.0f;
#pragma unroll
            for (int nt = 0; nt < 8; nt++) {
                float p0 = __expf(s[nt][2 * r] - mnew);
                float p1 = __expf(s[nt][2 * r + 1] - mnew);
                s[nt][2 * r] = p0; s[nt][2 * r + 1] = p1;
                ls += p0 + p1;
            }
            ls += __shfl_xor_sync(0xffffffffu, ls, 1);
            ls += __shfl_xor_sync(0xffffffffu, ls, 2);
            lrow[r] = lrow[r] * alpha + ls;
            mrow[r] = mnew;
#pragma unroll
            for (int nt = 0; nt < 8; nt++) {
                o[nt][2 * r] *= alpha; o[nt][2 * r + 1] *= alpha;
            }
        }

        uint32_t pH[4][4], pL[4][4];
#pragma unroll
        for (int j = 0; j < 4; j++) {
            pH[j][0] = pack_hi(s[2 * j][0], s[2 * j][1]);
            pH[j][1] = pack_hi(s[2 * j][2], s[2 * j][3]);
            pH[j][2] = pack_hi(s[2 * j + 1][0], s[2 * j + 1][1]);
            pH[j][3] = pack_hi(s[2 * j + 1][2], s[2 * j + 1][3]);
            pL[j][0] = pack_lo(s[2 * j][0], s[2 * j][1]);
            pL[j][1] = pack_lo(s[2 * j][2], s[2 * j][3]);
            pL[j][2] = pack_lo(s[2 * j + 1][0], s[2 * j + 1][1]);
            pL[j][3] = pack_lo(s[2 * j + 1][2], s[2 * j + 1][3]);
        }

#pragma unroll
        for (int j = 0; j < 4; j++) {
            const int rb = j * 16 * (FPITCH * 2);
            uint32_t vh[4][4], vl[4][4];
#pragma unroll
            for (int np = 0; np < 4; np++) {
                ldsm4t(vh[np], uVh + vboff + rb + np * 32);
                ldsm4t(vl[np], uVl + vboff + rb + np * 32);
            }
#pragma unroll
            for (int np = 0; np < 4; np++) {
                mma16816(o[2 * np],     pH[j], vh[np]);
                mma16816(o[2 * np + 1], pH[j], vh[np] + 2);
            }
#pragma unroll
            for (int np = 0; np < 4; np++) {
                mma16816(o[2 * np],     pH[j], vl[np]);
                mma16816(o[2 * np + 1], pH[j], vl[np] + 2);
            }
#pragma unroll
            for (int np = 0; np < 4; np++) {
                mma16816(o[2 * np],     pL[j], vh[np]);
                mma16816(o[2 * np + 1], pL[j], vh[np] + 2);
            }
        }
        __syncthreads();
    }

    const float inv0 = 1.0f / lrow[0], inv1 = 1.0f / lrow[1];
    const size_t orow0 = (size_t)(b * SS + q0 + warp * 16 + g) * OP + 2 * DD + h * HD;
    const size_t orow1 = orow0 + (size_t)8 * OP;
#pragma unroll
    for (int nt = 0; nt < 8; nt++) {
        const int c = nt * 8 + 2 * t;
        const float a0 = o[nt][0] * inv0, a1 = o[nt][1] * inv0;
        const float b0 = o[nt][2] * inv1, b1 = o[nt][3] * inv1;
        *(uint32_t*)(atth + orow0 + c) = pack_hi(a0, a1);
        *(uint32_t*)(attl + orow0 + c) = pack_lo(a0, a1);
        *(uint32_t*)(atth + orow1 + c) = pack_hi(b0, b1);
        *(uint32_t*)(attl + orow1 + c) = pack_lo(b0, b1);
    }
}

// ---------------------------------------------------------------------------
// Windowed causal attention body, fully coalesced (unchanged from R11)
// ---------------------------------------------------------------------------
#define WQS 0
#define WKS (64 * 65)
#define WVS (WKS + 80 * 65)

template <int W>
__device__ __forceinline__ void window_body(
    const __nv_bfloat16* __restrict__ qh, const __nv_bfloat16* __restrict__ ql,
    __nv_bfloat16* __restrict__ atth, __nv_bfloat16* __restrict__ attl,
    float* wsm, int br)
{
    float* Qs = wsm + WQS;
    float* Ks = wsm + WKS;
    float* Vs = wsm + WVS;

    const int tid = threadIdx.x;
    const int q0 = blockIdx.x * 64;
    const int bh = blockIdx.y;
    const int b = bh >> 3, h = bh & 7;
    const size_t base = (size_t)b * SS * QP + (size_t)br * D3 + h * HD;

    for (int e8 = tid; e8 < 64 * 8; e8 += 128) {
        int r = e8 >> 3, c8 = e8 & 7;
        size_t src = base + (size_t)(q0 + r) * QP + c8 * 8;
        uint4 xh4 = *(const uint4*)(qh + src);
        uint4 xl4 = *(const uint4*)(ql + src);
        float* qd = Qs + r * 65 + c8 * 8;
        float2 f;
        f = bf2sum(xh4.x, xl4.x); qd[0] = f.x; qd[1] = f.y;
        f = bf2sum(xh4.y, xl4.y); qd[2] = f.x; qd[3] = f.y;
        f = bf2sum(xh4.z, xl4.z); qd[4] = f.x; qd[5] = f.y;
        f = bf2sum(xh4.w, xl4.w); qd[6] = f.x; qd[7] = f.y;
    }
    for (int e8 = tid; e8 < 80 * 8; e8 += 128) {
        int r = e8 >> 3, c8 = e8 & 7;
        int s = q0 - 16 + r;
        if (s >= 0) {
            size_t src = base + (size_t)s * QP + c8 * 8;
            uint4 kh = *(const uint4*)(qh + src + 512);
            uint4 kl = *(const uint4*)(ql + src + 512);
            uint4 vh = *(const uint4*)(qh + src + 1024);
            uint4 vl = *(const uint4*)(ql + src + 1024);
            float* kd = Ks + r * 65 + c8 * 8;
            float* vd = Vs + r * 65 + c8 * 8;
            float2 f;
            f = bf2sum(kh.x, kl.x); kd[0] = f.x; kd[1] = f.y;
            f = bf2sum(kh.y, kl.y); kd[2] = f.x; kd[3] = f.y;
            f = bf2sum(kh.z, kl.z); kd[4] = f.x; kd[5] = f.y;
            f = bf2sum(kh.w, kl.w); kd[6] = f.x; kd[7] = f.y;
            f = bf2sum(vh.x, vl.x); vd[0] = f.x; vd[1] = f.y;
            f = bf2sum(vh.y, vl.y); vd[2] = f.x; vd[3] = f.y;
            f = bf2sum(vh.z, vl.z); vd[4] = f.x; vd[5] = f.y;
            f = bf2sum(vh.w, vl.w); vd[6] = f.x; vd[7] = f.y;
        }
    }
    __syncthreads();

    const int qlid = tid >> 1;
    const int half = tid & 1;
    const int q = q0 + qlid;

    float qreg[32];
#pragma unroll
    for (int dd = 0; dd < 32; dd++)
        qreg[dd] = Qs[qlid * 65 + 2 * dd + half] * 0.125f;
    __syncthreads();

    float sc[W];
    float m = -1e30f;
#pragma unroll
    for (int w = 0; w < W; w++) {
        int k = q - w;
        int kr = qlid + 16 - w;
        float dot = 0.0f;
        if (k >= 0) {
#pragma unroll
            for (int dd = 0; dd < 32; dd++)
                dot += qreg[dd] * Ks[kr * 65 + 2 * dd + half];
        }
        dot += __shfl_xor_sync(0xffffffffu, dot, 1);
        sc[w] = (k >= 0) ? dot : -1e30f;
        m = fmaxf(m, sc[w]);
    }

    float l = 0.0f;
    float p[W];
#pragma unroll
    for (int w = 0; w < W; w++) {
        p[w] = (q - w >= 0) ? __expf(sc[w] - m) : 0.0f;
        l += p[w];
    }

    float o[32];
#pragma unroll
    for (int dd = 0; dd < 32; dd++) o[dd] = 0.0f;
#pragma unroll
    for (int w = 0; w < W; w++) {
        int k = q - w;
        if (k >= 0) {
            int kr = qlid + 16 - w;
#pragma unroll
            for (int dd = 0; dd < 32; dd++)
                o[dd] += p[w] * Vs[kr * 65 + 2 * dd + half];
        }
    }

    float inv = 1.0f / l;
#pragma unroll
    for (int dd = 0; dd < 32; dd++)
        Qs[qlid * 65 + 2 * dd + half] = o[dd] * inv;
    __syncthreads();

    const size_t obase = (size_t)(b * SS + q0) * OP + (size_t)br * DD + h * HD;
    for (int e8 = tid; e8 < 64 * 8; e8 += 128) {
        int r = e8 >> 3, c8 = e8 & 7;
        const float* row = Qs + r * 65 + c8 * 8;
        uint4 hv, lv;
        hv.x = pack_hi(row[0], row[1]); lv.x = pack_lo(row[0], row[1]);
        hv.y = pack_hi(row[2], row[3]); lv.y = pack_lo(row[2], row[3]);
        hv.z = pack_hi(row[4], row[5]); lv.z = pack_lo(row[4], row[5]);
        hv.w = pack_hi(row[6], row[7]); lv.w = pack_lo(row[6], row[7]);
        size_t drow = obase + (size_t)r * OP + c8 * 8;
        *(uint4*)(atth + drow) = hv;
        *(uint4*)(attl + drow) = lv;
    }
}

// ---------------------------------------------------------------------------
// Unified attention kernel: z=0 window<5>, z=1 window<10>, z=2 flash.
// One launch lets window CTAs hide under the flash wave.
// Dynamic smem = max(FLASH_SMEM, window 58240) = FLASH_SMEM.
// ---------------------------------------------------------------------------
#define ATTN_SMEM FLASH_SMEM

__global__ __launch_bounds__(128) void attn_kernel(
    const __nv_bfloat16* __restrict__ qh, const __nv_bfloat16* __restrict__ ql,
    __nv_bfloat16* __restrict__ atth, __nv_bfloat16* __restrict__ attl)
{
    extern __shared__ char asmem[];
    if (blockIdx.z == 2) {
        flash_body(qh, ql, atth, attl, reinterpret_cast<__nv_bfloat16*>(asmem));
    } else if (blockIdx.z == 0) {
        window_body<5>(qh, ql, atth, attl, reinterpret_cast<float*>(asmem), 0);
    } else {
        window_body<10>(qh, ql, atth, attl, reinterpret_cast<float*>(asmem), 1);
    }
}

// ---------------------------------------------------------------------------
// Launch
// ---------------------------------------------------------------------------
extern "C" void kernel_launch(void* const* d_in, const int* in_sizes, int n_in,
                              void* d_out, int out_size)
{
    const float* x    = (const float*)d_in[0];   // [16,1024,512]
    const float* Wqkv = (const float*)d_in[1];   // [3,1536,512] = [4608,512]
    const float* bqkv = (const float*)d_in[2];   // [4608]
    const float* Wo   = (const float*)d_in[3];   // [3,512,512]
    const float* bo   = (const float*)d_in[4];   // [3,512]
    const float* Wf   = (const float*)d_in[5];   // [512,1536]
    const float* bf   = (const float*)d_in[6];   // [512]
    float* out = (float*)d_out;

    __nv_bfloat16 *xh, *xl, *qkvh, *qkvl, *atth, *attl, *combh, *combl;
    __nv_bfloat16 *Wqkvh, *Wqkvl, *Woh, *Wol, *Wfh, *Wfl;
    cudaGetSymbolAddress((void**)&xh, g_xh);
    cudaGetSymbolAddress((void**)&xl, g_xl);
    cudaGetSymbolAddress((void**)&qkvh, g_qkvh);
    cudaGetSymbolAddress((void**)&qkvl, g_qkvl);
    cudaGetSymbolAddress((void**)&atth, g_atth);
    cudaGetSymbolAddress((void**)&attl, g_attl);
    cudaGetSymbolAddress((void**)&combh, g_combh);
    cudaGetSymbolAddress((void**)&combl, g_combl);
    cudaGetSymbolAddress((void**)&Wqkvh, g_Wqkvh);
    cudaGetSymbolAddress((void**)&Wqkvl, g_Wqkvl);
    cudaGetSymbolAddress((void**)&Woh, g_Woh);
    cudaGetSymbolAddress((void**)&Wol, g_Wol);
    cudaGetSymbolAddress((void**)&Wfh, g_Wfh);
    cudaGetSymbolAddress((void**)&Wfl, g_Wfl);

    cudaFuncSetAttribute(gemm_bf16_kernel,
                         cudaFuncAttributeMaxDynamicSharedMemorySize, GEMM_SMEM);
    cudaFuncSetAttribute(attn_kernel,
                         cudaFuncAttributeMaxDynamicSharedMemorySize, ATTN_SMEM);

    // Conversions
    {
        int n4;
        n4 = MM * DD / 4;
        convert_hilo_kernel<<<(n4 + 255) / 256, 256>>>(x, xh, xl, n4);
        n4 = 3 * D3 * DD / 4;
        convert_hilo_kernel<<<(n4 + 255) / 256, 256>>>(Wqkv, Wqkvh, Wqkvl, n4);
        n4 = 3 * DD * DD / 4;
        convert_hilo_kernel<<<(n4 + 255) / 256, 256>>>(Wo, Woh, Wol, n4);
        n4 = DD * D3 / 4;
        convert_hilo_kernel<<<(n4 + 255) / 256, 256>>>(Wf, Wfh, Wfl, n4);
    }

    // 1) All three QKV projections as one GEMM
    {
        dim3 grid(QP / 256, MM / 128, 1);
        gemm_bf16_kernel<<<grid, 256, GEMM_SMEM>>>(
            xh, xl, Wqkvh, Wqkvl, bqkv, nullptr, qkvh, qkvl,
            DD, DD, QP, 0, 0, 0, 0, 0);
    }

    // 2) Attention: windows + flash in ONE launch (z=0,1 windows; z=2 flash)
    {
        dim3 agrid(SS / 64, BB * HH, 3);
        attn_kernel<<<agrid, 128, ATTN_SMEM>>>(qkvh, qkvl, atth, attl);
    }

    // 3) Batched out-projections
    {
        dim3 grid(DD / 256, MM / 128, 3);
        gemm_bf16_kernel<<<grid, 256, GEMM_SMEM>>>(
            atth, attl, Woh, Wol, bo, nullptr, combh, combl,
            DD, OP, OP, 0, DD, DD * DD, DD, DD);
    }

    // 4) Final projection (fp32 out)
    {
        dim3 grid(DD / 256, MM / 128, 1);
        gemm_bf16_kernel<<<grid, 256, GEMM_SMEM>>>(
            combh, combl, Wfh, Wfl, bf, out, nullptr, nullptr,
            D3, D3, DD, 0, 0, 0, 0, 0);
    }
}

// round 16
// speedup vs baseline: 4.1593x; 1.0302x over previous
#include <cuda_runtime.h>
#include <cuda_bf16.h>
#include <cstdint>
#include <math.h>

// Problem constants
#define BB 16
#define SS 1024
#define DD 512
#define HH 8
#define HD 64
#define MM (BB * SS)          // 16384 rows
#define D3 (3 * DD)           // 1536
#define QP (3 * D3)           // 4608 packed qkv width (3 branches)
#define OP D3                 // 1536 att/comb width

// ---------------------------------------------------------------------------
// Scratch (static device globals; no runtime allocation allowed)
// ---------------------------------------------------------------------------
__device__ __nv_bfloat16 g_xh[(size_t)MM * DD],   g_xl[(size_t)MM * DD];
__device__ __nv_bfloat16 g_qkvh[(size_t)MM * QP], g_qkvl[(size_t)MM * QP];
__device__ __nv_bfloat16 g_atth[(size_t)MM * OP], g_attl[(size_t)MM * OP];
__device__ __nv_bfloat16 g_combh[(size_t)MM * OP], g_combl[(size_t)MM * OP];
__device__ __nv_bfloat16 g_Wqkvh[(size_t)3 * D3 * DD], g_Wqkvl[(size_t)3 * D3 * DD];
__device__ __nv_bfloat16 g_Woh[(size_t)3 * DD * DD],   g_Wol[(size_t)3 * DD * DD];
__device__ __nv_bfloat16 g_Wfh[(size_t)DD * D3],   g_Wfl[(size_t)DD * D3];

// ---------------------------------------------------------------------------
// Helpers (base sm_80+ PTX only — NO 'a'-suffix features)
// ---------------------------------------------------------------------------
__device__ __forceinline__ uint32_t smem_u32(const void* p) {
    uint32_t a;
    asm("{ .reg .u64 t; cvta.to.shared.u64 t, %1; cvt.u32.u64 %0, t; }" : "=r"(a) : "l"(p));
    return a;
}
__device__ __forceinline__ void ldsm4(uint32_t* r, uint32_t addr) {
    asm volatile("ldmatrix.sync.aligned.m8n8.x4.shared.b16 {%0,%1,%2,%3}, [%4];"
                 : "=r"(r[0]), "=r"(r[1]), "=r"(r[2]), "=r"(r[3]) : "r"(addr));
}
__device__ __forceinline__ void ldsm4t(uint32_t* r, uint32_t addr) {
    asm volatile("ldmatrix.sync.aligned.m8n8.x4.trans.shared.b16 {%0,%1,%2,%3}, [%4];"
                 : "=r"(r[0]), "=r"(r[1]), "=r"(r[2]), "=r"(r[3]) : "r"(addr));
}
__device__ __forceinline__ void mma16816(float* c, const uint32_t* a, const uint32_t* b) {
    asm volatile("mma.sync.aligned.m16n8k16.row.col.f32.bf16.bf16.f32 "
                 "{%0,%1,%2,%3}, {%4,%5,%6,%7}, {%8,%9}, {%0,%1,%2,%3};"
                 : "+f"(c[0]), "+f"(c[1]), "+f"(c[2]), "+f"(c[3])
                 : "r"(a[0]), "r"(a[1]), "r"(a[2]), "r"(a[3]), "r"(b[0]), "r"(b[1]));
}
__device__ __forceinline__ void cp16(uint32_t saddr, const void* g) {
    asm volatile("cp.async.cg.shared.global [%0], [%1], 16;" :: "r"(saddr), "l"(g));
}
#define CP_COMMIT() asm volatile("cp.async.commit_group;" ::: "memory")
#define CP_WAIT1()  asm volatile("cp.async.wait_group 1;" ::: "memory")
#define CP_WAIT0()  asm volatile("cp.async.wait_group 0;" ::: "memory")

__device__ __forceinline__ uint32_t pack_hi(float x, float y) {
    uint16_t a = __bfloat16_as_ushort(__float2bfloat16_rn(x));
    uint16_t b = __bfloat16_as_ushort(__float2bfloat16_rn(y));
    return (uint32_t)a | ((uint32_t)b << 16);
}
__device__ __forceinline__ uint32_t pack_lo(float x, float y) {
    float xh = __bfloat162float(__float2bfloat16_rn(x));
    float yh = __bfloat162float(__float2bfloat16_rn(y));
    uint16_t a = __bfloat16_as_ushort(__float2bfloat16_rn(x - xh));
    uint16_t b = __bfloat16_as_ushort(__float2bfloat16_rn(y - yh));
    return (uint32_t)a | ((uint32_t)b << 16);
}
__device__ __forceinline__ float2 bf2sum(uint32_t h, uint32_t l) {
    __nv_bfloat162 hb = *reinterpret_cast<__nv_bfloat162*>(&h);
    __nv_bfloat162 lb = *reinterpret_cast<__nv_bfloat162*>(&l);
    float2 hf = __bfloat1622float2(hb), lf = __bfloat1622float2(lb);
    return make_float2(hf.x + lf.x, hf.y + lf.y);
}

// ---------------------------------------------------------------------------
// fp32 -> bf16 hi/lo conversion
// ---------------------------------------------------------------------------
__global__ __launch_bounds__(256) void convert_hilo_kernel(
    const float* __restrict__ src, __nv_bfloat16* __restrict__ h,
    __nv_bfloat16* __restrict__ l, int n4)
{
    int i = blockIdx.x * blockDim.x + threadIdx.x;
    if (i < n4) {
        float4 v = *(const float4*)(src + (size_t)i * 4);
        uint2 ph, pl;
        ph.x = pack_hi(v.x, v.y); ph.y = pack_hi(v.z, v.w);
        pl.x = pack_lo(v.x, v.y); pl.y = pack_lo(v.z, v.w);
        *(uint2*)(h + (size_t)i * 4) = ph;
        *(uint2*)(l + (size_t)i * 4) = pl;
    }
}

// ---------------------------------------------------------------------------
// HMMA GEMM, bf16 hi/lo 3-term split, batched over blockIdx.z.
// Block tile 128x256, KC=32, NOW 16 warps (512 threads) = 2(m) x 8(n),
// warp tile 64x32 -> 4 warps per SMSP to cover HMMA latency.
// 3-stage cp.async pipeline.
// ---------------------------------------------------------------------------
#define KC 32
#define PITCH 40                         // bf16 per smem row (80 B)
#define A_EL (128 * PITCH)               // 5120 elements per A tile
#define W_EL (256 * PITCH)               // 10240 elements per W tile
#define OFF_AL (A_EL * 2)                // byte offsets inside a stage
#define OFF_WH (A_EL * 4)
#define OFF_WL (A_EL * 4 + W_EL * 2)
#define STAGE_B ((A_EL * 2 + W_EL * 2) * 2)   // 61440 bytes per stage
#define GEMM_SMEM (3 * STAGE_B)               // 184320 bytes (3 stages)

__global__ __launch_bounds__(512, 1) void gemm_bf16_kernel(
    const __nv_bfloat16* __restrict__ Ah, const __nv_bfloat16* __restrict__ Al,
    const __nv_bfloat16* __restrict__ Wh, const __nv_bfloat16* __restrict__ Wl,
    const float* __restrict__ bias, float* __restrict__ C,
    __nv_bfloat16* __restrict__ Ch, __nv_bfloat16* __restrict__ Cl,
    int K, int lda, int ldc, int col0,
    int aColZ, int wZ, int biasZ, int cColZ)
{
    extern __shared__ __nv_bfloat16 smem[];
    const uint32_t sbase = smem_u32(smem);

    const int tid = threadIdx.x;
    const int wid = tid >> 5, lane = tid & 31;
    const int z = blockIdx.z;
    const int m0 = blockIdx.y * 128;
    const int n0 = blockIdx.x * 256;
    const int warp_m = (wid & 1) * 64;     // 2 m-groups of 64
    const int warp_n = (wid >> 1) * 32;    // 8 n-groups of 32

    const __nv_bfloat16* Abh = Ah + (size_t)m0 * lda + (size_t)z * aColZ;
    const __nv_bfloat16* Abl = Al + (size_t)m0 * lda + (size_t)z * aColZ;
    const __nv_bfloat16* Wbh = Wh + (size_t)z * wZ + (size_t)n0 * K;
    const __nv_bfloat16* Wbl = Wl + (size_t)z * wZ + (size_t)n0 * K;
    const float* biasz = bias + (size_t)z * biasZ;
    const int ccol0 = col0 + z * cColZ;

    const int aoff = (warp_m + (lane & 15)) * (PITCH * 2) + (((lane >> 4) << 3) << 1);
    const int bm = lane >> 3;
    const int boff = (warp_n + (lane & 7) + ((bm >> 1) << 3)) * (PITCH * 2) + (((bm & 1) << 3) << 1);

    float acc[4][4][4];    // [m16 tile][n8 tile][frag]
#pragma unroll
    for (int mt = 0; mt < 4; mt++)
#pragma unroll
        for (int nt = 0; nt < 4; nt++)
#pragma unroll
            for (int i = 0; i < 4; i++) acc[mt][nt][i] = 0.0f;

    const int nchunks = K / KC;

    auto prefetch = [&](int kt, int stg) {
        const int k0 = kt * KC;
        const uint32_t sb = sbase + stg * STAGE_B;
        // A: 128 rows x 32 cols = 512 x 16B per array; 1 per thread
        {
            int row = tid >> 2, c = tid & 3;
            uint32_t so = (uint32_t)(row * (PITCH * 2) + c * 16);
            size_t go = (size_t)row * lda + k0 + c * 8;
            cp16(sb + so,          Abh + go);
            cp16(sb + OFF_AL + so, Abl + go);
        }
        // W: 256 rows x 32 cols = 1024 x 16B per array; 2 per thread
#pragma unroll
        for (int j = 0; j < 2; j++) {
            int idx = tid + j * 512;
            int row = idx >> 2, c = idx & 3;
            uint32_t so = (uint32_t)(row * (PITCH * 2) + c * 16);
            size_t go = (size_t)row * K + k0 + c * 8;
            cp16(sb + OFF_WH + so, Wbh + go);
            cp16(sb + OFF_WL + so, Wbl + go);
        }
    };

    prefetch(0, 0);
    CP_COMMIT();
    prefetch(1, 1);
    CP_COMMIT();

    int stg = 0;
    for (int kt = 0; kt < nchunks; kt++) {
        if (kt + 1 < nchunks) { CP_WAIT1(); } else { CP_WAIT0(); }
        __syncthreads();

        if (kt + 2 < nchunks) {
            int ns = stg + 2; if (ns >= 3) ns -= 3;
            prefetch(kt + 2, ns);
            CP_COMMIT();
        }

        const uint32_t sb = sbase + stg * STAGE_B;
        const uint32_t uAh = sb, uAl = sb + OFF_AL;
        const uint32_t uWh = sb + OFF_WH, uWl = sb + OFF_WL;

#pragma unroll
        for (int ks = 0; ks < 2; ks++) {
            const int kb = ks * 32;

            uint32_t aH[4][4], aL[4][4];
#pragma unroll
            for (int mt = 0; mt < 4; mt++) {
                ldsm4(aH[mt], uAh + aoff + mt * 16 * (PITCH * 2) + kb);
                ldsm4(aL[mt], uAl + aoff + mt * 16 * (PITCH * 2) + kb);
            }
#pragma unroll
            for (int np = 0; np < 2; np++) {       // 2 n16 groups -> 4 n8 tiles
                uint32_t bH[4], bL[4];
                ldsm4(bH, uWh + boff + np * 16 * (PITCH * 2) + kb);
                ldsm4(bL, uWl + boff + np * 16 * (PITCH * 2) + kb);
                // 3 terms x 4 mt x 2 n8 = 24 MMAs; acc reuse distance 8
#pragma unroll
                for (int mt = 0; mt < 4; mt++) {
                    mma16816(acc[mt][2 * np],     aH[mt], bH);
                    mma16816(acc[mt][2 * np + 1], aH[mt], bH + 2);
                }
#pragma unroll
                for (int mt = 0; mt < 4; mt++) {
                    mma16816(acc[mt][2 * np],     aH[mt], bL);
                    mma16816(acc[mt][2 * np + 1], aH[mt], bL + 2);
                }
#pragma unroll
                for (int mt = 0; mt < 4; mt++) {
                    mma16816(acc[mt][2 * np],     aL[mt], bH);
                    mma16816(acc[mt][2 * np + 1], aL[mt], bH + 2);
                }
            }
        }
        if (++stg >= 3) stg = 0;
    }

    // Epilogue
    const int g = lane >> 2, tg = lane & 3;
#pragma unroll
    for (int nt = 0; nt < 4; nt++) {
        const int ncol = warp_n + nt * 8 + tg * 2;
        const float b0 = biasz[n0 + ncol], b1 = biasz[n0 + ncol + 1];
#pragma unroll
        for (int mt = 0; mt < 4; mt++) {
            const int r0 = m0 + warp_m + mt * 16 + g;
#pragma unroll
            for (int hh = 0; hh < 2; hh++) {
                const int r = r0 + hh * 8;
                const float v0 = acc[mt][nt][2 * hh] + b0;
                const float v1 = acc[mt][nt][2 * hh + 1] + b1;
                const size_t idx = (size_t)r * ldc + ccol0 + n0 + ncol;
                if (C) {
                    float2 o; o.x = v0; o.y = v1;
                    *(float2*)(C + idx) = o;
                } else {
                    *(uint32_t*)(Ch + idx) = pack_hi(v0, v1);
                    *(uint32_t*)(Cl + idx) = pack_lo(v0, v1);
                }
            }
        }
    }
}

// ---------------------------------------------------------------------------
// Flash attention body (branch 2 of packed qkv). 128 threads. (Unchanged.)
// ---------------------------------------------------------------------------
#define FPITCH 72
#define FTILE_B (64 * FPITCH * 2)         // 9216 bytes per tile
#define FSTAGE_B (4 * FTILE_B)            // 36864 bytes per stage (Kh,Kl,Vh,Vl)
#define FLASH_SMEM (2 * FSTAGE_B)         // 73728 bytes

__device__ void flash_body(
    const __nv_bfloat16* __restrict__ qh, const __nv_bfloat16* __restrict__ ql,
    __nv_bfloat16* __restrict__ atth, __nv_bfloat16* __restrict__ attl,
    __nv_bfloat16* fsm)
{
    const uint32_t sbase = smem_u32(fsm);

    const int tid = threadIdx.x;
    const int warp = tid >> 5, lane = tid & 31;
    const int g = lane >> 2, t = lane & 3;
    const int q0 = blockIdx.x * 64;
    const int b = blockIdx.y >> 3, h = blockIdx.y & 7;

    const size_t rowQ0 = (size_t)(b * SS + q0 + warp * 16 + g) * QP + 2 * D3 + h * HD;
    const size_t rowQ1 = rowQ0 + (size_t)8 * QP;
    uint32_t qH[4][4], qL[4][4];
#pragma unroll
    for (int ks = 0; ks < 4; ks++) {
        const int c = ks * 16 + 2 * t;
        qH[ks][0] = *(const uint32_t*)(qh + rowQ0 + c);
        qH[ks][1] = *(const uint32_t*)(qh + rowQ1 + c);
        qH[ks][2] = *(const uint32_t*)(qh + rowQ0 + c + 8);
        qH[ks][3] = *(const uint32_t*)(qh + rowQ1 + c + 8);
        qL[ks][0] = *(const uint32_t*)(ql + rowQ0 + c);
        qL[ks][1] = *(const uint32_t*)(ql + rowQ1 + c);
        qL[ks][2] = *(const uint32_t*)(ql + rowQ0 + c + 8);
        qL[ks][3] = *(const uint32_t*)(ql + rowQ1 + c + 8);
    }

    const int bm = lane >> 3;
    const int kboff = ((lane & 7) + ((bm >> 1) << 3)) * (FPITCH * 2) + ((bm & 1) << 3) * 2;
    const int vboff = ((lane & 7) + ((bm & 1) << 3)) * (FPITCH * 2) + (lane >> 4) * 16;

    float o[8][4];
    float mrow[2], lrow[2];
#pragma unroll
    for (int nt = 0; nt < 8; nt++)
#pragma unroll
        for (int i = 0; i < 4; i++) o[nt][i] = 0.0f;
    mrow[0] = mrow[1] = -1e30f;
    lrow[0] = lrow[1] = 0.0f;

    const size_t kvbase = (size_t)(b * SS) * QP + 2 * D3 + h * HD;

    auto prefetch_kv = [&](int kt, int stg) {
        const size_t tb = kvbase + (size_t)(kt * 64) * QP;
        const uint32_t sb = sbase + stg * FSTAGE_B;
#pragma unroll
        for (int l = 0; l < 4; l++) {
            int idx = tid + l * 128;
            int r = idx >> 3, c4 = idx & 7;
            size_t gsrc = tb + (size_t)r * QP + c4 * 8;
            uint32_t sdst = (uint32_t)(r * (FPITCH * 2) + c4 * 16);
            cp16(sb + sdst,               qh + gsrc + 512);
            cp16(sb + FTILE_B + sdst,     ql + gsrc + 512);
            cp16(sb + 2 * FTILE_B + sdst, qh + gsrc + 1024);
            cp16(sb + 3 * FTILE_B + sdst, ql + gsrc + 1024);
        }
    };

    prefetch_kv(0, 0);
    CP_COMMIT();

    for (int kt = 0; kt < 16; kt++) {
        if (kt + 1 < 16) {
            prefetch_kv(kt + 1, (kt + 1) & 1);
            CP_COMMIT();
            CP_WAIT1();
        } else {
            CP_WAIT0();
        }
        __syncthreads();

        const uint32_t sb = sbase + (kt & 1) * FSTAGE_B;
        const uint32_t uKh = sb, uKl = sb + FTILE_B;
        const uint32_t uVh = sb + 2 * FTILE_B, uVl = sb + 3 * FTILE_B;

        float s[8][4];
#pragma unroll
        for (int nt = 0; nt < 8; nt++)
#pragma unroll
            for (int i = 0; i < 4; i++) s[nt][i] = 0.0f;

#pragma unroll
        for (int ks = 0; ks < 4; ks++) {
            const int kb = ks * 32;
            uint32_t kh[4][4], kl[4][4];
#pragma unroll
            for (int np = 0; np < 4; np++) {
                ldsm4(kh[np], uKh + kboff + np * 16 * (FPITCH * 2) + kb);
                ldsm4(kl[np], uKl + kboff + np * 16 * (FPITCH * 2) + kb);
            }
#pragma unroll
            for (int np = 0; np < 4; np++) {
                mma16816(s[2 * np],     qH[ks], kh[np]);
                mma16816(s[2 * np + 1], qH[ks], kh[np] + 2);
            }
#pragma unroll
            for (int np = 0; np < 4; np++) {
                mma16816(s[2 * np],     qH[ks], kl[np]);
                mma16816(s[2 * np + 1], qH[ks], kl[np] + 2);
            }
#pragma unroll
            for (int np = 0; np < 4; np++) {
                mma16816(s[2 * np],     qL[ks], kh[np]);
                mma16816(s[2 * np + 1], qL[ks], kh[np] + 2);
            }
        }

#pragma unroll
        for (int r = 0; r < 2; r++) {
            float mx = -1e30f;
#pragma unroll
            for (int nt = 0; nt < 8; nt++) {
                s[nt][2 * r]     *= 0.125f;
                s[nt][2 * r + 1] *= 0.125f;
                mx = fmaxf(mx, fmaxf(s[nt][2 * r], s[nt][2 * r + 1]));
            }
            mx = fmaxf(mx, __shfl_xor_sync(0xffffffffu, mx, 1));
            mx = fmaxf(mx, __shfl_xor_sync(0xffffffffu, mx, 2));
            float mnew = fmaxf(mrow[r], mx);
            float alpha = __expf(mrow[r] - mnew);
            float ls = 0.0f;
#pragma unroll
            for (int nt = 0; nt < 8; nt++) {
                float p0 = __expf(s[nt][2 * r] - mnew);
                float p1 = __expf(s[nt][2 * r + 1] - mnew);
                s[nt][2 * r] = p0; s[nt][2 * r + 1] = p1;
                ls += p0 + p1;
            }
            ls += __shfl_xor_sync(0xffffffffu, ls, 1);
            ls += __shfl_xor_sync(0xffffffffu, ls, 2);
            lrow[r] = lrow[r] * alpha + ls;
            mrow[r] = mnew;
#pragma unroll
            for (int nt = 0; nt < 8; nt++) {
                o[nt][2 * r] *= alpha; o[nt][2 * r + 1] *= alpha;
            }
        }

        uint32_t pH[4][4], pL[4][4];
#pragma unroll
        for (int j = 0; j < 4; j++) {
            pH[j][0] = pack_hi(s[2 * j][0], s[2 * j][1]);
            pH[j][1] = pack_hi(s[2 * j][2], s[2 * j][3]);
            pH[j][2] = pack_hi(s[2 * j + 1][0], s[2 * j + 1][1]);
            pH[j][3] = pack_hi(s[2 * j + 1][2], s[2 * j + 1][3]);
            pL[j][0] = pack_lo(s[2 * j][0], s[2 * j][1]);
            pL[j][1] = pack_lo(s[2 * j][2], s[2 * j][3]);
            pL[j][2] = pack_lo(s[2 * j + 1][0], s[2 * j + 1][1]);
            pL[j][3] = pack_lo(s[2 * j + 1][2], s[2 * j + 1][3]);
        }

#pragma unroll
        for (int j = 0; j < 4; j++) {
            const int rb = j * 16 * (FPITCH * 2);
            uint32_t vh[4][4], vl[4][4];
#pragma unroll
            for (int np = 0; np < 4; np++) {
                ldsm4t(vh[np], uVh + vboff + rb + np * 32);
                ldsm4t(vl[np], uVl + vboff + rb + np * 32);
            }
#pragma unroll
            for (int np = 0; np < 4; np++) {
                mma16816(o[2 * np],     pH[j], vh[np]);
                mma16816(o[2 * np + 1], pH[j], vh[np] + 2);
            }
#pragma unroll
            for (int np = 0; np < 4; np++) {
                mma16816(o[2 * np],     pH[j], vl[np]);
                mma16816(o[2 * np + 1], pH[j], vl[np] + 2);
            }
#pragma unroll
            for (int np = 0; np < 4; np++) {
                mma16816(o[2 * np],     pL[j], vh[np]);
                mma16816(o[2 * np + 1], pL[j], vh[np] + 2);
            }
        }
        __syncthreads();
    }

    const float inv0 = 1.0f / lrow[0], inv1 = 1.0f / lrow[1];
    const size_t orow0 = (size_t)(b * SS + q0 + warp * 16 + g) * OP + 2 * DD + h * HD;
    const size_t orow1 = orow0 + (size_t)8 * OP;
#pragma unroll
    for (int nt = 0; nt < 8; nt++) {
        const int c = nt * 8 + 2 * t;
        const float a0 = o[nt][0] * inv0, a1 = o[nt][1] * inv0;
        const float b0 = o[nt][2] * inv1, b1 = o[nt][3] * inv1;
        *(uint32_t*)(atth + orow0 + c) = pack_hi(a0, a1);
        *(uint32_t*)(attl + orow0 + c) = pack_lo(a0, a1);
        *(uint32_t*)(atth + orow1 + c) = pack_hi(b0, b1);
        *(uint32_t*)(attl + orow1 + c) = pack_lo(b0, b1);
    }
}

// ---------------------------------------------------------------------------
// Windowed causal attention body, fully coalesced (unchanged)
// ---------------------------------------------------------------------------
#define WQS 0
#define WKS (64 * 65)
#define WVS (WKS + 80 * 65)

template <int W>
__device__ __forceinline__ void window_body(
    const __nv_bfloat16* __restrict__ qh, const __nv_bfloat16* __restrict__ ql,
    __nv_bfloat16* __restrict__ atth, __nv_bfloat16* __restrict__ attl,
    float* wsm, int br)
{
    float* Qs = wsm + WQS;
    float* Ks = wsm + WKS;
    float* Vs = wsm + WVS;

    const int tid = threadIdx.x;
    const int q0 = blockIdx.x * 64;
    const int bh = blockIdx.y;
    const int b = bh >> 3, h = bh & 7;
    const size_t base = (size_t)b * SS * QP + (size_t)br * D3 + h * HD;

    for (int e8 = tid; e8 < 64 * 8; e8 += 128) {
        int r = e8 >> 3, c8 = e8 & 7;
        size_t src = base + (size_t)(q0 + r) * QP + c8 * 8;
        uint4 xh4 = *(const uint4*)(qh + src);
        uint4 xl4 = *(const uint4*)(ql + src);
        float* qd = Qs + r * 65 + c8 * 8;
        float2 f;
        f = bf2sum(xh4.x, xl4.x); qd[0] = f.x; qd[1] = f.y;
        f = bf2sum(xh4.y, xl4.y); qd[2] = f.x; qd[3] = f.y;
        f = bf2sum(xh4.z, xl4.z); qd[4] = f.x; qd[5] = f.y;
        f = bf2sum(xh4.w, xl4.w); qd[6] = f.x; qd[7] = f.y;
    }
    for (int e8 = tid; e8 < 80 * 8; e8 += 128) {
        int r = e8 >> 3, c8 = e8 & 7;
        int s = q0 - 16 + r;
        if (s >= 0) {
            size_t src = base + (size_t)s * QP + c8 * 8;
            uint4 kh = *(const uint4*)(qh + src + 512);
            uint4 kl = *(const uint4*)(ql + src + 512);
            uint4 vh = *(const uint4*)(qh + src + 1024);
            uint4 vl = *(const uint4*)(ql + src + 1024);
            float* kd = Ks + r * 65 + c8 * 8;
            float* vd = Vs + r * 65 + c8 * 8;
            float2 f;
            f = bf2sum(kh.x, kl.x); kd[0] = f.x; kd[1] = f.y;
            f = bf2sum(kh.y, kl.y); kd[2] = f.x; kd[3] = f.y;
            f = bf2sum(kh.z, kl.z); kd[4] = f.x; kd[5] = f.y;
            f = bf2sum(kh.w, kl.w); kd[6] = f.x; kd[7] = f.y;
            f = bf2sum(vh.x, vl.x); vd[0] = f.x; vd[1] = f.y;
            f = bf2sum(vh.y, vl.y); vd[2] = f.x; vd[3] = f.y;
            f = bf2sum(vh.z, vl.z); vd[4] = f.x; vd[5] = f.y;
            f = bf2sum(vh.w, vl.w); vd[6] = f.x; vd[7] = f.y;
        }
    }
    __syncthreads();

    const int qlid = tid >> 1;
    const int half = tid & 1;
    const int q = q0 + qlid;

    float qreg[32];
#pragma unroll
    for (int dd = 0; dd < 32; dd++)
        qreg[dd] = Qs[qlid * 65 + 2 * dd + half] * 0.125f;
    __syncthreads();

    float sc[W];
    float m = -1e30f;
#pragma unroll
    for (int w = 0; w < W; w++) {
        int k = q - w;
        int kr = qlid + 16 - w;
        float dot = 0.0f;
        if (k >= 0) {
#pragma unroll
            for (int dd = 0; dd < 32; dd++)
                dot += qreg[dd] * Ks[kr * 65 + 2 * dd + half];
        }
        dot += __shfl_xor_sync(0xffffffffu, dot, 1);
        sc[w] = (k >= 0) ? dot : -1e30f;
        m = fmaxf(m, sc[w]);
    }

    float l = 0.0f;
    float p[W];
#pragma unroll
    for (int w = 0; w < W; w++) {
        p[w] = (q - w >= 0) ? __expf(sc[w] - m) : 0.0f;
        l += p[w];
    }

    float o[32];
#pragma unroll
    for (int dd = 0; dd < 32; dd++) o[dd] = 0.0f;
#pragma unroll
    for (int w = 0; w < W; w++) {
        int k = q - w;
        if (k >= 0) {
            int kr = qlid + 16 - w;
#pragma unroll
            for (int dd = 0; dd < 32; dd++)
                o[dd] += p[w] * Vs[kr * 65 + 2 * dd + half];
        }
    }

    float inv = 1.0f / l;
#pragma unroll
    for (int dd = 0; dd < 32; dd++)
        Qs[qlid * 65 + 2 * dd + half] = o[dd] * inv;
    __syncthreads();

    const size_t obase = (size_t)(b * SS + q0) * OP + (size_t)br * DD + h * HD;
    for (int e8 = tid; e8 < 64 * 8; e8 += 128) {
        int r = e8 >> 3, c8 = e8 & 7;
        const float* row = Qs + r * 65 + c8 * 8;
        uint4 hv, lv;
        hv.x = pack_hi(row[0], row[1]); lv.x = pack_lo(row[0], row[1]);
        hv.y = pack_hi(row[2], row[3]); lv.y = pack_lo(row[2], row[3]);
        hv.z = pack_hi(row[4], row[5]); lv.z = pack_lo(row[4], row[5]);
        hv.w = pack_hi(row[6], row[7]); lv.w = pack_lo(row[6], row[7]);
        size_t drow = obase + (size_t)r * OP + c8 * 8;
        *(uint4*)(atth + drow) = hv;
        *(uint4*)(attl + drow) = lv;
    }
}

// ---------------------------------------------------------------------------
// Unified attention kernel: z=0 window<5>, z=1 window<10>, z=2 flash.
// ---------------------------------------------------------------------------
#define ATTN_SMEM FLASH_SMEM

__global__ __launch_bounds__(128) void attn_kernel(
    const __nv_bfloat16* __restrict__ qh, const __nv_bfloat16* __restrict__ ql,
    __nv_bfloat16* __restrict__ atth, __nv_bfloat16* __restrict__ attl)
{
    extern __shared__ char asmem[];
    if (blockIdx.z == 2) {
        flash_body(qh, ql, atth, attl, reinterpret_cast<__nv_bfloat16*>(asmem));
    } else if (blockIdx.z == 0) {
        window_body<5>(qh, ql, atth, attl, reinterpret_cast<float*>(asmem), 0);
    } else {
        window_body<10>(qh, ql, atth, attl, reinterpret_cast<float*>(asmem), 1);
    }
}

// ---------------------------------------------------------------------------
// Launch
// ---------------------------------------------------------------------------
extern "C" void kernel_launch(void* const* d_in, const int* in_sizes, int n_in,
                              void* d_out, int out_size)
{
    const float* x    = (const float*)d_in[0];   // [16,1024,512]
    const float* Wqkv = (const float*)d_in[1];   // [3,1536,512] = [4608,512]
    const float* bqkv = (const float*)d_in[2];   // [4608]
    const float* Wo   = (const float*)d_in[3];   // [3,512,512]
    const float* bo   = (const float*)d_in[4];   // [3,512]
    const float* Wf   = (const float*)d_in[5];   // [512,1536]
    const float* bf   = (const float*)d_in[6];   // [512]
    float* out = (float*)d_out;

    __nv_bfloat16 *xh, *xl, *qkvh, *qkvl, *atth, *attl, *combh, *combl;
    __nv_bfloat16 *Wqkvh, *Wqkvl, *Woh, *Wol, *Wfh, *Wfl;
    cudaGetSymbolAddress((void**)&xh, g_xh);
    cudaGetSymbolAddress((void**)&xl, g_xl);
    cudaGetSymbolAddress((void**)&qkvh, g_qkvh);
    cudaGetSymbolAddress((void**)&qkvl, g_qkvl);
    cudaGetSymbolAddress((void**)&atth, g_atth);
    cudaGetSymbolAddress((void**)&attl, g_attl);
    cudaGetSymbolAddress((void**)&combh, g_combh);
    cudaGetSymbolAddress((void**)&combl, g_combl);
    cudaGetSymbolAddress((void**)&Wqkvh, g_Wqkvh);
    cudaGetSymbolAddress((void**)&Wqkvl, g_Wqkvl);
    cudaGetSymbolAddress((void**)&Woh, g_Woh);
    cudaGetSymbolAddress((void**)&Wol, g_Wol);
    cudaGetSymbolAddress((void**)&Wfh, g_Wfh);
    cudaGetSymbolAddress((void**)&Wfl, g_Wfl);

    cudaFuncSetAttribute(gemm_bf16_kernel,
                         cudaFuncAttributeMaxDynamicSharedMemorySize, GEMM_SMEM);
    cudaFuncSetAttribute(attn_kernel,
                         cudaFuncAttributeMaxDynamicSharedMemorySize, ATTN_SMEM);

    // Conversions
    {
        int n4;
        n4 = MM * DD / 4;
        convert_hilo_kernel<<<(n4 + 255) / 256, 256>>>(x, xh, xl, n4);
        n4 = 3 * D3 * DD / 4;
        convert_hilo_kernel<<<(n4 + 255) / 256, 256>>>(Wqkv, Wqkvh, Wqkvl, n4);
        n4 = 3 * DD * DD / 4;
        convert_hilo_kernel<<<(n4 + 255) / 256, 256>>>(Wo, Woh, Wol, n4);
        n4 = DD * D3 / 4;
        convert_hilo_kernel<<<(n4 + 255) / 256, 256>>>(Wf, Wfh, Wfl, n4);
    }

    // 1) All three QKV projections as one GEMM
    {
        dim3 grid(QP / 256, MM / 128, 1);
        gemm_bf16_kernel<<<grid, 512, GEMM_SMEM>>>(
            xh, xl, Wqkvh, Wqkvl, bqkv, nullptr, qkvh, qkvl,
            DD, DD, QP, 0, 0, 0, 0, 0);
    }

    // 2) Attention: windows + flash in ONE launch (z=0,1 windows; z=2 flash)
    {
        dim3 agrid(SS / 64, BB * HH, 3);
        attn_kernel<<<agrid, 128, ATTN_SMEM>>>(qkvh, qkvl, atth, attl);
    }

    // 3) Batched out-projections
    {
        dim3 grid(DD / 256, MM / 128, 3);
        gemm_bf16_kernel<<<grid, 512, GEMM_SMEM>>>(
            atth, attl, Woh, Wol, bo, nullptr, combh, combl,
            DD, OP, OP, 0, DD, DD * DD, DD, DD);
    }

    // 4) Final projection (fp32 out)
    {
        dim3 grid(DD / 256, MM / 128, 1);
        gemm_bf16_kernel<<<grid, 512, GEMM_SMEM>>>(
            combh, combl, Wfh, Wfl, bf, out, nullptr, nullptr,
            D3, D3, DD, 0, 0, 0, 0, 0);
    }
}

// round 17
// speedup vs baseline: 4.7469x; 1.1413x over previous
#include <cuda_runtime.h>
#include <cuda_fp16.h>
#include <cstdint>
#include <math.h>

// Problem constants
#define BB 16
#define SS 1024
#define DD 512
#define HH 8
#define HD 64
#define MM (BB * SS)          // 16384 rows
#define D3 (3 * DD)           // 1536
#define QP (3 * D3)           // 4608 packed qkv width (3 branches)
#define OP D3                 // 1536 att/comb width

// fp16 merged-correction constants (Ootomo-Yokota style), gamma = 1/64
#define GAM   0.015625f
#define IGAM  64.0f
#define OSCALE (1.0f / 1.015625f)

// ---------------------------------------------------------------------------
// Scratch (static device globals; no runtime allocation allowed)
// fp16 (h, c) pairs. A-role: c = fp16((x-h) + gam*h). B-role: c = fp16(h + (x-h)/gam).
// ---------------------------------------------------------------------------
__device__ __half g_xh[(size_t)MM * DD],   g_xc[(size_t)MM * DD];
__device__ __half g_qkvh[(size_t)MM * QP], g_qkvc[(size_t)MM * QP];
__device__ __half g_atth[(size_t)MM * OP], g_attc[(size_t)MM * OP];
__device__ __half g_combh[(size_t)MM * OP], g_combc[(size_t)MM * OP];
__device__ __half g_Wqkvh[(size_t)3 * D3 * DD], g_Wqkvc[(size_t)3 * D3 * DD];
__device__ __half g_Woh[(size_t)3 * DD * DD],   g_Woc[(size_t)3 * DD * DD];
__device__ __half g_Wfh[(size_t)DD * D3],   g_Wfc[(size_t)DD * D3];

// ---------------------------------------------------------------------------
// Helpers (base sm_80+ PTX only — NO 'a'-suffix features)
// ---------------------------------------------------------------------------
__device__ __forceinline__ uint32_t smem_u32(const void* p) {
    uint32_t a;
    asm("{ .reg .u64 t; cvta.to.shared.u64 t, %1; cvt.u32.u64 %0, t; }" : "=r"(a) : "l"(p));
    return a;
}
__device__ __forceinline__ void ldsm4(uint32_t* r, uint32_t addr) {
    asm volatile("ldmatrix.sync.aligned.m8n8.x4.shared.b16 {%0,%1,%2,%3}, [%4];"
                 : "=r"(r[0]), "=r"(r[1]), "=r"(r[2]), "=r"(r[3]) : "r"(addr));
}
__device__ __forceinline__ void ldsm4t(uint32_t* r, uint32_t addr) {
    asm volatile("ldmatrix.sync.aligned.m8n8.x4.trans.shared.b16 {%0,%1,%2,%3}, [%4];"
                 : "=r"(r[0]), "=r"(r[1]), "=r"(r[2]), "=r"(r[3]) : "r"(addr));
}
__device__ __forceinline__ void mma16816(float* c, const uint32_t* a, const uint32_t* b) {
    asm volatile("mma.sync.aligned.m16n8k16.row.col.f32.f16.f16.f32 "
                 "{%0,%1,%2,%3}, {%4,%5,%6,%7}, {%8,%9}, {%0,%1,%2,%3};"
                 : "+f"(c[0]), "+f"(c[1]), "+f"(c[2]), "+f"(c[3])
                 : "r"(a[0]), "r"(a[1]), "r"(a[2]), "r"(a[3]), "r"(b[0]), "r"(b[1]));
}
__device__ __forceinline__ void cp16(uint32_t saddr, const void* g) {
    asm volatile("cp.async.cg.shared.global [%0], [%1], 16;" :: "r"(saddr), "l"(g));
}
#define CP_COMMIT() asm volatile("cp.async.commit_group;" ::: "memory")
#define CP_WAIT1()  asm volatile("cp.async.wait_group 1;" ::: "memory")
#define CP_WAIT0()  asm volatile("cp.async.wait_group 0;" ::: "memory")

__device__ __forceinline__ uint32_t pack_h(float x, float y) {
    __half2 r = __floats2half2_rn(x, y);
    return *reinterpret_cast<uint32_t*>(&r);
}
__device__ __forceinline__ uint32_t pack_cA(float x, float y) {
    float hx = __half2float(__float2half_rn(x));
    float hy = __half2float(__float2half_rn(y));
    return pack_h((x - hx) + GAM * hx, (y - hy) + GAM * hy);
}
__device__ __forceinline__ uint32_t pack_cB(float x, float y) {
    float hx = __half2float(__float2half_rn(x));
    float hy = __half2float(__float2half_rn(y));
    return pack_h(hx + IGAM * (x - hx), hy + IGAM * (y - hy));
}
__device__ __forceinline__ float2 recA(uint32_t h, uint32_t c) {
    float2 hf = __half22float2(*reinterpret_cast<__half2*>(&h));
    float2 cf = __half22float2(*reinterpret_cast<__half2*>(&c));
    return make_float2((1.0f - GAM) * hf.x + cf.x, (1.0f - GAM) * hf.y + cf.y);
}
__device__ __forceinline__ float2 recB(uint32_t h, uint32_t c) {
    float2 hf = __half22float2(*reinterpret_cast<__half2*>(&h));
    float2 cf = __half22float2(*reinterpret_cast<__half2*>(&c));
    return make_float2((1.0f - GAM) * hf.x + GAM * cf.x, (1.0f - GAM) * hf.y + GAM * cf.y);
}

// ---------------------------------------------------------------------------
// fp32 -> fp16 (h, c) conversion; roleB selects B-role correction
// ---------------------------------------------------------------------------
__global__ __launch_bounds__(256) void convert_hc_kernel(
    const float* __restrict__ src, __half* __restrict__ h,
    __half* __restrict__ c, int n4, int roleB)
{
    int i = blockIdx.x * blockDim.x + threadIdx.x;
    if (i < n4) {
        float4 v = *(const float4*)(src + (size_t)i * 4);
        uint2 ph, pc;
        ph.x = pack_h(v.x, v.y); ph.y = pack_h(v.z, v.w);
        if (roleB) { pc.x = pack_cB(v.x, v.y); pc.y = pack_cB(v.z, v.w); }
        else       { pc.x = pack_cA(v.x, v.y); pc.y = pack_cA(v.z, v.w); }
        *(uint2*)(h + (size_t)i * 4) = ph;
        *(uint2*)(c + (size_t)i * 4) = pc;
    }
}

// ---------------------------------------------------------------------------
// HMMA GEMM, fp16 merged-correction 2-term, batched over blockIdx.z.
// acc = sum_k (Ah*Wh + Ac*Wc); true C = acc*OSCALE + bias.
// Block tile 128x256, KC=32, 512 threads = 16 warps = 2(m) x 8(n),
// warp tile 64x32. 3-stage cp.async pipeline.
// ---------------------------------------------------------------------------
#define KC 32
#define PITCH 40                         // fp16 per smem row (80 B)
#define A_EL (128 * PITCH)
#define W_EL (256 * PITCH)
#define OFF_AC (A_EL * 2)
#define OFF_WH (A_EL * 4)
#define OFF_WC (A_EL * 4 + W_EL * 2)
#define STAGE_B ((A_EL * 2 + W_EL * 2) * 2)   // 61440 bytes per stage
#define GEMM_SMEM (3 * STAGE_B)               // 184320 bytes

__global__ __launch_bounds__(512, 1) void gemm_fp16_kernel(
    const __half* __restrict__ Ah, const __half* __restrict__ Ac,
    const __half* __restrict__ Wh, const __half* __restrict__ Wc,
    const float* __restrict__ bias, float* __restrict__ C,
    __half* __restrict__ Ch, __half* __restrict__ Cc,
    int K, int lda, int ldc, int col0,
    int aColZ, int wZ, int biasZ, int cColZ, int qkvRole)
{
    extern __shared__ __half smem[];
    const uint32_t sbase = smem_u32(smem);

    const int tid = threadIdx.x;
    const int wid = tid >> 5, lane = tid & 31;
    const int z = blockIdx.z;
    const int m0 = blockIdx.y * 128;
    const int n0 = blockIdx.x * 256;
    const int warp_m = (wid & 1) * 64;
    const int warp_n = (wid >> 1) * 32;

    const __half* Abh = Ah + (size_t)m0 * lda + (size_t)z * aColZ;
    const __half* Abc = Ac + (size_t)m0 * lda + (size_t)z * aColZ;
    const __half* Wbh = Wh + (size_t)z * wZ + (size_t)n0 * K;
    const __half* Wbc = Wc + (size_t)z * wZ + (size_t)n0 * K;
    const float* biasz = bias + (size_t)z * biasZ;
    const int ccol0 = col0 + z * cColZ;

    const int aoff = (warp_m + (lane & 15)) * (PITCH * 2) + (((lane >> 4) << 3) << 1);
    const int bm = lane >> 3;
    const int boff = (warp_n + (lane & 7) + ((bm >> 1) << 3)) * (PITCH * 2) + (((bm & 1) << 3) << 1);

    float acc[4][4][4];
#pragma unroll
    for (int mt = 0; mt < 4; mt++)
#pragma unroll
        for (int nt = 0; nt < 4; nt++)
#pragma unroll
            for (int i = 0; i < 4; i++) acc[mt][nt][i] = 0.0f;

    const int nchunks = K / KC;

    auto prefetch = [&](int kt, int stg) {
        const int k0 = kt * KC;
        const uint32_t sb = sbase + stg * STAGE_B;
        {
            int row = tid >> 2, c = tid & 3;
            uint32_t so = (uint32_t)(row * (PITCH * 2) + c * 16);
            size_t go = (size_t)row * lda + k0 + c * 8;
            cp16(sb + so,          Abh + go);
            cp16(sb + OFF_AC + so, Abc + go);
        }
#pragma unroll
        for (int j = 0; j < 2; j++) {
            int idx = tid + j * 512;
            int row = idx >> 2, c = idx & 3;
            uint32_t so = (uint32_t)(row * (PITCH * 2) + c * 16);
            size_t go = (size_t)row * K + k0 + c * 8;
            cp16(sb + OFF_WH + so, Wbh + go);
            cp16(sb + OFF_WC + so, Wbc + go);
        }
    };

    prefetch(0, 0);
    CP_COMMIT();
    prefetch(1, 1);
    CP_COMMIT();

    int stg = 0;
    for (int kt = 0; kt < nchunks; kt++) {
        if (kt + 1 < nchunks) { CP_WAIT1(); } else { CP_WAIT0(); }
        __syncthreads();

        if (kt + 2 < nchunks) {
            int ns = stg + 2; if (ns >= 3) ns -= 3;
            prefetch(kt + 2, ns);
            CP_COMMIT();
        }

        const uint32_t sb = sbase + stg * STAGE_B;
        const uint32_t uAh = sb, uAc = sb + OFF_AC;
        const uint32_t uWh = sb + OFF_WH, uWc = sb + OFF_WC;

#pragma unroll
        for (int ks = 0; ks < 2; ks++) {
            const int kb = ks * 32;

            uint32_t aH[4][4], aC[4][4];
#pragma unroll
            for (int mt = 0; mt < 4; mt++) {
                ldsm4(aH[mt], uAh + aoff + mt * 16 * (PITCH * 2) + kb);
                ldsm4(aC[mt], uAc + aoff + mt * 16 * (PITCH * 2) + kb);
            }
#pragma unroll
            for (int np = 0; np < 2; np++) {
                uint32_t bH[4], bC[4];
                ldsm4(bH, uWh + boff + np * 16 * (PITCH * 2) + kb);
                ldsm4(bC, uWc + boff + np * 16 * (PITCH * 2) + kb);
#pragma unroll
                for (int mt = 0; mt < 4; mt++) {
                    mma16816(acc[mt][2 * np],     aH[mt], bH);
                    mma16816(acc[mt][2 * np + 1], aH[mt], bH + 2);
                }
#pragma unroll
                for (int mt = 0; mt < 4; mt++) {
                    mma16816(acc[mt][2 * np],     aC[mt], bC);
                    mma16816(acc[mt][2 * np + 1], aC[mt], bC + 2);
                }
            }
        }
        if (++stg >= 3) stg = 0;
    }

    // Epilogue: true value = acc*OSCALE + bias; role-baked fp16 output
    const int g = lane >> 2, tg = lane & 3;
#pragma unroll
    for (int nt = 0; nt < 4; nt++) {
        const int ncol = warp_n + nt * 8 + tg * 2;
        const float b0 = biasz[n0 + ncol], b1 = biasz[n0 + ncol + 1];
        int rc = (ccol0 + n0 + ncol) % D3;
        const bool isA = (!qkvRole) || (rc < DD);
#pragma unroll
        for (int mt = 0; mt < 4; mt++) {
            const int r0 = m0 + warp_m + mt * 16 + g;
#pragma unroll
            for (int hh = 0; hh < 2; hh++) {
                const int r = r0 + hh * 8;
                const float v0 = acc[mt][nt][2 * hh] * OSCALE + b0;
                const float v1 = acc[mt][nt][2 * hh + 1] * OSCALE + b1;
                const size_t idx = (size_t)r * ldc + ccol0 + n0 + ncol;
                if (C) {
                    float2 o; o.x = v0; o.y = v1;
                    *(float2*)(C + idx) = o;
                } else {
                    *(uint32_t*)(Ch + idx) = pack_h(v0, v1);
                    *(uint32_t*)(Cc + idx) = isA ? pack_cA(v0, v1) : pack_cB(v0, v1);
                }
            }
        }
    }
}

// ---------------------------------------------------------------------------
// Flash attention body (branch 2 of packed qkv). 128 threads.
// 2-stage cp.async K/V staging; fp16 merged-correction 2-term MMAs.
// ---------------------------------------------------------------------------
#define FPITCH 72
#define FTILE_B (64 * FPITCH * 2)
#define FSTAGE_B (4 * FTILE_B)
#define FLASH_SMEM (2 * FSTAGE_B)         // 73728 bytes

__device__ void flash_body(
    const __half* __restrict__ qh, const __half* __restrict__ qc,
    __half* __restrict__ atth, __half* __restrict__ attc,
    __half* fsm)
{
    const uint32_t sbase = smem_u32(fsm);

    const int tid = threadIdx.x;
    const int warp = tid >> 5, lane = tid & 31;
    const int g = lane >> 2, t = lane & 3;
    const int q0 = blockIdx.x * 64;
    const int b = blockIdx.y >> 3, h = blockIdx.y & 7;

    const size_t rowQ0 = (size_t)(b * SS + q0 + warp * 16 + g) * QP + 2 * D3 + h * HD;
    const size_t rowQ1 = rowQ0 + (size_t)8 * QP;
    uint32_t qH[4][4], qC[4][4];
#pragma unroll
    for (int ks = 0; ks < 4; ks++) {
        const int c = ks * 16 + 2 * t;
        qH[ks][0] = *(const uint32_t*)(qh + rowQ0 + c);
        qH[ks][1] = *(const uint32_t*)(qh + rowQ1 + c);
        qH[ks][2] = *(const uint32_t*)(qh + rowQ0 + c + 8);
        qH[ks][3] = *(const uint32_t*)(qh + rowQ1 + c + 8);
        qC[ks][0] = *(const uint32_t*)(qc + rowQ0 + c);
        qC[ks][1] = *(const uint32_t*)(qc + rowQ1 + c);
        qC[ks][2] = *(const uint32_t*)(qc + rowQ0 + c + 8);
        qC[ks][3] = *(const uint32_t*)(qc + rowQ1 + c + 8);
    }

    const int bm = lane >> 3;
    const int kboff = ((lane & 7) + ((bm >> 1) << 3)) * (FPITCH * 2) + ((bm & 1) << 3) * 2;
    const int vboff = ((lane & 7) + ((bm & 1) << 3)) * (FPITCH * 2) + (lane >> 4) * 16;

    float o[8][4];
    float mrow[2], lrow[2];
#pragma unroll
    for (int nt = 0; nt < 8; nt++)
#pragma unroll
        for (int i = 0; i < 4; i++) o[nt][i] = 0.0f;
    mrow[0] = mrow[1] = -1e30f;
    lrow[0] = lrow[1] = 0.0f;

    const size_t kvbase = (size_t)(b * SS) * QP + 2 * D3 + h * HD;

    auto prefetch_kv = [&](int kt, int stg) {
        const size_t tb = kvbase + (size_t)(kt * 64) * QP;
        const uint32_t sb = sbase + stg * FSTAGE_B;
#pragma unroll
        for (int l = 0; l < 4; l++) {
            int idx = tid + l * 128;
            int r = idx >> 3, c4 = idx & 7;
            size_t gsrc = tb + (size_t)r * QP + c4 * 8;
            uint32_t sdst = (uint32_t)(r * (FPITCH * 2) + c4 * 16);
            cp16(sb + sdst,               qh + gsrc + 512);
            cp16(sb + FTILE_B + sdst,     qc + gsrc + 512);
            cp16(sb + 2 * FTILE_B + sdst, qh + gsrc + 1024);
            cp16(sb + 3 * FTILE_B + sdst, qc + gsrc + 1024);
        }
    };

    prefetch_kv(0, 0);
    CP_COMMIT();

    for (int kt = 0; kt < 16; kt++) {
        if (kt + 1 < 16) {
            prefetch_kv(kt + 1, (kt + 1) & 1);
            CP_COMMIT();
            CP_WAIT1();
        } else {
            CP_WAIT0();
        }
        __syncthreads();

        const uint32_t sb = sbase + (kt & 1) * FSTAGE_B;
        const uint32_t uKh = sb, uKc = sb + FTILE_B;
        const uint32_t uVh = sb + 2 * FTILE_B, uVc = sb + 3 * FTILE_B;

        float s[8][4];
#pragma unroll
        for (int nt = 0; nt < 8; nt++)
#pragma unroll
            for (int i = 0; i < 4; i++) s[nt][i] = 0.0f;

#pragma unroll
        for (int ks = 0; ks < 4; ks++) {
            const int kb = ks * 32;
            uint32_t kh[4][4], kc[4][4];
#pragma unroll
            for (int np = 0; np < 4; np++) {
                ldsm4(kh[np], uKh + kboff + np * 16 * (FPITCH * 2) + kb);
                ldsm4(kc[np], uKc + kboff + np * 16 * (FPITCH * 2) + kb);
            }
#pragma unroll
            for (int np = 0; np < 4; np++) {
                mma16816(s[2 * np],     qH[ks], kh[np]);
                mma16816(s[2 * np + 1], qH[ks], kh[np] + 2);
            }
#pragma unroll
            for (int np = 0; np < 4; np++) {
                mma16816(s[2 * np],     qC[ks], kc[np]);
                mma16816(s[2 * np + 1], qC[ks], kc[np] + 2);
            }
        }

        // softmax; fold OSCALE into the 1/8 score scale
#pragma unroll
        for (int r = 0; r < 2; r++) {
            float mx = -1e30f;
#pragma unroll
            for (int nt = 0; nt < 8; nt++) {
                s[nt][2 * r]     *= 0.125f * OSCALE;
                s[nt][2 * r + 1] *= 0.125f * OSCALE;
                mx = fmaxf(mx, fmaxf(s[nt][2 * r], s[nt][2 * r + 1]));
            }
            mx = fmaxf(mx, __shfl_xor_sync(0xffffffffu, mx, 1));
            mx = fmaxf(mx, __shfl_xor_sync(0xffffffffu, mx, 2));
            float mnew = fmaxf(mrow[r], mx);
            float alpha = __expf(mrow[r] - mnew);
            float ls = 0.0f;
#pragma unroll
            for (int nt = 0; nt < 8; nt++) {
                float p0 = __expf(s[nt][2 * r] - mnew);
                float p1 = __expf(s[nt][2 * r + 1] - mnew);
                s[nt][2 * r] = p0; s[nt][2 * r + 1] = p1;
                ls += p0 + p1;
            }
            ls += __shfl_xor_sync(0xffffffffu, ls, 1);
            ls += __shfl_xor_sync(0xffffffffu, ls, 2);
            lrow[r] = lrow[r] * alpha + ls;
            mrow[r] = mnew;
#pragma unroll
            for (int nt = 0; nt < 8; nt++) {
                o[nt][2 * r] *= alpha; o[nt][2 * r + 1] *= alpha;
            }
        }

        // split P (A-role) into h/c fragments
        uint32_t pH[4][4], pC[4][4];
#pragma unroll
        for (int j = 0; j < 4; j++) {
            pH[j][0] = pack_h(s[2 * j][0], s[2 * j][1]);
            pH[j][1] = pack_h(s[2 * j][2], s[2 * j][3]);
            pH[j][2] = pack_h(s[2 * j + 1][0], s[2 * j + 1][1]);
            pH[j][3] = pack_h(s[2 * j + 1][2], s[2 * j + 1][3]);
            pC[j][0] = pack_cA(s[2 * j][0], s[2 * j][1]);
            pC[j][1] = pack_cA(s[2 * j][2], s[2 * j][3]);
            pC[j][2] = pack_cA(s[2 * j + 1][0], s[2 * j + 1][1]);
            pC[j][3] = pack_cA(s[2 * j + 1][2], s[2 * j + 1][3]);
        }

#pragma unroll
        for (int j = 0; j < 4; j++) {
            const int rb = j * 16 * (FPITCH * 2);
            uint32_t vh[4][4], vc[4][4];
#pragma unroll
            for (int np = 0; np < 4; np++) {
                ldsm4t(vh[np], uVh + vboff + rb + np * 32);
                ldsm4t(vc[np], uVc + vboff + rb + np * 32);
            }
#pragma unroll
            for (int np = 0; np < 4; np++) {
                mma16816(o[2 * np],     pH[j], vh[np]);
                mma16816(o[2 * np + 1], pH[j], vh[np] + 2);
            }
#pragma unroll
            for (int np = 0; np < 4; np++) {
                mma16816(o[2 * np],     pC[j], vc[np]);
                mma16816(o[2 * np + 1], pC[j], vc[np] + 2);
            }
        }
        __syncthreads();
    }

    const float inv0 = OSCALE / lrow[0], inv1 = OSCALE / lrow[1];
    const size_t orow0 = (size_t)(b * SS + q0 + warp * 16 + g) * OP + 2 * DD + h * HD;
    const size_t orow1 = orow0 + (size_t)8 * OP;
#pragma unroll
    for (int nt = 0; nt < 8; nt++) {
        const int c = nt * 8 + 2 * t;
        const float a0 = o[nt][0] * inv0, a1 = o[nt][1] * inv0;
        const float b0 = o[nt][2] * inv1, b1 = o[nt][3] * inv1;
        *(uint32_t*)(atth + orow0 + c) = pack_h(a0, a1);
        *(uint32_t*)(attc + orow0 + c) = pack_cA(a0, a1);
        *(uint32_t*)(atth + orow1 + c) = pack_h(b0, b1);
        *(uint32_t*)(attc + orow1 + c) = pack_cA(b0, b1);
    }
}

// ---------------------------------------------------------------------------
// Windowed causal attention body, coalesced; role-aware reconstruction.
// ---------------------------------------------------------------------------
#define WQS 0
#define WKS (64 * 65)
#define WVS (WKS + 80 * 65)

template <int W>
__device__ __forceinline__ void window_body(
    const __half* __restrict__ qh, const __half* __restrict__ qc,
    __half* __restrict__ atth, __half* __restrict__ attc,
    float* wsm, int br)
{
    float* Qs = wsm + WQS;
    float* Ks = wsm + WKS;
    float* Vs = wsm + WVS;

    const int tid = threadIdx.x;
    const int q0 = blockIdx.x * 64;
    const int bh = blockIdx.y;
    const int b = bh >> 3, h = bh & 7;
    const size_t base = (size_t)b * SS * QP + (size_t)br * D3 + h * HD;

    for (int e8 = tid; e8 < 64 * 8; e8 += 128) {
        int r = e8 >> 3, c8 = e8 & 7;
        size_t src = base + (size_t)(q0 + r) * QP + c8 * 8;
        uint4 xh4 = *(const uint4*)(qh + src);
        uint4 xc4 = *(const uint4*)(qc + src);
        float* qd = Qs + r * 65 + c8 * 8;
        float2 f;
        f = recA(xh4.x, xc4.x); qd[0] = f.x; qd[1] = f.y;
        f = recA(xh4.y, xc4.y); qd[2] = f.x; qd[3] = f.y;
        f = recA(xh4.z, xc4.z); qd[4] = f.x; qd[5] = f.y;
        f = recA(xh4.w, xc4.w); qd[6] = f.x; qd[7] = f.y;
    }
    for (int e8 = tid; e8 < 80 * 8; e8 += 128) {
        int r = e8 >> 3, c8 = e8 & 7;
        int s = q0 - 16 + r;
        if (s >= 0) {
            size_t src = base + (size_t)s * QP + c8 * 8;
            uint4 kh = *(const uint4*)(qh + src + 512);
            uint4 kc = *(const uint4*)(qc + src + 512);
            uint4 vh = *(const uint4*)(qh + src + 1024);
            uint4 vc = *(const uint4*)(qc + src + 1024);
            float* kd = Ks + r * 65 + c8 * 8;
            float* vd = Vs + r * 65 + c8 * 8;
            float2 f;
            f = recB(kh.x, kc.x); kd[0] = f.x; kd[1] = f.y;
            f = recB(kh.y, kc.y); kd[2] = f.x; kd[3] = f.y;
            f = recB(kh.z, kc.z); kd[4] = f.x; kd[5] = f.y;
            f = recB(kh.w, kc.w); kd[6] = f.x; kd[7] = f.y;
            f = recB(vh.x, vc.x); vd[0] = f.x; vd[1] = f.y;
            f = recB(vh.y, vc.y); vd[2] = f.x; vd[3] = f.y;
            f = recB(vh.z, vc.z); vd[4] = f.x; vd[5] = f.y;
            f = recB(vh.w, vc.w); vd[6] = f.x; vd[7] = f.y;
        }
    }
    __syncthreads();

    const int qlid = tid >> 1;
    const int half = tid & 1;
    const int q = q0 + qlid;

    float qreg[32];
#pragma unroll
    for (int dd = 0; dd < 32; dd++)
        qreg[dd] = Qs[qlid * 65 + 2 * dd + half] * 0.125f;
    __syncthreads();

    float sc[W];
    float m = -1e30f;
#pragma unroll
    for (int w = 0; w < W; w++) {
        int k = q - w;
        int kr = qlid + 16 - w;
        float dot = 0.0f;
        if (k >= 0) {
#pragma unroll
            for (int dd = 0; dd < 32; dd++)
                dot += qreg[dd] * Ks[kr * 65 + 2 * dd + half];
        }
        dot += __shfl_xor_sync(0xffffffffu, dot, 1);
        sc[w] = (k >= 0) ? dot : -1e30f;
        m = fmaxf(m, sc[w]);
    }

    float l = 0.0f;
    float p[W];
#pragma unroll
    for (int w = 0; w < W; w++) {
        p[w] = (q - w >= 0) ? __expf(sc[w] - m) : 0.0f;
        l += p[w];
    }

    float o[32];
#pragma unroll
    for (int dd = 0; dd < 32; dd++) o[dd] = 0.0f;
#pragma unroll
    for (int w = 0; w < W; w++) {
        int k = q - w;
        if (k >= 0) {
            int kr = qlid + 16 - w;
#pragma unroll
            for (int dd = 0; dd < 32; dd++)
                o[dd] += p[w] * Vs[kr * 65 + 2 * dd + half];
        }
    }

    float inv = 1.0f / l;
#pragma unroll
    for (int dd = 0; dd < 32; dd++)
        Qs[qlid * 65 + 2 * dd + half] = o[dd] * inv;
    __syncthreads();

    const size_t obase = (size_t)(b * SS + q0) * OP + (size_t)br * DD + h * HD;
    for (int e8 = tid; e8 < 64 * 8; e8 += 128) {
        int r = e8 >> 3, c8 = e8 & 7;
        const float* row = Qs + r * 65 + c8 * 8;
        uint4 hv, cv;
        hv.x = pack_h(row[0], row[1]); cv.x = pack_cA(row[0], row[1]);
        hv.y = pack_h(row[2], row[3]); cv.y = pack_cA(row[2], row[3]);
        hv.z = pack_h(row[4], row[5]); cv.z = pack_cA(row[4], row[5]);
        hv.w = pack_h(row[6], row[7]); cv.w = pack_cA(row[6], row[7]);
        size_t drow = obase + (size_t)r * OP + c8 * 8;
        *(uint4*)(atth + drow) = hv;
        *(uint4*)(attc + drow) = cv;
    }
}

// ---------------------------------------------------------------------------
// Unified attention kernel: z=0 window<5>, z=1 window<10>, z=2 flash.
// ---------------------------------------------------------------------------
#define ATTN_SMEM FLASH_SMEM

__global__ __launch_bounds__(128) void attn_kernel(
    const __half* __restrict__ qh, const __half* __restrict__ qc,
    __half* __restrict__ atth, __half* __restrict__ attc)
{
    extern __shared__ char asmem[];
    if (blockIdx.z == 2) {
        flash_body(qh, qc, atth, attc, reinterpret_cast<__half*>(asmem));
    } else if (blockIdx.z == 0) {
        window_body<5>(qh, qc, atth, attc, reinterpret_cast<float*>(asmem), 0);
    } else {
        window_body<10>(qh, qc, atth, attc, reinterpret_cast<float*>(asmem), 1);
    }
}

// ---------------------------------------------------------------------------
// Launch
// ---------------------------------------------------------------------------
extern "C" void kernel_launch(void* const* d_in, const int* in_sizes, int n_in,
                              void* d_out, int out_size)
{
    const float* x    = (const float*)d_in[0];   // [16,1024,512]
    const float* Wqkv = (const float*)d_in[1];   // [3,1536,512] = [4608,512]
    const float* bqkv = (const float*)d_in[2];   // [4608]
    const float* Wo   = (const float*)d_in[3];   // [3,512,512]
    const float* bo   = (const float*)d_in[4];   // [3,512]
    const float* Wf   = (const float*)d_in[5];   // [512,1536]
    const float* bf   = (const float*)d_in[6];   // [512]
    float* out = (float*)d_out;

    __half *xh, *xc, *qkvh, *qkvc, *atth, *attc, *combh, *combc;
    __half *Wqkvh, *Wqkvc, *Woh, *Woc, *Wfh, *Wfc;
    cudaGetSymbolAddress((void**)&xh, g_xh);
    cudaGetSymbolAddress((void**)&xc, g_xc);
    cudaGetSymbolAddress((void**)&qkvh, g_qkvh);
    cudaGetSymbolAddress((void**)&qkvc, g_qkvc);
    cudaGetSymbolAddress((void**)&atth, g_atth);
    cudaGetSymbolAddress((void**)&attc, g_attc);
    cudaGetSymbolAddress((void**)&combh, g_combh);
    cudaGetSymbolAddress((void**)&combc, g_combc);
    cudaGetSymbolAddress((void**)&Wqkvh, g_Wqkvh);
    cudaGetSymbolAddress((void**)&Wqkvc, g_Wqkvc);
    cudaGetSymbolAddress((void**)&Woh, g_Woh);
    cudaGetSymbolAddress((void**)&Woc, g_Woc);
    cudaGetSymbolAddress((void**)&Wfh, g_Wfh);
    cudaGetSymbolAddress((void**)&Wfc, g_Wfc);

    cudaFuncSetAttribute(gemm_fp16_kernel,
                         cudaFuncAttributeMaxDynamicSharedMemorySize, GEMM_SMEM);
    cudaFuncSetAttribute(attn_kernel,
                         cudaFuncAttributeMaxDynamicSharedMemorySize, ATTN_SMEM);

    // Conversions: x is A-role; all weights are B-role
    {
        int n4;
        n4 = MM * DD / 4;
        convert_hc_kernel<<<(n4 + 255) / 256, 256>>>(x, xh, xc, n4, 0);
        n4 = 3 * D3 * DD / 4;
        convert_hc_kernel<<<(n4 + 255) / 256, 256>>>(Wqkv, Wqkvh, Wqkvc, n4, 1);
        n4 = 3 * DD * DD / 4;
        convert_hc_kernel<<<(n4 + 255) / 256, 256>>>(Wo, Woh, Woc, n4, 1);
        n4 = DD * D3 / 4;
        convert_hc_kernel<<<(n4 + 255) / 256, 256>>>(Wf, Wfh, Wfc, n4, 1);
    }

    // 1) All three QKV projections as one GEMM (role-baked output)
    {
        dim3 grid(QP / 256, MM / 128, 1);
        gemm_fp16_kernel<<<grid, 512, GEMM_SMEM>>>(
            xh, xc, Wqkvh, Wqkvc, bqkv, nullptr, qkvh, qkvc,
            DD, DD, QP, 0, 0, 0, 0, 0, /*qkvRole=*/1);
    }

    // 2) Attention: windows + flash in ONE launch
    {
        dim3 agrid(SS / 64, BB * HH, 3);
        attn_kernel<<<agrid, 128, ATTN_SMEM>>>(qkvh, qkvc, atth, attc);
    }

    // 3) Batched out-projections (A-role output)
    {
        dim3 grid(DD / 256, MM / 128, 3);
        gemm_fp16_kernel<<<grid, 512, GEMM_SMEM>>>(
            atth, attc, Woh, Woc, bo, nullptr, combh, combc,
            DD, OP, OP, 0, DD, DD * DD, DD, DD, 0);
    }

    // 4) Final projection (fp32 out)
    {
        dim3 grid(DD / 256, MM / 128, 1);
        gemm_fp16_kernel<<<grid, 512, GEMM_SMEM>>>(
            combh, combc, Wfh, Wfc, bf, out, nullptr, nullptr,
            D3, D3, DD, 0, 0, 0, 0, 0, 0);
    }
}